// round 11
// baseline (speedup 1.0000x reference)
#include <cuda_runtime.h>
#include <cuda_bf16.h>
#include <cstdint>

// ---------------- problem constants ----------------
#define B_TOK   1024
#define NA      32
#define DZ      96
#define DA      32
#define DMODEL  128
#define ND      4096      // NA*DMODEL
#define NEXP    8
#define FF      1024
#define HH      512
#define NR      4
#define KTOP    2

#define PAIR_MAX  2072
#define GROUP_MAX 518

// ---------------- scratch ----------------
__device__ float g_x [B_TOK * ND];               // concat(z,a), UNROUNDED (router + LN1 residual)
__device__ float g_xt[B_TOK * ND];               // tf32-rounded copy (GEMM A operand)
__device__ float g_y [B_TOK * ND];
__device__ float g_qkv[(size_t)PAIR_MAX * 32 * 384];
__device__ float g_ao [(size_t)PAIR_MAX * 32 * 128];
__device__ float g_o  [(size_t)PAIR_MAX * 32 * 128];
__device__ float g_h  [(size_t)PAIR_MAX * 32 * 128];
__device__ float g_f2 [(size_t)PAIR_MAX * 32 * 128];
__device__ float g_hid[B_TOK * HH];
__device__ float g_hp [4 * B_TOK * HH];
__device__ float g_lse[B_TOK];
__device__ int   g_topidx[B_TOK * KTOP];
__device__ float g_topgate[B_TOK * KTOP];

// tf32-rounded weight copies (ONLY referenced from device code!)
__device__ float g_wint [NEXP * 384 * 128];
__device__ float g_woutt[NEXP * 128 * 128];
__device__ float g_w1t  [NEXP * 1024 * 128];
__device__ float g_w2t  [NEXP * 128 * 1024];
__device__ float g_hw1t [HH * ND];

__device__ int   g_ngroups;
__device__ int   g_npad;
__device__ int   g_grp_expert[GROUP_MAX];
__device__ int   g_sp_pair[PAIR_MAX];
__device__ int   g_tok_sp[B_TOK * KTOP];

// ---------------- helpers ----------------
__device__ __forceinline__ float to_tf32(float f) {
    uint32_t u;
    asm("cvt.rna.tf32.f32 %0, %1;" : "=r"(u) : "f"(f));
    return __uint_as_float(u);
}

__device__ __forceinline__ void mma_tf32(float* c, const uint32_t* a, const uint32_t* b) {
    asm volatile(
        "mma.sync.aligned.m16n8k8.row.col.f32.tf32.tf32.f32 "
        "{%0,%1,%2,%3},{%4,%5,%6,%7},{%8,%9},{%0,%1,%2,%3};"
        : "+f"(c[0]), "+f"(c[1]), "+f"(c[2]), "+f"(c[3])
        : "r"(a[0]), "r"(a[1]), "r"(a[2]), "r"(a[3]), "r"(b[0]), "r"(b[1]));
}

__device__ __forceinline__ void cp_async16(uint32_t saddr, const void* gaddr) {
    asm volatile("cp.async.cg.shared.global [%0], [%1], 16;\n" :: "r"(saddr), "l"(gaddr));
}
#define CP_COMMIT() asm volatile("cp.async.commit_group;\n")
#define CP_WAIT1()  asm volatile("cp.async.wait_group 1;\n")
#define CP_WAIT0()  asm volatile("cp.async.wait_group 0;\n")

// ---------------- weight rounding prep ----------------
#define RW0 (NEXP * 384 * 128)
#define RW1 (RW0 + NEXP * 128 * 128)
#define RW2 (RW1 + NEXP * 1024 * 128)
#define RW3 (RW2 + NEXP * 128 * 1024)
#define RW4 (RW3 + HH * ND)
__global__ void k_round(const float* __restrict__ w_in, const float* __restrict__ w_out,
                        const float* __restrict__ w1, const float* __restrict__ w2,
                        const float* __restrict__ hw1) {
    int i = blockIdx.x * 256 + threadIdx.x;
    if (i < RW0)      g_wint[i]        = to_tf32(w_in[i]);
    else if (i < RW1) g_woutt[i - RW0] = to_tf32(w_out[i - RW0]);
    else if (i < RW2) g_w1t[i - RW1]   = to_tf32(w1[i - RW1]);
    else if (i < RW3) g_w2t[i - RW2]   = to_tf32(w2[i - RW2]);
    else if (i < RW4) g_hw1t[i - RW3]  = to_tf32(hw1[i - RW3]);
}

// ---------------- concat: unrounded + rounded copies ----------------
__global__ void k_concat(const float* __restrict__ z, const float* __restrict__ a) {
    int idx = blockIdx.x * 256 + threadIdx.x;
    int dd = idx & 127;
    int row = idx >> 7;
    float v = (dd < DZ) ? z[row * DZ + dd] : a[row * DA + (dd - DZ)];
    g_x[idx]  = v;
    g_xt[idx] = to_tf32(v);
}

// ---------------- router (reads UNROUNDED x: exact top-k selection) ----------------
__global__ __launch_bounds__(256) void k_router(const float* __restrict__ w_gate,
                                                float* __restrict__ gates_out) {
    __shared__ float red[256 * 8];
    int b = blockIdx.x, tid = threadIdx.x;
    float p[8];
#pragma unroll
    for (int e = 0; e < 8; e++) p[e] = 0.f;
    const float* xb = g_x + (size_t)b * ND;
    for (int k = tid; k < ND; k += 256) {
        float xv = xb[k];
        const float4* wg = reinterpret_cast<const float4*>(w_gate + (size_t)k * 8);
        float4 w0 = wg[0], w1 = wg[1];
        p[0] = fmaf(xv, w0.x, p[0]); p[1] = fmaf(xv, w0.y, p[1]);
        p[2] = fmaf(xv, w0.z, p[2]); p[3] = fmaf(xv, w0.w, p[3]);
        p[4] = fmaf(xv, w1.x, p[4]); p[5] = fmaf(xv, w1.y, p[5]);
        p[6] = fmaf(xv, w1.z, p[6]); p[7] = fmaf(xv, w1.w, p[7]);
    }
#pragma unroll
    for (int e = 0; e < 8; e++) red[tid * 8 + e] = p[e];
    __syncthreads();
    for (int s = 128; s > 0; s >>= 1) {
        if (tid < s) {
#pragma unroll
            for (int e = 0; e < 8; e++) red[tid * 8 + e] += red[(tid + s) * 8 + e];
        }
        __syncthreads();
    }
    if (tid == 0) {
        float l[8];
#pragma unroll
        for (int e = 0; e < 8; e++) l[e] = red[e];
        int i0 = 0; float v0 = l[0];
#pragma unroll
        for (int e = 1; e < 8; e++) if (l[e] > v0) { v0 = l[e]; i0 = e; }
        int i1 = -1; float v1 = -3.4e38f;
#pragma unroll
        for (int e = 0; e < 8; e++) if (e != i0 && l[e] > v1) { v1 = l[e]; i1 = e; }
        float e1 = expf(v1 - v0);
        float inv = 1.f / (1.f + e1);
        float g0 = inv, g1v = e1 * inv;
#pragma unroll
        for (int e = 0; e < 8; e++)
            gates_out[b * 8 + e] = (e == i0) ? g0 : ((e == i1) ? g1v : 0.f);
        g_topidx[b * 2] = i0;  g_topidx[b * 2 + 1] = i1;
        g_topgate[b * 2] = g0; g_topgate[b * 2 + 1] = g1v;
        float s = 0.f;
#pragma unroll
        for (int e = 0; e < 8; e++) s += expf(l[e] - v0);
        g_lse[b] = v0 + logf(s);
    }
}

// ---------------- parallel deterministic counting sort ----------------
__global__ __launch_bounds__(256) void k_sort() {
    __shared__ int s_cnt[256][8];
    __shared__ int s_ecnt[8];
    __shared__ int s_base[8];
    int t = threadIdx.x;
    int my[8];
    int lc[8] = {0, 0, 0, 0, 0, 0, 0, 0};
#pragma unroll
    for (int i = 0; i < 8; i++) {
        int e = g_topidx[t * 8 + i];
        my[i] = e;
        lc[e]++;
    }
#pragma unroll
    for (int e = 0; e < 8; e++) s_cnt[t][e] = lc[e];
    __syncthreads();
    if (t < 8) {
        int off = 0;
        for (int i = 0; i < 256; i++) {
            int v = s_cnt[i][t];
            s_cnt[i][t] = off;
            off += v;
        }
        s_ecnt[t] = off;
    }
    __syncthreads();
    if (t == 0) {
        int o = 0, g = 0;
        for (int e = 0; e < 8; e++) {
            s_base[e] = o;
            int pc = (s_ecnt[e] + 3) & ~3;
            for (int i = 0; i < (pc >> 2); i++) g_grp_expert[g++] = e;
            o += pc;
        }
        g_ngroups = g;
        g_npad = o;
    }
    __syncthreads();
#pragma unroll
    for (int i = 0; i < 8; i++) {
        int p = t * 8 + i;
        int e = my[i];
        int sp = s_base[e] + s_cnt[t][e]++;
        g_sp_pair[sp] = p;
        g_tok_sp[p] = sp;
    }
    if (t < 8) {
        int start = s_base[t] + s_ecnt[t];
        int end = s_base[t] + ((s_ecnt[t] + 3) & ~3);
        for (int sp = start; sp < end; sp++) g_sp_pair[sp] = -1;
    }
}

// ---------------- cp.async stage helpers ----------------
__device__ __forceinline__ void gemm_issue(uint32_t smu, int buf, int kc,
                                           const float* const* s_ab,
                                           const float* wb, int tid) {
#pragma unroll
    for (int it = 0; it < 4; it++) {
        int i = tid + it * 256;
        int r = i >> 3, q = (i & 7) * 4;
        cp_async16(smu + (uint32_t)(buf * 4608 + r * 36 + q) * 4,
                   s_ab[r >> 5] + (size_t)(r & 31) * 128 + kc + q);
        cp_async16(smu + (uint32_t)(9216 + buf * 4608 + r * 36 + q) * 4,
                   wb + (size_t)r * 128 + kc + q);
    }
    CP_COMMIT();
}

__device__ __forceinline__ void head_issue(uint32_t smu, int buf, int kc,
                                           const float* Ab, const float* Bb, int tid) {
#pragma unroll
    for (int it = 0; it < 4; it++) {
        int i = tid + it * 256;
        int r = i >> 3, q = (i & 7) * 4;
        cp_async16(smu + (uint32_t)(buf * 4608 + r * 36 + q) * 4,
                   Ab + (size_t)r * ND + kc + q);
        cp_async16(smu + (uint32_t)(9216 + buf * 4608 + r * 36 + q) * 4,
                   Bb + (size_t)r * ND + kc + q);
    }
    CP_COMMIT();
}

// ---------------- tf32 batched GEMM (cp.async double-buffered) ----------------
#define GEMM_SMEM_BYTES 73728
template<int SRC, int DST>
__global__ __launch_bounds__(256) void k_gemm(const float* __restrict__ bias, int Ntot) {
    int g = blockIdx.x;
    if (g >= g_ngroups) return;
    int e = g_grp_expert[g];
    int n0 = blockIdx.y * 128;
    int tid = threadIdx.x, lane = tid & 31, w = tid >> 5;

    extern __shared__ float sm[];
    uint32_t smu = (uint32_t)__cvta_generic_to_shared(sm);
    __shared__ const float* s_ab[4];
    if (tid < 4) {
        const float* ab;
        if (SRC == 0) {
            int pr = g_sp_pair[g * 4 + tid];
            int tok = (pr >= 0) ? (pr >> 1) : 0;
            ab = g_xt + (size_t)tok * ND;
        } else {
            ab = g_ao + (size_t)(g * 4 + tid) * 32 * 128;
        }
        s_ab[tid] = ab;
    }
    __syncthreads();

    const float* W = (SRC == 0) ? g_wint : g_woutt;
    const float* wb = W + (size_t)e * Ntot * 128 + (size_t)n0 * 128;

    float acc[2][8][4];
#pragma unroll
    for (int i = 0; i < 2; i++)
#pragma unroll
        for (int j = 0; j < 8; j++)
#pragma unroll
            for (int k = 0; k < 4; k++) acc[i][j][k] = 0.f;

    int mt_base = (w & 3) * 2;
    int nt_base = (w >> 2) * 8;

    gemm_issue(smu, 0, 0, s_ab, wb, tid);
    for (int c = 0; c < 4; c++) {
        if (c + 1 < 4) { gemm_issue(smu, (c + 1) & 1, (c + 1) * 32, s_ab, wb, tid); CP_WAIT1(); }
        else CP_WAIT0();
        __syncthreads();
        const float* sA = sm + (c & 1) * 4608;
        const float* sB = sm + 9216 + (c & 1) * 4608;
#pragma unroll
        for (int ks = 0; ks < 4; ks++) {
            int col = ks * 8 + (lane & 3);
            uint32_t a[2][4];
#pragma unroll
            for (int mt = 0; mt < 2; mt++) {
                int r0 = (mt_base + mt) * 16 + (lane >> 2);
                a[mt][0] = __float_as_uint(sA[r0 * 36 + col]);
                a[mt][1] = __float_as_uint(sA[(r0 + 8) * 36 + col]);
                a[mt][2] = __float_as_uint(sA[r0 * 36 + col + 4]);
                a[mt][3] = __float_as_uint(sA[(r0 + 8) * 36 + col + 4]);
            }
#pragma unroll
            for (int nt = 0; nt < 8; nt++) {
                int nr = (nt_base + nt) * 8 + (lane >> 2);
                uint32_t b[2];
                b[0] = __float_as_uint(sB[nr * 36 + col]);
                b[1] = __float_as_uint(sB[nr * 36 + col + 4]);
                mma_tf32(acc[0][nt], a[0], b);
                mma_tf32(acc[1][nt], a[1], b);
            }
        }
        __syncthreads();
    }

    float* Cb = (DST == 0) ? g_qkv : g_o;
#pragma unroll
    for (int mt = 0; mt < 2; mt++) {
        int r0 = (mt_base + mt) * 16 + (lane >> 2);
        int r1 = r0 + 8;
#pragma unroll
        for (int nt = 0; nt < 8; nt++) {
            int nc = n0 + (nt_base + nt) * 8 + 2 * (lane & 3);
            float2 bv = *reinterpret_cast<const float2*>(bias + (size_t)e * Ntot + nc);
            float2 o0, o1;
            o0.x = acc[mt][nt][0] + bv.x; o0.y = acc[mt][nt][1] + bv.y;
            o1.x = acc[mt][nt][2] + bv.x; o1.y = acc[mt][nt][3] + bv.y;
            *reinterpret_cast<float2*>(Cb + ((size_t)g * 128 + r0) * Ntot + nc) = o0;
            *reinterpret_cast<float2*>(Cb + ((size_t)g * 128 + r1) * Ntot + nc) = o1;
        }
    }
}

// ---------------- head1: split-K tf32 GEMM (cp.async double-buffered) ----------------
__global__ __launch_bounds__(256) void k_head1() {
    int bm = blockIdx.x, bn = blockIdx.y, ks4 = blockIdx.z;
    int tid = threadIdx.x, lane = tid & 31, w = tid >> 5;

    extern __shared__ float sm[];
    uint32_t smu = (uint32_t)__cvta_generic_to_shared(sm);

    const float* Ab = g_y + (size_t)(bm * 128) * ND + ks4 * 1024;
    const float* Bb = g_hw1t + (size_t)(bn * 128) * ND + ks4 * 1024;

    float acc[2][8][4];
#pragma unroll
    for (int i = 0; i < 2; i++)
#pragma unroll
        for (int j = 0; j < 8; j++)
#pragma unroll
            for (int k = 0; k < 4; k++) acc[i][j][k] = 0.f;

    int mt_base = (w & 3) * 2;
    int nt_base = (w >> 2) * 8;

    head_issue(smu, 0, 0, Ab, Bb, tid);
    for (int c = 0; c < 32; c++) {
        if (c + 1 < 32) { head_issue(smu, (c + 1) & 1, (c + 1) * 32, Ab, Bb, tid); CP_WAIT1(); }
        else CP_WAIT0();
        __syncthreads();
        const float* sA = sm + (c & 1) * 4608;
        const float* sB = sm + 9216 + (c & 1) * 4608;
#pragma unroll
        for (int ks = 0; ks < 4; ks++) {
            int col = ks * 8 + (lane & 3);
            uint32_t a[2][4];
#pragma unroll
            for (int mt = 0; mt < 2; mt++) {
                int r0 = (mt_base + mt) * 16 + (lane >> 2);
                a[mt][0] = __float_as_uint(sA[r0 * 36 + col]);
                a[mt][1] = __float_as_uint(sA[(r0 + 8) * 36 + col]);
                a[mt][2] = __float_as_uint(sA[r0 * 36 + col + 4]);
                a[mt][3] = __float_as_uint(sA[(r0 + 8) * 36 + col + 4]);
            }
#pragma unroll
            for (int nt = 0; nt < 8; nt++) {
                int nr = (nt_base + nt) * 8 + (lane >> 2);
                uint32_t b[2];
                b[0] = __float_as_uint(sB[nr * 36 + col]);
                b[1] = __float_as_uint(sB[nr * 36 + col + 4]);
                mma_tf32(acc[0][nt], a[0], b);
                mma_tf32(acc[1][nt], a[1], b);
            }
        }
        __syncthreads();
    }

    float* dst = g_hp + ((size_t)ks4 * B_TOK + bm * 128) * HH + bn * 128;
#pragma unroll
    for (int mt = 0; mt < 2; mt++) {
        int r0 = (mt_base + mt) * 16 + (lane >> 2);
        int r1 = r0 + 8;
#pragma unroll
        for (int nt = 0; nt < 8; nt++) {
            int nc = (nt_base + nt) * 8 + 2 * (lane & 3);
            float2 o0, o1;
            o0.x = acc[mt][nt][0]; o0.y = acc[mt][nt][1];
            o1.x = acc[mt][nt][2]; o1.y = acc[mt][nt][3];
            *reinterpret_cast<float2*>(dst + (size_t)r0 * HH + nc) = o0;
            *reinterpret_cast<float2*>(dst + (size_t)r1 * HH + nc) = o1;
        }
    }
}

__global__ void k_head1red(const float* __restrict__ hb1) {
    int i = blockIdx.x * 256 + threadIdx.x;
    int n = i & (HH - 1);
    float s = g_hp[i] + g_hp[B_TOK * HH + i] + g_hp[2 * B_TOK * HH + i]
            + g_hp[3 * B_TOK * HH + i] + hb1[n];
    g_hid[i] = fmaxf(s, 0.f);
}

// ---------------- fused FFN (R9 envelope; warp tile rebalanced 2m x 4n) ----------------
// smem floats: sA[64*132]=8448 | sW[2][128*36]=9216 | sF[64*132]=8448 => 104448 B
#define FFN_SMEM_BYTES ((8448 + 9216 + 8448) * 4)
__device__ __forceinline__ void ffn_issue(uint32_t smu, int s,
                                          const float* w1b, const float* w2b, int tid) {
    int c = s >> 3, ph = (s >> 2) & 1, kc = s & 3;
    const float* base;
    int rstride;
    if (ph) { base = w2b + c * 128 + kc * 32;                 rstride = 1024; }
    else    { base = w1b + (size_t)(c * 128) * 128 + kc * 32; rstride = 128; }
#pragma unroll
    for (int it = 0; it < 4; it++) {
        int i = tid + it * 256;
        int r = i >> 3, q = (i & 7) * 4;
        cp_async16(smu + (uint32_t)(8448 + (s & 1) * 4608 + r * 36 + q) * 4,
                   base + (size_t)r * rstride + q);
    }
    CP_COMMIT();
}

__global__ __launch_bounds__(256) void k_ffn(const float* __restrict__ B1,
                                             const float* __restrict__ B2) {
    int g = blockIdx.x;
    if (g >= g_ngroups) return;
    int half = blockIdx.y;
    int e = g_grp_expert[g];
    int tid = threadIdx.x, lane = tid & 31, w = tid >> 5;

    extern __shared__ float sm[];
    float* sA = sm;                  // 64 x 132 (h tile, resident)
    float* sW = sm + 8448;           // 2 x 128 x 36 (weight ring)
    float* sF = sm + 8448 + 9216;    // 64 x 132 (f1 chunk)
    uint32_t smu = (uint32_t)__cvta_generic_to_shared(sm);

    const float* hb  = g_h + ((size_t)g * 128 + half * 64) * 128;
    const float* w1b = g_w1t + (size_t)e * 1024 * 128;
    const float* w2b = g_w2t + (size_t)e * 128 * 1024;

#pragma unroll
    for (int it = 0; it < 8; it++) {
        int i = tid + it * 256;
        int r = i >> 5, q = (i & 31) * 4;
        *reinterpret_cast<float4*>(sA + r * 132 + q) =
            *reinterpret_cast<const float4*>(hb + (size_t)r * 128 + q);
    }

    // warp tile: 2 m-tiles x 4 n-tiles (M 64 = 2 warp-rows x 2mt x 16; N 128 = 4 warp-cols x 4nt x 8)
    int mt_base = (w & 1) * 2;
    int nt_base = (w >> 1) * 4;
    int rq = lane >> 2;

    float acc1[2][4][4], acc2[2][4][4];
#pragma unroll
    for (int mt = 0; mt < 2; mt++)
#pragma unroll
        for (int j = 0; j < 4; j++)
#pragma unroll
            for (int k = 0; k < 4; k++) acc2[mt][j][k] = 0.f;

    ffn_issue(smu, 0, w1b, w2b, tid);
    ffn_issue(smu, 1, w1b, w2b, tid);

    for (int s = 0; s < 64; s++) {
        if (s < 63) CP_WAIT1(); else CP_WAIT0();
        __syncthreads();                       // sW[s&1] ready; also covers sA load at s=0
        if ((s & 7) == 0) {
#pragma unroll
            for (int mt = 0; mt < 2; mt++)
#pragma unroll
                for (int j = 0; j < 4; j++)
#pragma unroll
                    for (int k = 0; k < 4; k++) acc1[mt][j][k] = 0.f;
        }
        int ph = (s >> 2) & 1;
        int kc = s & 3;
        const float* sWb = sW + (s & 1) * 4608;
        const float* src = ph ? sF : sA;
        float (*accp)[4][4] = ph ? acc2 : acc1;
#pragma unroll
        for (int ks = 0; ks < 4; ks++) {
            int colA = kc * 32 + ks * 8 + (lane & 3);
            uint32_t a[2][4];
#pragma unroll
            for (int mt = 0; mt < 2; mt++) {
                int r0 = (mt_base + mt) * 16 + rq;
                a[mt][0] = __float_as_uint(src[r0 * 132 + colA]);
                a[mt][1] = __float_as_uint(src[(r0 + 8) * 132 + colA]);
                a[mt][2] = __float_as_uint(src[r0 * 132 + colA + 4]);
                a[mt][3] = __float_as_uint(src[(r0 + 8) * 132 + colA + 4]);
            }
            int cw = ks * 8 + (lane & 3);
#pragma unroll
            for (int nt = 0; nt < 4; nt++) {
                int nr = (nt_base + nt) * 8 + rq;
                uint32_t b[2];
                b[0] = __float_as_uint(sWb[nr * 36 + cw]);
                b[1] = __float_as_uint(sWb[nr * 36 + cw + 4]);
                mma_tf32(accp[0][nt], a[0], b);
                mma_tf32(accp[1][nt], a[1], b);
            }
        }
        __syncthreads();                       // mma done before sW[s&1] reuse / sF write
        if ((s & 7) == 3) {
            int c = s >> 3;
#pragma unroll
            for (int mt = 0; mt < 2; mt++) {
                int r0 = (mt_base + mt) * 16 + rq;
#pragma unroll
                for (int nt = 0; nt < 4; nt++) {
                    int nc = (nt_base + nt) * 8 + 2 * (lane & 3);
                    float2 bv = *reinterpret_cast<const float2*>(B1 + (size_t)e * 1024 + c * 128 + nc);
                    sF[r0 * 132 + nc]           = to_tf32(fmaxf(acc1[mt][nt][0] + bv.x, 0.f));
                    sF[r0 * 132 + nc + 1]       = to_tf32(fmaxf(acc1[mt][nt][1] + bv.y, 0.f));
                    sF[(r0 + 8) * 132 + nc]     = to_tf32(fmaxf(acc1[mt][nt][2] + bv.x, 0.f));
                    sF[(r0 + 8) * 132 + nc + 1] = to_tf32(fmaxf(acc1[mt][nt][3] + bv.y, 0.f));
                }
            }
            __syncthreads();                   // sF visible before stage-2 reads
        }
        if (s + 2 < 64) ffn_issue(smu, s + 2, w1b, w2b, tid);
    }

    {
        float* f2b = g_f2 + ((size_t)g * 128 + half * 64) * 128;
#pragma unroll
        for (int mt = 0; mt < 2; mt++) {
            int r0 = (mt_base + mt) * 16 + rq;
#pragma unroll
            for (int nt = 0; nt < 4; nt++) {
                int nc = (nt_base + nt) * 8 + 2 * (lane & 3);
                float2 bv = *reinterpret_cast<const float2*>(B2 + (size_t)e * 128 + nc);
                float2 o0, o1;
                o0.x = acc2[mt][nt][0] + bv.x; o0.y = acc2[mt][nt][1] + bv.y;
                o1.x = acc2[mt][nt][2] + bv.x; o1.y = acc2[mt][nt][3] + bv.y;
                *reinterpret_cast<float2*>(f2b + (size_t)r0 * 128 + nc) = o0;
                *reinterpret_cast<float2*>(f2b + (size_t)(r0 + 8) * 128 + nc) = o1;
            }
        }
    }
}

// ---------------- attention ----------------
__global__ __launch_bounds__(128) void k_attn() {
    int sp = blockIdx.x;
    if (sp >= g_npad) return;
    if (g_sp_pair[sp] < 0) return;
    __shared__ float s_kv[32 * 261];
    int tid = threadIdx.x, lane = tid & 31, h = tid >> 5;
    for (int i = tid; i < 32 * 256; i += 128) {
        int r = i >> 8, c = i & 255;
        s_kv[r * 261 + c] = g_qkv[((size_t)sp * 32 + r) * 384 + 128 + c];
    }
    __syncthreads();
    float kreg[32];
#pragma unroll
    for (int d = 0; d < 32; d++) kreg[d] = s_kv[lane * 261 + h * 32 + d];
    const float* qb = g_qkv + (size_t)sp * 32 * 384;
    for (int q = 0; q < 32; q++) {
        const float4* qp = reinterpret_cast<const float4*>(qb + q * 384 + h * 32);
        float sc = 0.f;
#pragma unroll
        for (int d4 = 0; d4 < 8; d4++) {
            float4 q4 = qp[d4];
            sc += q4.x * kreg[d4 * 4] + q4.y * kreg[d4 * 4 + 1]
                + q4.z * kreg[d4 * 4 + 2] + q4.w * kreg[d4 * 4 + 3];
        }
        sc *= 0.1767766952966369f;
        float m = sc;
#pragma unroll
        for (int off = 16; off > 0; off >>= 1)
            m = fmaxf(m, __shfl_xor_sync(0xffffffffu, m, off));
        float pr = expf(sc - m);
        float ss = pr;
#pragma unroll
        for (int off = 16; off > 0; off >>= 1)
            ss += __shfl_xor_sync(0xffffffffu, ss, off);
        float att = pr / ss;
        float o = 0.f;
#pragma unroll
        for (int kk = 0; kk < 32; kk++) {
            float av = __shfl_sync(0xffffffffu, att, kk);
            o = fmaf(av, s_kv[kk * 261 + 128 + h * 32 + lane], o);
        }
        g_ao[((size_t)sp * 32 + q) * 128 + h * 32 + lane] = to_tf32(o);
    }
}

// ---------------- LN1 (residual uses UNROUNDED x) ----------------
__global__ __launch_bounds__(128) void k_ln1(const float* __restrict__ ln1_g,
                                             const float* __restrict__ ln1_b) {
    int sp = blockIdx.x;
    if (sp >= g_npad) return;
    int pr = g_sp_pair[sp];
    if (pr < 0) return;
    int token = pr >> 1;
    int e = g_topidx[pr];
    int tid = threadIdx.x, lane = tid & 31, w = tid >> 5;
    const float* g1 = ln1_g + e * 128;
    const float* b1 = ln1_b + e * 128;
    for (int rr = 0; rr < 8; rr++) {
        int r = w * 8 + rr;
        float v[4]; float sum = 0.f, sq = 0.f;
#pragma unroll
        for (int j = 0; j < 4; j++) {
            int c = lane + 32 * j;
            v[j] = g_x[(size_t)token * ND + r * 128 + c]
                 + g_o[((size_t)sp * 32 + r) * 128 + c];
            sum += v[j]; sq += v[j] * v[j];
        }
#pragma unroll
        for (int off = 16; off > 0; off >>= 1) {
            sum += __shfl_xor_sync(0xffffffffu, sum, off);
            sq  += __shfl_xor_sync(0xffffffffu, sq, off);
        }
        float mu = sum * (1.f / 128.f);
        float var = sq * (1.f / 128.f) - mu * mu;
        float rs = rsqrtf(var + 1e-5f);
#pragma unroll
        for (int j = 0; j < 4; j++) {
            int c = lane + 32 * j;
            g_h[((size_t)sp * 32 + r) * 128 + c] = to_tf32((v[j] - mu) * rs * g1[c] + b1[c]);
        }
    }
}

// ---------------- finish ----------------
__global__ __launch_bounds__(128) void k_finish(const float* __restrict__ ln2_g,
                                                const float* __restrict__ ln2_b) {
    int t = blockIdx.x;
    int tid = threadIdx.x, lane = tid & 31, w = tid >> 5;
    float y[8][4];
#pragma unroll
    for (int rr = 0; rr < 8; rr++)
#pragma unroll
        for (int j = 0; j < 4; j++) y[rr][j] = 0.f;

    for (int slot = 0; slot < 2; slot++) {
        int pr = t * 2 + slot;
        int sp = g_tok_sp[pr];
        int e = g_topidx[pr];
        float gate = g_topgate[pr];
        const float* g2 = ln2_g + e * 128;
        const float* b2 = ln2_b + e * 128;
        for (int rr = 0; rr < 8; rr++) {
            int r = w * 8 + rr;
            float v[4]; float sum = 0.f, sq = 0.f;
#pragma unroll
            for (int j = 0; j < 4; j++) {
                int c = lane + 32 * j;
                v[j] = g_h[((size_t)sp * 32 + r) * 128 + c]
                     + g_f2[((size_t)sp * 32 + r) * 128 + c];
                sum += v[j]; sq += v[j] * v[j];
            }
#pragma unroll
            for (int off = 16; off > 0; off >>= 1) {
                sum += __shfl_xor_sync(0xffffffffu, sum, off);
                sq  += __shfl_xor_sync(0xffffffffu, sq, off);
            }
            float mu = sum * (1.f / 128.f);
            float var = sq * (1.f / 128.f) - mu * mu;
            float rs = rsqrtf(var + 1e-5f);
#pragma unroll
            for (int j = 0; j < 4; j++) {
                int c = lane + 32 * j;
                y[rr][j] += gate * ((v[j] - mu) * rs * g2[c] + b2[c]);
            }
        }
    }
    for (int rr = 0; rr < 8; rr++) {
        int r = w * 8 + rr;
#pragma unroll
        for (int j = 0; j < 4; j++) {
            int c = lane + 32 * j;
            g_y[(size_t)t * ND + r * 128 + c] = to_tf32(y[rr][j]);
        }
    }
}

// ---------------- head GEMV2 ----------------
__global__ void k_head2(const float* __restrict__ hw2, const float* __restrict__ hb2,
                        float* __restrict__ out_r) {
    int b = blockIdx.x;
    int j = threadIdx.x >> 5;
    int lane = threadIdx.x & 31;
    const float* hb = g_hid + (size_t)b * HH;
    const float* w = hw2 + (size_t)j * HH;
    float s = 0.f;
    for (int k = lane; k < HH; k += 32) s = fmaf(hb[k], w[k], s);
#pragma unroll
    for (int off = 16; off > 0; off >>= 1) s += __shfl_xor_sync(0xffffffffu, s, off);
    if (lane == 0) out_r[b * NR + j] = s + hb2[j];
}

// ---------------- loss ----------------
__global__ void k_loss(const float* __restrict__ gates, float* __restrict__ out_loss) {
    __shared__ float s_imp[8][32], s_ld[8][32], s_lse[256];
    int t = threadIdx.x;
    int e = t & 7, c = t >> 3;
    float imp = 0.f, ld = 0.f;
    for (int b = c; b < B_TOK; b += 32) {
        float g = gates[b * 8 + e];
        imp += g;
        if (g > 0.f) ld += 1.f;
    }
    s_imp[e][c] = imp; s_ld[e][c] = ld;
    float ls = 0.f;
    for (int b = t; b < B_TOK; b += 256) ls += g_lse[b];
    s_lse[t] = ls;
    __syncthreads();
    for (int s = 128; s > 0; s >>= 1) {
        if (t < s) s_lse[t] += s_lse[t + s];
        __syncthreads();
    }
    if (t == 0) {
        float I[8], L[8];
        float mi = 0.f, ml = 0.f;
        for (int e2 = 0; e2 < 8; e2++) {
            float si = 0.f, sl = 0.f;
            for (int c2 = 0; c2 < 32; c2++) { si += s_imp[e2][c2]; sl += s_ld[e2][c2]; }
            I[e2] = si; L[e2] = sl; mi += si; ml += sl;
        }
        mi *= 0.125f; ml *= 0.125f;
        float vi = 0.f, vl = 0.f;
        for (int e2 = 0; e2 < 8; e2++) {
            vi += (I[e2] - mi) * (I[e2] - mi);
            vl += (L[e2] - ml) * (L[e2] - ml);
        }
        vi /= 7.f; vl /= 7.f;
        float loss = vi / (mi * mi + 1e-10f) + vl / (ml * ml + 1e-10f)
                   + s_lse[0] * (1.f / (float)B_TOK);
        *out_loss = loss;
    }
}

// ---------------- launch ----------------
extern "C" void kernel_launch(void* const* d_in, const int* in_sizes, int n_in,
                              void* d_out, int out_size) {
    const float* z      = (const float*)d_in[0];
    const float* a      = (const float*)d_in[1];
    const float* w_gate = (const float*)d_in[2];
    const float* w_in   = (const float*)d_in[3];
    const float* b_in   = (const float*)d_in[4];
    const float* w_out  = (const float*)d_in[5];
    const float* b_out  = (const float*)d_in[6];
    const float* ln1_g  = (const float*)d_in[7];
    const float* ln1_b  = (const float*)d_in[8];
    const float* w1     = (const float*)d_in[9];
    const float* b1     = (const float*)d_in[10];
    const float* w2     = (const float*)d_in[11];
    const float* b2     = (const float*)d_in[12];
    const float* ln2_g  = (const float*)d_in[13];
    const float* ln2_b  = (const float*)d_in[14];
    const float* hw1    = (const float*)d_in[15];
    const float* hb1    = (const float*)d_in[16];
    const float* hw2    = (const float*)d_in[17];
    const float* hb2    = (const float*)d_in[18];

    float* out       = (float*)d_out;
    float* gates_out = out + B_TOK * NR;
    float* loss_out  = out + B_TOK * NR + B_TOK * NEXP;

    cudaFuncSetAttribute(k_gemm<0, 0>, cudaFuncAttributeMaxDynamicSharedMemorySize, GEMM_SMEM_BYTES);
    cudaFuncSetAttribute(k_gemm<1, 1>, cudaFuncAttributeMaxDynamicSharedMemorySize, GEMM_SMEM_BYTES);
    cudaFuncSetAttribute(k_head1, cudaFuncAttributeMaxDynamicSharedMemorySize, GEMM_SMEM_BYTES);
    cudaFuncSetAttribute(k_ffn, cudaFuncAttributeMaxDynamicSharedMemorySize, FFN_SMEM_BYTES);

    k_round<<<(RW4 + 255) / 256, 256>>>(w_in, w_out, w1, w2, hw1);
    k_concat<<<(B_TOK * ND) / 256, 256>>>(z, a);
    k_router<<<B_TOK, 256>>>(w_gate, gates_out);
    k_sort<<<1, 256>>>();

    k_gemm<0, 0><<<dim3(GROUP_MAX, 3), 256, GEMM_SMEM_BYTES>>>(b_in, 384);
    k_attn<<<PAIR_MAX, 128>>>();
    k_gemm<1, 1><<<dim3(GROUP_MAX, 1), 256, GEMM_SMEM_BYTES>>>(b_out, 128);
    k_ln1<<<PAIR_MAX, 128>>>(ln1_g, ln1_b);
    k_ffn<<<dim3(GROUP_MAX, 2), 256, FFN_SMEM_BYTES>>>(b1, b2);
    k_finish<<<B_TOK, 128>>>(ln2_g, ln2_b);
    k_head1<<<dim3(8, 4, 4), 256, GEMM_SMEM_BYTES>>>();
    k_head1red<<<(B_TOK * HH) / 256, 256>>>(hb1);
    k_head2<<<B_TOK, 128>>>(hw2, hb2, out);
    k_loss<<<1, 256>>>(gates_out, loss_out);
}

// round 12
// speedup vs baseline: 1.3456x; 1.3456x over previous
#include <cuda_runtime.h>
#include <cuda_bf16.h>
#include <cstdint>

// ---------------- problem constants ----------------
#define B_TOK   1024
#define NA      32
#define DZ      96
#define DA      32
#define DMODEL  128
#define ND      4096      // NA*DMODEL
#define NEXP    8
#define FF      1024
#define HH      512
#define NR      4
#define KTOP    2

#define PAIR_MAX  2072
#define GROUP_MAX 518

// ---------------- scratch ----------------
__device__ float g_x [B_TOK * ND];               // concat(z,a), UNROUNDED (router + LN1 residual)
__device__ float g_xt[B_TOK * ND];               // tf32-rounded copy (GEMM A operand)
__device__ float g_y [B_TOK * ND];
__device__ float g_qkv[(size_t)PAIR_MAX * 32 * 384];
__device__ float g_ao [(size_t)PAIR_MAX * 32 * 128];
__device__ float g_o  [(size_t)PAIR_MAX * 32 * 128];
__device__ float g_h  [(size_t)PAIR_MAX * 32 * 128];
__device__ float g_f2 [(size_t)PAIR_MAX * 32 * 128];
__device__ float g_hid[B_TOK * HH];
__device__ float g_hp [4 * B_TOK * HH];
__device__ float g_lse[B_TOK];
__device__ int   g_topidx[B_TOK * KTOP];
__device__ float g_topgate[B_TOK * KTOP];

// tf32-rounded weight copies (ONLY referenced from device code!)
__device__ float g_wint [NEXP * 384 * 128];
__device__ float g_woutt[NEXP * 128 * 128];
__device__ float g_w1t  [NEXP * 1024 * 128];
__device__ float g_w2t  [NEXP * 128 * 1024];
__device__ float g_hw1t [HH * ND];

__device__ int   g_ngroups;
__device__ int   g_npad;
__device__ int   g_grp_expert[GROUP_MAX];
__device__ int   g_sp_pair[PAIR_MAX];
__device__ int   g_tok_sp[B_TOK * KTOP];

// ---------------- helpers ----------------
__device__ __forceinline__ float to_tf32(float f) {
    uint32_t u;
    asm("cvt.rna.tf32.f32 %0, %1;" : "=r"(u) : "f"(f));
    return __uint_as_float(u);
}

__device__ __forceinline__ void mma_tf32(float* c, const uint32_t* a, const uint32_t* b) {
    asm volatile(
        "mma.sync.aligned.m16n8k8.row.col.f32.tf32.tf32.f32 "
        "{%0,%1,%2,%3},{%4,%5,%6,%7},{%8,%9},{%0,%1,%2,%3};"
        : "+f"(c[0]), "+f"(c[1]), "+f"(c[2]), "+f"(c[3])
        : "r"(a[0]), "r"(a[1]), "r"(a[2]), "r"(a[3]), "r"(b[0]), "r"(b[1]));
}

__device__ __forceinline__ void cp_async16(uint32_t saddr, const void* gaddr) {
    asm volatile("cp.async.cg.shared.global [%0], [%1], 16;\n" :: "r"(saddr), "l"(gaddr));
}
#define CP_COMMIT() asm volatile("cp.async.commit_group;\n")
#define CP_WAIT1()  asm volatile("cp.async.wait_group 1;\n")
#define CP_WAIT0()  asm volatile("cp.async.wait_group 0;\n")

// ---------------- weight rounding prep ----------------
#define RW0 (NEXP * 384 * 128)
#define RW1 (RW0 + NEXP * 128 * 128)
#define RW2 (RW1 + NEXP * 1024 * 128)
#define RW3 (RW2 + NEXP * 128 * 1024)
#define RW4 (RW3 + HH * ND)
__global__ void k_round(const float* __restrict__ w_in, const float* __restrict__ w_out,
                        const float* __restrict__ w1, const float* __restrict__ w2,
                        const float* __restrict__ hw1) {
    int i = blockIdx.x * 256 + threadIdx.x;
    if (i < RW0)      g_wint[i]        = to_tf32(w_in[i]);
    else if (i < RW1) g_woutt[i - RW0] = to_tf32(w_out[i - RW0]);
    else if (i < RW2) g_w1t[i - RW1]   = to_tf32(w1[i - RW1]);
    else if (i < RW3) g_w2t[i - RW2]   = to_tf32(w2[i - RW2]);
    else if (i < RW4) g_hw1t[i - RW3]  = to_tf32(hw1[i - RW3]);
}

// ---------------- concat: unrounded + rounded copies ----------------
__global__ void k_concat(const float* __restrict__ z, const float* __restrict__ a) {
    int idx = blockIdx.x * 256 + threadIdx.x;
    int dd = idx & 127;
    int row = idx >> 7;
    float v = (dd < DZ) ? z[row * DZ + dd] : a[row * DA + (dd - DZ)];
    g_x[idx]  = v;
    g_xt[idx] = to_tf32(v);
}

// ---------------- router (reads UNROUNDED x: exact top-k selection) ----------------
__global__ __launch_bounds__(256) void k_router(const float* __restrict__ w_gate,
                                                float* __restrict__ gates_out) {
    __shared__ float red[256 * 8];
    int b = blockIdx.x, tid = threadIdx.x;
    float p[8];
#pragma unroll
    for (int e = 0; e < 8; e++) p[e] = 0.f;
    const float* xb = g_x + (size_t)b * ND;
    for (int k = tid; k < ND; k += 256) {
        float xv = xb[k];
        const float4* wg = reinterpret_cast<const float4*>(w_gate + (size_t)k * 8);
        float4 w0 = wg[0], w1 = wg[1];
        p[0] = fmaf(xv, w0.x, p[0]); p[1] = fmaf(xv, w0.y, p[1]);
        p[2] = fmaf(xv, w0.z, p[2]); p[3] = fmaf(xv, w0.w, p[3]);
        p[4] = fmaf(xv, w1.x, p[4]); p[5] = fmaf(xv, w1.y, p[5]);
        p[6] = fmaf(xv, w1.z, p[6]); p[7] = fmaf(xv, w1.w, p[7]);
    }
#pragma unroll
    for (int e = 0; e < 8; e++) red[tid * 8 + e] = p[e];
    __syncthreads();
    for (int s = 128; s > 0; s >>= 1) {
        if (tid < s) {
#pragma unroll
            for (int e = 0; e < 8; e++) red[tid * 8 + e] += red[(tid + s) * 8 + e];
        }
        __syncthreads();
    }
    if (tid == 0) {
        float l[8];
#pragma unroll
        for (int e = 0; e < 8; e++) l[e] = red[e];
        int i0 = 0; float v0 = l[0];
#pragma unroll
        for (int e = 1; e < 8; e++) if (l[e] > v0) { v0 = l[e]; i0 = e; }
        int i1 = -1; float v1 = -3.4e38f;
#pragma unroll
        for (int e = 0; e < 8; e++) if (e != i0 && l[e] > v1) { v1 = l[e]; i1 = e; }
        float e1 = expf(v1 - v0);
        float inv = 1.f / (1.f + e1);
        float g0 = inv, g1v = e1 * inv;
#pragma unroll
        for (int e = 0; e < 8; e++)
            gates_out[b * 8 + e] = (e == i0) ? g0 : ((e == i1) ? g1v : 0.f);
        g_topidx[b * 2] = i0;  g_topidx[b * 2 + 1] = i1;
        g_topgate[b * 2] = g0; g_topgate[b * 2 + 1] = g1v;
        float s = 0.f;
#pragma unroll
        for (int e = 0; e < 8; e++) s += expf(l[e] - v0);
        g_lse[b] = v0 + logf(s);
    }
}

// ---------------- parallel deterministic counting sort ----------------
__global__ __launch_bounds__(256) void k_sort() {
    __shared__ int s_cnt[256][8];
    __shared__ int s_ecnt[8];
    __shared__ int s_base[8];
    int t = threadIdx.x;
    int my[8];
    int lc[8] = {0, 0, 0, 0, 0, 0, 0, 0};
#pragma unroll
    for (int i = 0; i < 8; i++) {
        int e = g_topidx[t * 8 + i];
        my[i] = e;
        lc[e]++;
    }
#pragma unroll
    for (int e = 0; e < 8; e++) s_cnt[t][e] = lc[e];
    __syncthreads();
    if (t < 8) {
        int off = 0;
        for (int i = 0; i < 256; i++) {
            int v = s_cnt[i][t];
            s_cnt[i][t] = off;
            off += v;
        }
        s_ecnt[t] = off;
    }
    __syncthreads();
    if (t == 0) {
        int o = 0, g = 0;
        for (int e = 0; e < 8; e++) {
            s_base[e] = o;
            int pc = (s_ecnt[e] + 3) & ~3;
            for (int i = 0; i < (pc >> 2); i++) g_grp_expert[g++] = e;
            o += pc;
        }
        g_ngroups = g;
        g_npad = o;
    }
    __syncthreads();
#pragma unroll
    for (int i = 0; i < 8; i++) {
        int p = t * 8 + i;
        int e = my[i];
        int sp = s_base[e] + s_cnt[t][e]++;
        g_sp_pair[sp] = p;
        g_tok_sp[p] = sp;
    }
    if (t < 8) {
        int start = s_base[t] + s_ecnt[t];
        int end = s_base[t] + ((s_ecnt[t] + 3) & ~3);
        for (int sp = start; sp < end; sp++) g_sp_pair[sp] = -1;
    }
}

// ---------------- cp.async stage helpers ----------------
__device__ __forceinline__ void gemm_issue(uint32_t smu, int buf, int kc,
                                           const float* const* s_ab,
                                           const float* wb, int tid) {
#pragma unroll
    for (int it = 0; it < 4; it++) {
        int i = tid + it * 256;
        int r = i >> 3, q = (i & 7) * 4;
        cp_async16(smu + (uint32_t)(buf * 4608 + r * 36 + q) * 4,
                   s_ab[r >> 5] + (size_t)(r & 31) * 128 + kc + q);
        cp_async16(smu + (uint32_t)(9216 + buf * 4608 + r * 36 + q) * 4,
                   wb + (size_t)r * 128 + kc + q);
    }
    CP_COMMIT();
}

__device__ __forceinline__ void head_issue(uint32_t smu, int buf, int kc,
                                           const float* Ab, const float* Bb, int tid) {
#pragma unroll
    for (int it = 0; it < 4; it++) {
        int i = tid + it * 256;
        int r = i >> 3, q = (i & 7) * 4;
        cp_async16(smu + (uint32_t)(buf * 4608 + r * 36 + q) * 4,
                   Ab + (size_t)r * ND + kc + q);
        cp_async16(smu + (uint32_t)(9216 + buf * 4608 + r * 36 + q) * 4,
                   Bb + (size_t)r * ND + kc + q);
    }
    CP_COMMIT();
}

// ---------------- tf32 batched GEMM (cp.async double-buffered) ----------------
#define GEMM_SMEM_BYTES 73728
template<int SRC, int DST>
__global__ __launch_bounds__(256) void k_gemm(const float* __restrict__ bias, int Ntot) {
    int g = blockIdx.x;
    if (g >= g_ngroups) return;
    int e = g_grp_expert[g];
    int n0 = blockIdx.y * 128;
    int tid = threadIdx.x, lane = tid & 31, w = tid >> 5;

    extern __shared__ float sm[];
    uint32_t smu = (uint32_t)__cvta_generic_to_shared(sm);
    __shared__ const float* s_ab[4];
    if (tid < 4) {
        const float* ab;
        if (SRC == 0) {
            int pr = g_sp_pair[g * 4 + tid];
            int tok = (pr >= 0) ? (pr >> 1) : 0;
            ab = g_xt + (size_t)tok * ND;
        } else {
            ab = g_ao + (size_t)(g * 4 + tid) * 32 * 128;
        }
        s_ab[tid] = ab;
    }
    __syncthreads();

    const float* W = (SRC == 0) ? g_wint : g_woutt;
    const float* wb = W + (size_t)e * Ntot * 128 + (size_t)n0 * 128;

    float acc[2][8][4];
#pragma unroll
    for (int i = 0; i < 2; i++)
#pragma unroll
        for (int j = 0; j < 8; j++)
#pragma unroll
            for (int k = 0; k < 4; k++) acc[i][j][k] = 0.f;

    int mt_base = (w & 3) * 2;
    int nt_base = (w >> 2) * 8;

    gemm_issue(smu, 0, 0, s_ab, wb, tid);
    for (int c = 0; c < 4; c++) {
        if (c + 1 < 4) { gemm_issue(smu, (c + 1) & 1, (c + 1) * 32, s_ab, wb, tid); CP_WAIT1(); }
        else CP_WAIT0();
        __syncthreads();
        const float* sA = sm + (c & 1) * 4608;
        const float* sB = sm + 9216 + (c & 1) * 4608;
#pragma unroll
        for (int ks = 0; ks < 4; ks++) {
            int col = ks * 8 + (lane & 3);
            uint32_t a[2][4];
#pragma unroll
            for (int mt = 0; mt < 2; mt++) {
                int r0 = (mt_base + mt) * 16 + (lane >> 2);
                a[mt][0] = __float_as_uint(sA[r0 * 36 + col]);
                a[mt][1] = __float_as_uint(sA[(r0 + 8) * 36 + col]);
                a[mt][2] = __float_as_uint(sA[r0 * 36 + col + 4]);
                a[mt][3] = __float_as_uint(sA[(r0 + 8) * 36 + col + 4]);
            }
#pragma unroll
            for (int nt = 0; nt < 8; nt++) {
                int nr = (nt_base + nt) * 8 + (lane >> 2);
                uint32_t b[2];
                b[0] = __float_as_uint(sB[nr * 36 + col]);
                b[1] = __float_as_uint(sB[nr * 36 + col + 4]);
                mma_tf32(acc[0][nt], a[0], b);
                mma_tf32(acc[1][nt], a[1], b);
            }
        }
        __syncthreads();
    }

    float* Cb = (DST == 0) ? g_qkv : g_o;
#pragma unroll
    for (int mt = 0; mt < 2; mt++) {
        int r0 = (mt_base + mt) * 16 + (lane >> 2);
        int r1 = r0 + 8;
#pragma unroll
        for (int nt = 0; nt < 8; nt++) {
            int nc = n0 + (nt_base + nt) * 8 + 2 * (lane & 3);
            float2 bv = *reinterpret_cast<const float2*>(bias + (size_t)e * Ntot + nc);
            float2 o0, o1;
            o0.x = acc[mt][nt][0] + bv.x; o0.y = acc[mt][nt][1] + bv.y;
            o1.x = acc[mt][nt][2] + bv.x; o1.y = acc[mt][nt][3] + bv.y;
            *reinterpret_cast<float2*>(Cb + ((size_t)g * 128 + r0) * Ntot + nc) = o0;
            *reinterpret_cast<float2*>(Cb + ((size_t)g * 128 + r1) * Ntot + nc) = o1;
        }
    }
}

// ---------------- head1: split-K tf32 GEMM (cp.async double-buffered) ----------------
__global__ __launch_bounds__(256) void k_head1() {
    int bm = blockIdx.x, bn = blockIdx.y, ks4 = blockIdx.z;
    int tid = threadIdx.x, lane = tid & 31, w = tid >> 5;

    extern __shared__ float sm[];
    uint32_t smu = (uint32_t)__cvta_generic_to_shared(sm);

    const float* Ab = g_y + (size_t)(bm * 128) * ND + ks4 * 1024;
    const float* Bb = g_hw1t + (size_t)(bn * 128) * ND + ks4 * 1024;

    float acc[2][8][4];
#pragma unroll
    for (int i = 0; i < 2; i++)
#pragma unroll
        for (int j = 0; j < 8; j++)
#pragma unroll
            for (int k = 0; k < 4; k++) acc[i][j][k] = 0.f;

    int mt_base = (w & 3) * 2;
    int nt_base = (w >> 2) * 8;

    head_issue(smu, 0, 0, Ab, Bb, tid);
    for (int c = 0; c < 32; c++) {
        if (c + 1 < 32) { head_issue(smu, (c + 1) & 1, (c + 1) * 32, Ab, Bb, tid); CP_WAIT1(); }
        else CP_WAIT0();
        __syncthreads();
        const float* sA = sm + (c & 1) * 4608;
        const float* sB = sm + 9216 + (c & 1) * 4608;
#pragma unroll
        for (int ks = 0; ks < 4; ks++) {
            int col = ks * 8 + (lane & 3);
            uint32_t a[2][4];
#pragma unroll
            for (int mt = 0; mt < 2; mt++) {
                int r0 = (mt_base + mt) * 16 + (lane >> 2);
                a[mt][0] = __float_as_uint(sA[r0 * 36 + col]);
                a[mt][1] = __float_as_uint(sA[(r0 + 8) * 36 + col]);
                a[mt][2] = __float_as_uint(sA[r0 * 36 + col + 4]);
                a[mt][3] = __float_as_uint(sA[(r0 + 8) * 36 + col + 4]);
            }
#pragma unroll
            for (int nt = 0; nt < 8; nt++) {
                int nr = (nt_base + nt) * 8 + (lane >> 2);
                uint32_t b[2];
                b[0] = __float_as_uint(sB[nr * 36 + col]);
                b[1] = __float_as_uint(sB[nr * 36 + col + 4]);
                mma_tf32(acc[0][nt], a[0], b);
                mma_tf32(acc[1][nt], a[1], b);
            }
        }
        __syncthreads();
    }

    float* dst = g_hp + ((size_t)ks4 * B_TOK + bm * 128) * HH + bn * 128;
#pragma unroll
    for (int mt = 0; mt < 2; mt++) {
        int r0 = (mt_base + mt) * 16 + (lane >> 2);
        int r1 = r0 + 8;
#pragma unroll
        for (int nt = 0; nt < 8; nt++) {
            int nc = (nt_base + nt) * 8 + 2 * (lane & 3);
            float2 o0, o1;
            o0.x = acc[mt][nt][0]; o0.y = acc[mt][nt][1];
            o1.x = acc[mt][nt][2]; o1.y = acc[mt][nt][3];
            *reinterpret_cast<float2*>(dst + (size_t)r0 * HH + nc) = o0;
            *reinterpret_cast<float2*>(dst + (size_t)r1 * HH + nc) = o1;
        }
    }
}

__global__ void k_head1red(const float* __restrict__ hb1) {
    int i = blockIdx.x * 256 + threadIdx.x;
    int n = i & (HH - 1);
    float s = g_hp[i] + g_hp[B_TOK * HH + i] + g_hp[2 * B_TOK * HH + i]
            + g_hp[3 * B_TOK * HH + i] + hb1[n];
    g_hid[i] = fmaxf(s, 0.f);
}

// ---------------- fused FFN (R9 envelope; 2m x 4n warp tile, EXPLICIT branches) ----------------
// smem floats: sA[64*132]=8448 | sW[2][128*36]=9216 | sF[64*132]=8448 => 104448 B
#define FFN_SMEM_BYTES ((8448 + 9216 + 8448) * 4)
__device__ __forceinline__ void ffn_issue(uint32_t smu, int s,
                                          const float* w1b, const float* w2b, int tid) {
    int c = s >> 3, ph = (s >> 2) & 1, kc = s & 3;
    const float* base;
    int rstride;
    if (ph) { base = w2b + c * 128 + kc * 32;                 rstride = 1024; }
    else    { base = w1b + (size_t)(c * 128) * 128 + kc * 32; rstride = 128; }
#pragma unroll
    for (int it = 0; it < 4; it++) {
        int i = tid + it * 256;
        int r = i >> 3, q = (i & 7) * 4;
        cp_async16(smu + (uint32_t)(8448 + (s & 1) * 4608 + r * 36 + q) * 4,
                   base + (size_t)r * rstride + q);
    }
    CP_COMMIT();
}

__global__ __launch_bounds__(256) void k_ffn(const float* __restrict__ B1,
                                             const float* __restrict__ B2) {
    int g = blockIdx.x;
    if (g >= g_ngroups) return;
    int half = blockIdx.y;
    int e = g_grp_expert[g];
    int tid = threadIdx.x, lane = tid & 31, w = tid >> 5;

    extern __shared__ float sm[];
    float* sA = sm;                  // 64 x 132 (h tile, resident)
    float* sW = sm + 8448;           // 2 x 128 x 36 (weight ring)
    float* sF = sm + 8448 + 9216;    // 64 x 132 (f1 chunk)
    uint32_t smu = (uint32_t)__cvta_generic_to_shared(sm);

    const float* hb  = g_h + ((size_t)g * 128 + half * 64) * 128;
    const float* w1b = g_w1t + (size_t)e * 1024 * 128;
    const float* w2b = g_w2t + (size_t)e * 128 * 1024;

#pragma unroll
    for (int it = 0; it < 8; it++) {
        int i = tid + it * 256;
        int r = i >> 5, q = (i & 31) * 4;
        *reinterpret_cast<float4*>(sA + r * 132 + q) =
            *reinterpret_cast<const float4*>(hb + (size_t)r * 128 + q);
    }

    // warp tile: 2 m-tiles x 4 n-tiles
    int mt_base = (w & 1) * 2;
    int nt_base = (w >> 1) * 4;
    int rq = lane >> 2;

    float acc1[2][4][4], acc2[2][4][4];
#pragma unroll
    for (int mt = 0; mt < 2; mt++)
#pragma unroll
        for (int j = 0; j < 4; j++)
#pragma unroll
            for (int k = 0; k < 4; k++) acc2[mt][j][k] = 0.f;

    ffn_issue(smu, 0, w1b, w2b, tid);
    ffn_issue(smu, 1, w1b, w2b, tid);

    for (int s = 0; s < 64; s++) {
        if (s < 63) CP_WAIT1(); else CP_WAIT0();
        __syncthreads();                       // sW[s&1] ready; also covers sA load at s=0
        if ((s & 7) == 0) {
#pragma unroll
            for (int mt = 0; mt < 2; mt++)
#pragma unroll
                for (int j = 0; j < 4; j++)
#pragma unroll
                    for (int k = 0; k < 4; k++) acc1[mt][j][k] = 0.f;
        }
        int ph = (s >> 2) & 1;
        int kc = s & 3;
        const float* sWb = sW + (s & 1) * 4608;
        if (!ph) {
            // stage 1: sA -> acc1 (explicit; accumulators stay in registers)
#pragma unroll
            for (int ks = 0; ks < 4; ks++) {
                int colA = kc * 32 + ks * 8 + (lane & 3);
                uint32_t a[2][4];
#pragma unroll
                for (int mt = 0; mt < 2; mt++) {
                    int r0 = (mt_base + mt) * 16 + rq;
                    a[mt][0] = __float_as_uint(sA[r0 * 132 + colA]);
                    a[mt][1] = __float_as_uint(sA[(r0 + 8) * 132 + colA]);
                    a[mt][2] = __float_as_uint(sA[r0 * 132 + colA + 4]);
                    a[mt][3] = __float_as_uint(sA[(r0 + 8) * 132 + colA + 4]);
                }
                int cw = ks * 8 + (lane & 3);
#pragma unroll
                for (int nt = 0; nt < 4; nt++) {
                    int nr = (nt_base + nt) * 8 + rq;
                    uint32_t b[2];
                    b[0] = __float_as_uint(sWb[nr * 36 + cw]);
                    b[1] = __float_as_uint(sWb[nr * 36 + cw + 4]);
                    mma_tf32(acc1[0][nt], a[0], b);
                    mma_tf32(acc1[1][nt], a[1], b);
                }
            }
        } else {
            // stage 2: sF -> acc2
#pragma unroll
            for (int ks = 0; ks < 4; ks++) {
                int colA = kc * 32 + ks * 8 + (lane & 3);
                uint32_t a[2][4];
#pragma unroll
                for (int mt = 0; mt < 2; mt++) {
                    int r0 = (mt_base + mt) * 16 + rq;
                    a[mt][0] = __float_as_uint(sF[r0 * 132 + colA]);
                    a[mt][1] = __float_as_uint(sF[(r0 + 8) * 132 + colA]);
                    a[mt][2] = __float_as_uint(sF[r0 * 132 + colA + 4]);
                    a[mt][3] = __float_as_uint(sF[(r0 + 8) * 132 + colA + 4]);
                }
                int cw = ks * 8 + (lane & 3);
#pragma unroll
                for (int nt = 0; nt < 4; nt++) {
                    int nr = (nt_base + nt) * 8 + rq;
                    uint32_t b[2];
                    b[0] = __float_as_uint(sWb[nr * 36 + cw]);
                    b[1] = __float_as_uint(sWb[nr * 36 + cw + 4]);
                    mma_tf32(acc2[0][nt], a[0], b);
                    mma_tf32(acc2[1][nt], a[1], b);
                }
            }
        }
        __syncthreads();                       // mma done before sW[s&1] reuse / sF write
        if ((s & 7) == 3) {
            int c = s >> 3;
#pragma unroll
            for (int mt = 0; mt < 2; mt++) {
                int r0 = (mt_base + mt) * 16 + rq;
#pragma unroll
                for (int nt = 0; nt < 4; nt++) {
                    int nc = (nt_base + nt) * 8 + 2 * (lane & 3);
                    float2 bv = *reinterpret_cast<const float2*>(B1 + (size_t)e * 1024 + c * 128 + nc);
                    sF[r0 * 132 + nc]           = to_tf32(fmaxf(acc1[mt][nt][0] + bv.x, 0.f));
                    sF[r0 * 132 + nc + 1]       = to_tf32(fmaxf(acc1[mt][nt][1] + bv.y, 0.f));
                    sF[(r0 + 8) * 132 + nc]     = to_tf32(fmaxf(acc1[mt][nt][2] + bv.x, 0.f));
                    sF[(r0 + 8) * 132 + nc + 1] = to_tf32(fmaxf(acc1[mt][nt][3] + bv.y, 0.f));
                }
            }
            __syncthreads();                   // sF visible before stage-2 reads
        }
        if (s + 2 < 64) ffn_issue(smu, s + 2, w1b, w2b, tid);
    }

    {
        float* f2b = g_f2 + ((size_t)g * 128 + half * 64) * 128;
#pragma unroll
        for (int mt = 0; mt < 2; mt++) {
            int r0 = (mt_base + mt) * 16 + rq;
#pragma unroll
            for (int nt = 0; nt < 4; nt++) {
                int nc = (nt_base + nt) * 8 + 2 * (lane & 3);
                float2 bv = *reinterpret_cast<const float2*>(B2 + (size_t)e * 128 + nc);
                float2 o0, o1;
                o0.x = acc2[mt][nt][0] + bv.x; o0.y = acc2[mt][nt][1] + bv.y;
                o1.x = acc2[mt][nt][2] + bv.x; o1.y = acc2[mt][nt][3] + bv.y;
                *reinterpret_cast<float2*>(f2b + (size_t)r0 * 128 + nc) = o0;
                *reinterpret_cast<float2*>(f2b + (size_t)(r0 + 8) * 128 + nc) = o1;
            }
        }
    }
}

// ---------------- attention ----------------
__global__ __launch_bounds__(128) void k_attn() {
    int sp = blockIdx.x;
    if (sp >= g_npad) return;
    if (g_sp_pair[sp] < 0) return;
    __shared__ float s_kv[32 * 261];
    int tid = threadIdx.x, lane = tid & 31, h = tid >> 5;
    for (int i = tid; i < 32 * 256; i += 128) {
        int r = i >> 8, c = i & 255;
        s_kv[r * 261 + c] = g_qkv[((size_t)sp * 32 + r) * 384 + 128 + c];
    }
    __syncthreads();
    float kreg[32];
#pragma unroll
    for (int d = 0; d < 32; d++) kreg[d] = s_kv[lane * 261 + h * 32 + d];
    const float* qb = g_qkv + (size_t)sp * 32 * 384;
    for (int q = 0; q < 32; q++) {
        const float4* qp = reinterpret_cast<const float4*>(qb + q * 384 + h * 32);
        float sc = 0.f;
#pragma unroll
        for (int d4 = 0; d4 < 8; d4++) {
            float4 q4 = qp[d4];
            sc += q4.x * kreg[d4 * 4] + q4.y * kreg[d4 * 4 + 1]
                + q4.z * kreg[d4 * 4 + 2] + q4.w * kreg[d4 * 4 + 3];
        }
        sc *= 0.1767766952966369f;
        float m = sc;
#pragma unroll
        for (int off = 16; off > 0; off >>= 1)
            m = fmaxf(m, __shfl_xor_sync(0xffffffffu, m, off));
        float pr = expf(sc - m);
        float ss = pr;
#pragma unroll
        for (int off = 16; off > 0; off >>= 1)
            ss += __shfl_xor_sync(0xffffffffu, ss, off);
        float att = pr / ss;
        float o = 0.f;
#pragma unroll
        for (int kk = 0; kk < 32; kk++) {
            float av = __shfl_sync(0xffffffffu, att, kk);
            o = fmaf(av, s_kv[kk * 261 + 128 + h * 32 + lane], o);
        }
        g_ao[((size_t)sp * 32 + q) * 128 + h * 32 + lane] = to_tf32(o);
    }
}

// ---------------- LN1 (residual uses UNROUNDED x) ----------------
__global__ __launch_bounds__(128) void k_ln1(const float* __restrict__ ln1_g,
                                             const float* __restrict__ ln1_b) {
    int sp = blockIdx.x;
    if (sp >= g_npad) return;
    int pr = g_sp_pair[sp];
    if (pr < 0) return;
    int token = pr >> 1;
    int e = g_topidx[pr];
    int tid = threadIdx.x, lane = tid & 31, w = tid >> 5;
    const float* g1 = ln1_g + e * 128;
    const float* b1 = ln1_b + e * 128;
    for (int rr = 0; rr < 8; rr++) {
        int r = w * 8 + rr;
        float v[4]; float sum = 0.f, sq = 0.f;
#pragma unroll
        for (int j = 0; j < 4; j++) {
            int c = lane + 32 * j;
            v[j] = g_x[(size_t)token * ND + r * 128 + c]
                 + g_o[((size_t)sp * 32 + r) * 128 + c];
            sum += v[j]; sq += v[j] * v[j];
        }
#pragma unroll
        for (int off = 16; off > 0; off >>= 1) {
            sum += __shfl_xor_sync(0xffffffffu, sum, off);
            sq  += __shfl_xor_sync(0xffffffffu, sq, off);
        }
        float mu = sum * (1.f / 128.f);
        float var = sq * (1.f / 128.f) - mu * mu;
        float rs = rsqrtf(var + 1e-5f);
#pragma unroll
        for (int j = 0; j < 4; j++) {
            int c = lane + 32 * j;
            g_h[((size_t)sp * 32 + r) * 128 + c] = to_tf32((v[j] - mu) * rs * g1[c] + b1[c]);
        }
    }
}

// ---------------- finish ----------------
__global__ __launch_bounds__(128) void k_finish(const float* __restrict__ ln2_g,
                                                const float* __restrict__ ln2_b) {
    int t = blockIdx.x;
    int tid = threadIdx.x, lane = tid & 31, w = tid >> 5;
    float y[8][4];
#pragma unroll
    for (int rr = 0; rr < 8; rr++)
#pragma unroll
        for (int j = 0; j < 4; j++) y[rr][j] = 0.f;

    for (int slot = 0; slot < 2; slot++) {
        int pr = t * 2 + slot;
        int sp = g_tok_sp[pr];
        int e = g_topidx[pr];
        float gate = g_topgate[pr];
        const float* g2 = ln2_g + e * 128;
        const float* b2 = ln2_b + e * 128;
        for (int rr = 0; rr < 8; rr++) {
            int r = w * 8 + rr;
            float v[4]; float sum = 0.f, sq = 0.f;
#pragma unroll
            for (int j = 0; j < 4; j++) {
                int c = lane + 32 * j;
                v[j] = g_h[((size_t)sp * 32 + r) * 128 + c]
                     + g_f2[((size_t)sp * 32 + r) * 128 + c];
                sum += v[j]; sq += v[j] * v[j];
            }
#pragma unroll
            for (int off = 16; off > 0; off >>= 1) {
                sum += __shfl_xor_sync(0xffffffffu, sum, off);
                sq  += __shfl_xor_sync(0xffffffffu, sq, off);
            }
            float mu = sum * (1.f / 128.f);
            float var = sq * (1.f / 128.f) - mu * mu;
            float rs = rsqrtf(var + 1e-5f);
#pragma unroll
            for (int j = 0; j < 4; j++) {
                int c = lane + 32 * j;
                y[rr][j] += gate * ((v[j] - mu) * rs * g2[c] + b2[c]);
            }
        }
    }
    for (int rr = 0; rr < 8; rr++) {
        int r = w * 8 + rr;
#pragma unroll
        for (int j = 0; j < 4; j++) {
            int c = lane + 32 * j;
            g_y[(size_t)t * ND + r * 128 + c] = to_tf32(y[rr][j]);
        }
    }
}

// ---------------- head GEMV2 ----------------
__global__ void k_head2(const float* __restrict__ hw2, const float* __restrict__ hb2,
                        float* __restrict__ out_r) {
    int b = blockIdx.x;
    int j = threadIdx.x >> 5;
    int lane = threadIdx.x & 31;
    const float* hb = g_hid + (size_t)b * HH;
    const float* w = hw2 + (size_t)j * HH;
    float s = 0.f;
    for (int k = lane; k < HH; k += 32) s = fmaf(hb[k], w[k], s);
#pragma unroll
    for (int off = 16; off > 0; off >>= 1) s += __shfl_xor_sync(0xffffffffu, s, off);
    if (lane == 0) out_r[b * NR + j] = s + hb2[j];
}

// ---------------- loss ----------------
__global__ void k_loss(const float* __restrict__ gates, float* __restrict__ out_loss) {
    __shared__ float s_imp[8][32], s_ld[8][32], s_lse[256];
    int t = threadIdx.x;
    int e = t & 7, c = t >> 3;
    float imp = 0.f, ld = 0.f;
    for (int b = c; b < B_TOK; b += 32) {
        float g = gates[b * 8 + e];
        imp += g;
        if (g > 0.f) ld += 1.f;
    }
    s_imp[e][c] = imp; s_ld[e][c] = ld;
    float ls = 0.f;
    for (int b = t; b < B_TOK; b += 256) ls += g_lse[b];
    s_lse[t] = ls;
    __syncthreads();
    for (int s = 128; s > 0; s >>= 1) {
        if (t < s) s_lse[t] += s_lse[t + s];
        __syncthreads();
    }
    if (t == 0) {
        float I[8], L[8];
        float mi = 0.f, ml = 0.f;
        for (int e2 = 0; e2 < 8; e2++) {
            float si = 0.f, sl = 0.f;
            for (int c2 = 0; c2 < 32; c2++) { si += s_imp[e2][c2]; sl += s_ld[e2][c2]; }
            I[e2] = si; L[e2] = sl; mi += si; ml += sl;
        }
        mi *= 0.125f; ml *= 0.125f;
        float vi = 0.f, vl = 0.f;
        for (int e2 = 0; e2 < 8; e2++) {
            vi += (I[e2] - mi) * (I[e2] - mi);
            vl += (L[e2] - ml) * (L[e2] - ml);
        }
        vi /= 7.f; vl /= 7.f;
        float loss = vi / (mi * mi + 1e-10f) + vl / (ml * ml + 1e-10f)
                   + s_lse[0] * (1.f / (float)B_TOK);
        *out_loss = loss;
    }
}

// ---------------- launch ----------------
extern "C" void kernel_launch(void* const* d_in, const int* in_sizes, int n_in,
                              void* d_out, int out_size) {
    const float* z      = (const float*)d_in[0];
    const float* a      = (const float*)d_in[1];
    const float* w_gate = (const float*)d_in[2];
    const float* w_in   = (const float*)d_in[3];
    const float* b_in   = (const float*)d_in[4];
    const float* w_out  = (const float*)d_in[5];
    const float* b_out  = (const float*)d_in[6];
    const float* ln1_g  = (const float*)d_in[7];
    const float* ln1_b  = (const float*)d_in[8];
    const float* w1     = (const float*)d_in[9];
    const float* b1     = (const float*)d_in[10];
    const float* w2     = (const float*)d_in[11];
    const float* b2     = (const float*)d_in[12];
    const float* ln2_g  = (const float*)d_in[13];
    const float* ln2_b  = (const float*)d_in[14];
    const float* hw1    = (const float*)d_in[15];
    const float* hb1    = (const float*)d_in[16];
    const float* hw2    = (const float*)d_in[17];
    const float* hb2    = (const float*)d_in[18];

    float* out       = (float*)d_out;
    float* gates_out = out + B_TOK * NR;
    float* loss_out  = out + B_TOK * NR + B_TOK * NEXP;

    cudaFuncSetAttribute(k_gemm<0, 0>, cudaFuncAttributeMaxDynamicSharedMemorySize, GEMM_SMEM_BYTES);
    cudaFuncSetAttribute(k_gemm<1, 1>, cudaFuncAttributeMaxDynamicSharedMemorySize, GEMM_SMEM_BYTES);
    cudaFuncSetAttribute(k_head1, cudaFuncAttributeMaxDynamicSharedMemorySize, GEMM_SMEM_BYTES);
    cudaFuncSetAttribute(k_ffn, cudaFuncAttributeMaxDynamicSharedMemorySize, FFN_SMEM_BYTES);

    k_round<<<(RW4 + 255) / 256, 256>>>(w_in, w_out, w1, w2, hw1);
    k_concat<<<(B_TOK * ND) / 256, 256>>>(z, a);
    k_router<<<B_TOK, 256>>>(w_gate, gates_out);
    k_sort<<<1, 256>>>();

    k_gemm<0, 0><<<dim3(GROUP_MAX, 3), 256, GEMM_SMEM_BYTES>>>(b_in, 384);
    k_attn<<<PAIR_MAX, 128>>>();
    k_gemm<1, 1><<<dim3(GROUP_MAX, 1), 256, GEMM_SMEM_BYTES>>>(b_out, 128);
    k_ln1<<<PAIR_MAX, 128>>>(ln1_g, ln1_b);
    k_ffn<<<dim3(GROUP_MAX, 2), 256, FFN_SMEM_BYTES>>>(b1, b2);
    k_finish<<<B_TOK, 128>>>(ln2_g, ln2_b);
    k_head1<<<dim3(8, 4, 4), 256, GEMM_SMEM_BYTES>>>();
    k_head1red<<<(B_TOK * HH) / 256, 256>>>(hb1);
    k_head2<<<B_TOK, 128>>>(hw2, hb2, out);
    k_loss<<<1, 256>>>(gates_out, loss_out);
}

// round 13
// speedup vs baseline: 1.3538x; 1.0062x over previous
#include <cuda_runtime.h>
#include <cuda_bf16.h>
#include <cstdint>

// ---------------- problem constants ----------------
#define B_TOK   1024
#define NA      32
#define DZ      96
#define DA      32
#define DMODEL  128
#define ND      4096      // NA*DMODEL
#define NEXP    8
#define FF      1024
#define HH      512
#define NR      4
#define KTOP    2

#define PAIR_MAX  2072
#define GROUP_MAX 518

// ---------------- scratch ----------------
__device__ float g_x [B_TOK * ND];               // concat(z,a), UNROUNDED
__device__ float g_xt[B_TOK * ND];               // tf32-rounded copy
__device__ float g_y [B_TOK * ND];
__device__ float g_qkv[(size_t)PAIR_MAX * 32 * 384];
__device__ float g_ao [(size_t)PAIR_MAX * 32 * 128];
__device__ float g_h  [(size_t)PAIR_MAX * 32 * 128];
__device__ float g_f2 [(size_t)PAIR_MAX * 32 * 128];
__device__ float g_hp [4 * B_TOK * HH];
__device__ float g_lse[B_TOK];
__device__ int   g_topidx[B_TOK * KTOP];
__device__ float g_topgate[B_TOK * KTOP];

// tf32-rounded weight copies (ONLY referenced from device code!)
__device__ float g_wint [NEXP * 384 * 128];
__device__ float g_woutt[NEXP * 128 * 128];
__device__ float g_w1t  [NEXP * 1024 * 128];
__device__ float g_w2t  [NEXP * 128 * 1024];
__device__ float g_hw1t [HH * ND];

__device__ int   g_ngroups;
__device__ int   g_npad;
__device__ int   g_grp_expert[GROUP_MAX];
__device__ int   g_sp_pair[PAIR_MAX];
__device__ int   g_tok_sp[B_TOK * KTOP];

// ---------------- helpers ----------------
__device__ __forceinline__ float to_tf32(float f) {
    uint32_t u;
    asm("cvt.rna.tf32.f32 %0, %1;" : "=r"(u) : "f"(f));
    return __uint_as_float(u);
}

__device__ __forceinline__ void mma_tf32(float* c, const uint32_t* a, const uint32_t* b) {
    asm volatile(
        "mma.sync.aligned.m16n8k8.row.col.f32.tf32.tf32.f32 "
        "{%0,%1,%2,%3},{%4,%5,%6,%7},{%8,%9},{%0,%1,%2,%3};"
        : "+f"(c[0]), "+f"(c[1]), "+f"(c[2]), "+f"(c[3])
        : "r"(a[0]), "r"(a[1]), "r"(a[2]), "r"(a[3]), "r"(b[0]), "r"(b[1]));
}

__device__ __forceinline__ void cp_async16(uint32_t saddr, const void* gaddr) {
    asm volatile("cp.async.cg.shared.global [%0], [%1], 16;\n" :: "r"(saddr), "l"(gaddr));
}
#define CP_COMMIT() asm volatile("cp.async.commit_group;\n")
#define CP_WAIT1()  asm volatile("cp.async.wait_group 1;\n")
#define CP_WAIT0()  asm volatile("cp.async.wait_group 0;\n")

// ---------------- weight rounding prep ----------------
#define RW0 (NEXP * 384 * 128)
#define RW1 (RW0 + NEXP * 128 * 128)
#define RW2 (RW1 + NEXP * 1024 * 128)
#define RW3 (RW2 + NEXP * 128 * 1024)
#define RW4 (RW3 + HH * ND)
__global__ void k_round(const float* __restrict__ w_in, const float* __restrict__ w_out,
                        const float* __restrict__ w1, const float* __restrict__ w2,
                        const float* __restrict__ hw1) {
    int i = blockIdx.x * 256 + threadIdx.x;
    if (i < RW0)      g_wint[i]        = to_tf32(w_in[i]);
    else if (i < RW1) g_woutt[i - RW0] = to_tf32(w_out[i - RW0]);
    else if (i < RW2) g_w1t[i - RW1]   = to_tf32(w1[i - RW1]);
    else if (i < RW3) g_w2t[i - RW2]   = to_tf32(w2[i - RW2]);
    else if (i < RW4) g_hw1t[i - RW3]  = to_tf32(hw1[i - RW3]);
}

// ---------------- router + fused concat ----------------
__global__ __launch_bounds__(256) void k_router(const float* __restrict__ z,
                                                const float* __restrict__ a,
                                                const float* __restrict__ w_gate,
                                                float* __restrict__ gates_out) {
    __shared__ float red[256 * 8];
    int b = blockIdx.x, tid = threadIdx.x;
    float p[8];
#pragma unroll
    for (int e = 0; e < 8; e++) p[e] = 0.f;
    for (int k = tid; k < ND; k += 256) {
        int dd = k & 127;
        int row = b * 32 + (k >> 7);
        float xv = (dd < DZ) ? z[row * DZ + dd] : a[row * DA + (dd - DZ)];
        g_x [(size_t)b * ND + k] = xv;
        g_xt[(size_t)b * ND + k] = to_tf32(xv);
        const float4* wg = reinterpret_cast<const float4*>(w_gate + (size_t)k * 8);
        float4 w0 = wg[0], w1 = wg[1];
        p[0] = fmaf(xv, w0.x, p[0]); p[1] = fmaf(xv, w0.y, p[1]);
        p[2] = fmaf(xv, w0.z, p[2]); p[3] = fmaf(xv, w0.w, p[3]);
        p[4] = fmaf(xv, w1.x, p[4]); p[5] = fmaf(xv, w1.y, p[5]);
        p[6] = fmaf(xv, w1.z, p[6]); p[7] = fmaf(xv, w1.w, p[7]);
    }
#pragma unroll
    for (int e = 0; e < 8; e++) red[tid * 8 + e] = p[e];
    __syncthreads();
    for (int s = 128; s > 0; s >>= 1) {
        if (tid < s) {
#pragma unroll
            for (int e = 0; e < 8; e++) red[tid * 8 + e] += red[(tid + s) * 8 + e];
        }
        __syncthreads();
    }
    if (tid == 0) {
        float l[8];
#pragma unroll
        for (int e = 0; e < 8; e++) l[e] = red[e];
        int i0 = 0; float v0 = l[0];
#pragma unroll
        for (int e = 1; e < 8; e++) if (l[e] > v0) { v0 = l[e]; i0 = e; }
        int i1 = -1; float v1 = -3.4e38f;
#pragma unroll
        for (int e = 0; e < 8; e++) if (e != i0 && l[e] > v1) { v1 = l[e]; i1 = e; }
        float e1 = expf(v1 - v0);
        float inv = 1.f / (1.f + e1);
        float g0 = inv, g1v = e1 * inv;
#pragma unroll
        for (int e = 0; e < 8; e++)
            gates_out[b * 8 + e] = (e == i0) ? g0 : ((e == i1) ? g1v : 0.f);
        g_topidx[b * 2] = i0;  g_topidx[b * 2 + 1] = i1;
        g_topgate[b * 2] = g0; g_topgate[b * 2 + 1] = g1v;
        float s = 0.f;
#pragma unroll
        for (int e = 0; e < 8; e++) s += expf(l[e] - v0);
        g_lse[b] = v0 + logf(s);
    }
}

// ---------------- parallel deterministic counting sort ----------------
__global__ __launch_bounds__(256) void k_sort() {
    __shared__ int s_cnt[256][8];
    __shared__ int s_ecnt[8];
    __shared__ int s_base[8];
    int t = threadIdx.x;
    int my[8];
    int lc[8] = {0, 0, 0, 0, 0, 0, 0, 0};
#pragma unroll
    for (int i = 0; i < 8; i++) {
        int e = g_topidx[t * 8 + i];
        my[i] = e;
        lc[e]++;
    }
#pragma unroll
    for (int e = 0; e < 8; e++) s_cnt[t][e] = lc[e];
    __syncthreads();
    if (t < 8) {
        int off = 0;
        for (int i = 0; i < 256; i++) {
            int v = s_cnt[i][t];
            s_cnt[i][t] = off;
            off += v;
        }
        s_ecnt[t] = off;
    }
    __syncthreads();
    if (t == 0) {
        int o = 0, g = 0;
        for (int e = 0; e < 8; e++) {
            s_base[e] = o;
            int pc = (s_ecnt[e] + 3) & ~3;
            for (int i = 0; i < (pc >> 2); i++) g_grp_expert[g++] = e;
            o += pc;
        }
        g_ngroups = g;
        g_npad = o;
    }
    __syncthreads();
#pragma unroll
    for (int i = 0; i < 8; i++) {
        int p = t * 8 + i;
        int e = my[i];
        int sp = s_base[e] + s_cnt[t][e]++;
        g_sp_pair[sp] = p;
        g_tok_sp[p] = sp;
    }
    if (t < 8) {
        int start = s_base[t] + s_ecnt[t];
        int end = s_base[t] + ((s_ecnt[t] + 3) & ~3);
        for (int sp = start; sp < end; sp++) g_sp_pair[sp] = -1;
    }
}

// ---------------- cp.async stage helpers ----------------
__device__ __forceinline__ void gemm_issue(uint32_t smu, int buf, int kc,
                                           const float* const* s_ab,
                                           const float* wb, int tid) {
#pragma unroll
    for (int it = 0; it < 4; it++) {
        int i = tid + it * 256;
        int r = i >> 3, q = (i & 7) * 4;
        cp_async16(smu + (uint32_t)(buf * 4608 + r * 36 + q) * 4,
                   s_ab[r >> 5] + (size_t)(r & 31) * 128 + kc + q);
        cp_async16(smu + (uint32_t)(9216 + buf * 4608 + r * 36 + q) * 4,
                   wb + (size_t)r * 128 + kc + q);
    }
    CP_COMMIT();
}

__device__ __forceinline__ void head_issue(uint32_t smu, int buf, int kc,
                                           const float* Ab, const float* Bb, int tid) {
#pragma unroll
    for (int it = 0; it < 4; it++) {
        int i = tid + it * 256;
        int r = i >> 3, q = (i & 7) * 4;
        cp_async16(smu + (uint32_t)(buf * 4608 + r * 36 + q) * 4,
                   Ab + (size_t)r * ND + kc + q);
        cp_async16(smu + (uint32_t)(9216 + buf * 4608 + r * 36 + q) * 4,
                   Bb + (size_t)r * ND + kc + q);
    }
    CP_COMMIT();
}

// ---------------- tf32 batched GEMM (cp.async double-buffered) ----------------
// DST==0: qkv -> g_qkv.  DST==1: o-proj with FUSED residual+LN1 -> g_h.
#define GEMM_SMEM_BYTES 73728
template<int SRC, int DST>
__global__ __launch_bounds__(256) void k_gemm(const float* __restrict__ bias, int Ntot,
                                              const float* __restrict__ ln1_g,
                                              const float* __restrict__ ln1_b) {
    int g = blockIdx.x;
    if (g >= g_ngroups) return;
    int e = g_grp_expert[g];
    int n0 = blockIdx.y * 128;
    int tid = threadIdx.x, lane = tid & 31, w = tid >> 5;

    extern __shared__ float sm[];
    uint32_t smu = (uint32_t)__cvta_generic_to_shared(sm);
    __shared__ const float* s_ab[4];
    if (tid < 4) {
        const float* ab;
        if (SRC == 0) {
            int pr = g_sp_pair[g * 4 + tid];
            int tok = (pr >= 0) ? (pr >> 1) : 0;
            ab = g_xt + (size_t)tok * ND;
        } else {
            ab = g_ao + (size_t)(g * 4 + tid) * 32 * 128;
        }
        s_ab[tid] = ab;
    }
    __syncthreads();

    const float* W = (SRC == 0) ? g_wint : g_woutt;
    const float* wb = W + (size_t)e * Ntot * 128 + (size_t)n0 * 128;

    float acc[2][8][4];
#pragma unroll
    for (int i = 0; i < 2; i++)
#pragma unroll
        for (int j = 0; j < 8; j++)
#pragma unroll
            for (int k = 0; k < 4; k++) acc[i][j][k] = 0.f;

    int mt_base = (w & 3) * 2;
    int nt_base = (w >> 2) * 8;

    gemm_issue(smu, 0, 0, s_ab, wb, tid);
    for (int c = 0; c < 4; c++) {
        if (c + 1 < 4) { gemm_issue(smu, (c + 1) & 1, (c + 1) * 32, s_ab, wb, tid); CP_WAIT1(); }
        else CP_WAIT0();
        __syncthreads();
        const float* sA = sm + (c & 1) * 4608;
        const float* sB = sm + 9216 + (c & 1) * 4608;
#pragma unroll
        for (int ks = 0; ks < 4; ks++) {
            int col = ks * 8 + (lane & 3);
            uint32_t a[2][4];
#pragma unroll
            for (int mt = 0; mt < 2; mt++) {
                int r0 = (mt_base + mt) * 16 + (lane >> 2);
                a[mt][0] = __float_as_uint(sA[r0 * 36 + col]);
                a[mt][1] = __float_as_uint(sA[(r0 + 8) * 36 + col]);
                a[mt][2] = __float_as_uint(sA[r0 * 36 + col + 4]);
                a[mt][3] = __float_as_uint(sA[(r0 + 8) * 36 + col + 4]);
            }
#pragma unroll
            for (int nt = 0; nt < 8; nt++) {
                int nr = (nt_base + nt) * 8 + (lane >> 2);
                uint32_t b[2];
                b[0] = __float_as_uint(sB[nr * 36 + col]);
                b[1] = __float_as_uint(sB[nr * 36 + col + 4]);
                mma_tf32(acc[0][nt], a[0], b);
                mma_tf32(acc[1][nt], a[1], b);
            }
        }
        __syncthreads();
    }

    if (DST == 0) {
#pragma unroll
        for (int mt = 0; mt < 2; mt++) {
            int r0 = (mt_base + mt) * 16 + (lane >> 2);
            int r1 = r0 + 8;
#pragma unroll
            for (int nt = 0; nt < 8; nt++) {
                int nc = n0 + (nt_base + nt) * 8 + 2 * (lane & 3);
                float2 bv = *reinterpret_cast<const float2*>(bias + (size_t)e * Ntot + nc);
                float2 o0, o1;
                o0.x = acc[mt][nt][0] + bv.x; o0.y = acc[mt][nt][1] + bv.y;
                o1.x = acc[mt][nt][2] + bv.x; o1.y = acc[mt][nt][3] + bv.y;
                *reinterpret_cast<float2*>(g_qkv + ((size_t)g * 128 + r0) * Ntot + nc) = o0;
                *reinterpret_cast<float2*>(g_qkv + ((size_t)g * 128 + r1) * Ntot + nc) = o1;
            }
        }
    } else {
        // stage o = acc + bias into smem tile sO[128][132], then fused residual+LN1 -> g_h
        float* sO = sm;
#pragma unroll
        for (int mt = 0; mt < 2; mt++) {
            int r0 = (mt_base + mt) * 16 + (lane >> 2);
            int r1 = r0 + 8;
#pragma unroll
            for (int nt = 0; nt < 8; nt++) {
                int nc = (nt_base + nt) * 8 + 2 * (lane & 3);
                float2 bv = *reinterpret_cast<const float2*>(bias + (size_t)e * 128 + nc);
                sO[r0 * 132 + nc]     = acc[mt][nt][0] + bv.x;
                sO[r0 * 132 + nc + 1] = acc[mt][nt][1] + bv.y;
                sO[r1 * 132 + nc]     = acc[mt][nt][2] + bv.x;
                sO[r1 * 132 + nc + 1] = acc[mt][nt][3] + bv.y;
            }
        }
        __syncthreads();
        const float* g1 = ln1_g + e * 128;
        const float* b1 = ln1_b + e * 128;
        for (int rr = 0; rr < 16; rr++) {
            int r = w * 16 + rr;                 // block row 0..127
            int sp = g * 4 + (r >> 5);
            int pr = g_sp_pair[sp];
            if (pr < 0) continue;
            int token = pr >> 1;
            float v[4]; float sum = 0.f, sq = 0.f;
#pragma unroll
            for (int j = 0; j < 4; j++) {
                int c = lane + 32 * j;
                v[j] = g_x[(size_t)token * ND + (r & 31) * 128 + c] + sO[r * 132 + c];
                sum += v[j]; sq += v[j] * v[j];
            }
#pragma unroll
            for (int off = 16; off > 0; off >>= 1) {
                sum += __shfl_xor_sync(0xffffffffu, sum, off);
                sq  += __shfl_xor_sync(0xffffffffu, sq, off);
            }
            float mu = sum * (1.f / 128.f);
            float var = sq * (1.f / 128.f) - mu * mu;
            float rs = rsqrtf(var + 1e-5f);
#pragma unroll
            for (int j = 0; j < 4; j++) {
                int c = lane + 32 * j;
                g_h[((size_t)g * 128 + r) * 128 + c] = to_tf32((v[j] - mu) * rs * g1[c] + b1[c]);
            }
        }
    }
}

// ---------------- head1: split-K tf32 GEMM (cp.async double-buffered) ----------------
__global__ __launch_bounds__(256) void k_head1() {
    int bm = blockIdx.x, bn = blockIdx.y, ks4 = blockIdx.z;
    int tid = threadIdx.x, lane = tid & 31, w = tid >> 5;

    extern __shared__ float sm[];
    uint32_t smu = (uint32_t)__cvta_generic_to_shared(sm);

    const float* Ab = g_y + (size_t)(bm * 128) * ND + ks4 * 1024;
    const float* Bb = g_hw1t + (size_t)(bn * 128) * ND + ks4 * 1024;

    float acc[2][8][4];
#pragma unroll
    for (int i = 0; i < 2; i++)
#pragma unroll
        for (int j = 0; j < 8; j++)
#pragma unroll
            for (int k = 0; k < 4; k++) acc[i][j][k] = 0.f;

    int mt_base = (w & 3) * 2;
    int nt_base = (w >> 2) * 8;

    head_issue(smu, 0, 0, Ab, Bb, tid);
    for (int c = 0; c < 32; c++) {
        if (c + 1 < 32) { head_issue(smu, (c + 1) & 1, (c + 1) * 32, Ab, Bb, tid); CP_WAIT1(); }
        else CP_WAIT0();
        __syncthreads();
        const float* sA = sm + (c & 1) * 4608;
        const float* sB = sm + 9216 + (c & 1) * 4608;
#pragma unroll
        for (int ks = 0; ks < 4; ks++) {
            int col = ks * 8 + (lane & 3);
            uint32_t a[2][4];
#pragma unroll
            for (int mt = 0; mt < 2; mt++) {
                int r0 = (mt_base + mt) * 16 + (lane >> 2);
                a[mt][0] = __float_as_uint(sA[r0 * 36 + col]);
                a[mt][1] = __float_as_uint(sA[(r0 + 8) * 36 + col]);
                a[mt][2] = __float_as_uint(sA[r0 * 36 + col + 4]);
                a[mt][3] = __float_as_uint(sA[(r0 + 8) * 36 + col + 4]);
            }
#pragma unroll
            for (int nt = 0; nt < 8; nt++) {
                int nr = (nt_base + nt) * 8 + (lane >> 2);
                uint32_t b[2];
                b[0] = __float_as_uint(sB[nr * 36 + col]);
                b[1] = __float_as_uint(sB[nr * 36 + col + 4]);
                mma_tf32(acc[0][nt], a[0], b);
                mma_tf32(acc[1][nt], a[1], b);
            }
        }
        __syncthreads();
    }

    float* dst = g_hp + ((size_t)ks4 * B_TOK + bm * 128) * HH + bn * 128;
#pragma unroll
    for (int mt = 0; mt < 2; mt++) {
        int r0 = (mt_base + mt) * 16 + (lane >> 2);
        int r1 = r0 + 8;
#pragma unroll
        for (int nt = 0; nt < 8; nt++) {
            int nc = (nt_base + nt) * 8 + 2 * (lane & 3);
            float2 o0, o1;
            o0.x = acc[mt][nt][0]; o0.y = acc[mt][nt][1];
            o1.x = acc[mt][nt][2]; o1.y = acc[mt][nt][3];
            *reinterpret_cast<float2*>(dst + (size_t)r0 * HH + nc) = o0;
            *reinterpret_cast<float2*>(dst + (size_t)r1 * HH + nc) = o1;
        }
    }
}

// ---------------- fused FFN (2m x 4n warp tile, explicit branches) ----------------
// smem floats: sA[64*132]=8448 | sW[2][128*36]=9216 | sF[64*132]=8448 => 104448 B
#define FFN_SMEM_BYTES ((8448 + 9216 + 8448) * 4)
__device__ __forceinline__ void ffn_issue(uint32_t smu, int s,
                                          const float* w1b, const float* w2b, int tid) {
    int c = s >> 3, ph = (s >> 2) & 1, kc = s & 3;
    const float* base;
    int rstride;
    if (ph) { base = w2b + c * 128 + kc * 32;                 rstride = 1024; }
    else    { base = w1b + (size_t)(c * 128) * 128 + kc * 32; rstride = 128; }
#pragma unroll
    for (int it = 0; it < 4; it++) {
        int i = tid + it * 256;
        int r = i >> 3, q = (i & 7) * 4;
        cp_async16(smu + (uint32_t)(8448 + (s & 1) * 4608 + r * 36 + q) * 4,
                   base + (size_t)r * rstride + q);
    }
    CP_COMMIT();
}

__global__ __launch_bounds__(256) void k_ffn(const float* __restrict__ B1,
                                             const float* __restrict__ B2) {
    int g = blockIdx.x;
    if (g >= g_ngroups) return;
    int half = blockIdx.y;
    int e = g_grp_expert[g];
    int tid = threadIdx.x, lane = tid & 31, w = tid >> 5;

    extern __shared__ float sm[];
    float* sA = sm;
    float* sW = sm + 8448;
    float* sF = sm + 8448 + 9216;
    uint32_t smu = (uint32_t)__cvta_generic_to_shared(sm);

    const float* hb  = g_h + ((size_t)g * 128 + half * 64) * 128;
    const float* w1b = g_w1t + (size_t)e * 1024 * 128;
    const float* w2b = g_w2t + (size_t)e * 128 * 1024;

#pragma unroll
    for (int it = 0; it < 8; it++) {
        int i = tid + it * 256;
        int r = i >> 5, q = (i & 31) * 4;
        *reinterpret_cast<float4*>(sA + r * 132 + q) =
            *reinterpret_cast<const float4*>(hb + (size_t)r * 128 + q);
    }

    int mt_base = (w & 1) * 2;
    int nt_base = (w >> 1) * 4;
    int rq = lane >> 2;

    float acc1[2][4][4], acc2[2][4][4];
#pragma unroll
    for (int mt = 0; mt < 2; mt++)
#pragma unroll
        for (int j = 0; j < 4; j++)
#pragma unroll
            for (int k = 0; k < 4; k++) acc2[mt][j][k] = 0.f;

    ffn_issue(smu, 0, w1b, w2b, tid);
    ffn_issue(smu, 1, w1b, w2b, tid);

    for (int s = 0; s < 64; s++) {
        if (s < 63) CP_WAIT1(); else CP_WAIT0();
        __syncthreads();
        if ((s & 7) == 0) {
#pragma unroll
            for (int mt = 0; mt < 2; mt++)
#pragma unroll
                for (int j = 0; j < 4; j++)
#pragma unroll
                    for (int k = 0; k < 4; k++) acc1[mt][j][k] = 0.f;
        }
        int ph = (s >> 2) & 1;
        int kc = s & 3;
        const float* sWb = sW + (s & 1) * 4608;
        if (!ph) {
#pragma unroll
            for (int ks = 0; ks < 4; ks++) {
                int colA = kc * 32 + ks * 8 + (lane & 3);
                uint32_t a[2][4];
#pragma unroll
                for (int mt = 0; mt < 2; mt++) {
                    int r0 = (mt_base + mt) * 16 + rq;
                    a[mt][0] = __float_as_uint(sA[r0 * 132 + colA]);
                    a[mt][1] = __float_as_uint(sA[(r0 + 8) * 132 + colA]);
                    a[mt][2] = __float_as_uint(sA[r0 * 132 + colA + 4]);
                    a[mt][3] = __float_as_uint(sA[(r0 + 8) * 132 + colA + 4]);
                }
                int cw = ks * 8 + (lane & 3);
#pragma unroll
                for (int nt = 0; nt < 4; nt++) {
                    int nr = (nt_base + nt) * 8 + rq;
                    uint32_t b[2];
                    b[0] = __float_as_uint(sWb[nr * 36 + cw]);
                    b[1] = __float_as_uint(sWb[nr * 36 + cw + 4]);
                    mma_tf32(acc1[0][nt], a[0], b);
                    mma_tf32(acc1[1][nt], a[1], b);
                }
            }
        } else {
#pragma unroll
            for (int ks = 0; ks < 4; ks++) {
                int colA = kc * 32 + ks * 8 + (lane & 3);
                uint32_t a[2][4];
#pragma unroll
                for (int mt = 0; mt < 2; mt++) {
                    int r0 = (mt_base + mt) * 16 + rq;
                    a[mt][0] = __float_as_uint(sF[r0 * 132 + colA]);
                    a[mt][1] = __float_as_uint(sF[(r0 + 8) * 132 + colA]);
                    a[mt][2] = __float_as_uint(sF[r0 * 132 + colA + 4]);
                    a[mt][3] = __float_as_uint(sF[(r0 + 8) * 132 + colA + 4]);
                }
                int cw = ks * 8 + (lane & 3);
#pragma unroll
                for (int nt = 0; nt < 4; nt++) {
                    int nr = (nt_base + nt) * 8 + rq;
                    uint32_t b[2];
                    b[0] = __float_as_uint(sWb[nr * 36 + cw]);
                    b[1] = __float_as_uint(sWb[nr * 36 + cw + 4]);
                    mma_tf32(acc2[0][nt], a[0], b);
                    mma_tf32(acc2[1][nt], a[1], b);
                }
            }
        }
        __syncthreads();
        if ((s & 7) == 3) {
            int c = s >> 3;
#pragma unroll
            for (int mt = 0; mt < 2; mt++) {
                int r0 = (mt_base + mt) * 16 + rq;
#pragma unroll
                for (int nt = 0; nt < 4; nt++) {
                    int nc = (nt_base + nt) * 8 + 2 * (lane & 3);
                    float2 bv = *reinterpret_cast<const float2*>(B1 + (size_t)e * 1024 + c * 128 + nc);
                    sF[r0 * 132 + nc]           = to_tf32(fmaxf(acc1[mt][nt][0] + bv.x, 0.f));
                    sF[r0 * 132 + nc + 1]       = to_tf32(fmaxf(acc1[mt][nt][1] + bv.y, 0.f));
                    sF[(r0 + 8) * 132 + nc]     = to_tf32(fmaxf(acc1[mt][nt][2] + bv.x, 0.f));
                    sF[(r0 + 8) * 132 + nc + 1] = to_tf32(fmaxf(acc1[mt][nt][3] + bv.y, 0.f));
                }
            }
            __syncthreads();
        }
        if (s + 2 < 64) ffn_issue(smu, s + 2, w1b, w2b, tid);
    }

    {
        float* f2b = g_f2 + ((size_t)g * 128 + half * 64) * 128;
#pragma unroll
        for (int mt = 0; mt < 2; mt++) {
            int r0 = (mt_base + mt) * 16 + rq;
#pragma unroll
            for (int nt = 0; nt < 4; nt++) {
                int nc = (nt_base + nt) * 8 + 2 * (lane & 3);
                float2 bv = *reinterpret_cast<const float2*>(B2 + (size_t)e * 128 + nc);
                float2 o0, o1;
                o0.x = acc2[mt][nt][0] + bv.x; o0.y = acc2[mt][nt][1] + bv.y;
                o1.x = acc2[mt][nt][2] + bv.x; o1.y = acc2[mt][nt][3] + bv.y;
                *reinterpret_cast<float2*>(f2b + (size_t)r0 * 128 + nc) = o0;
                *reinterpret_cast<float2*>(f2b + (size_t)(r0 + 8) * 128 + nc) = o1;
            }
        }
    }
}

// ---------------- attention ----------------
__global__ __launch_bounds__(128) void k_attn() {
    int sp = blockIdx.x;
    if (sp >= g_npad) return;
    if (g_sp_pair[sp] < 0) return;
    __shared__ float s_kv[32 * 261];
    int tid = threadIdx.x, lane = tid & 31, h = tid >> 5;
    for (int i = tid; i < 32 * 256; i += 128) {
        int r = i >> 8, c = i & 255;
        s_kv[r * 261 + c] = g_qkv[((size_t)sp * 32 + r) * 384 + 128 + c];
    }
    __syncthreads();
    float kreg[32];
#pragma unroll
    for (int d = 0; d < 32; d++) kreg[d] = s_kv[lane * 261 + h * 32 + d];
    const float* qb = g_qkv + (size_t)sp * 32 * 384;
    for (int q = 0; q < 32; q++) {
        const float4* qp = reinterpret_cast<const float4*>(qb + q * 384 + h * 32);
        float sc = 0.f;
#pragma unroll
        for (int d4 = 0; d4 < 8; d4++) {
            float4 q4 = qp[d4];
            sc += q4.x * kreg[d4 * 4] + q4.y * kreg[d4 * 4 + 1]
                + q4.z * kreg[d4 * 4 + 2] + q4.w * kreg[d4 * 4 + 3];
        }
        sc *= 0.1767766952966369f;
        float m = sc;
#pragma unroll
        for (int off = 16; off > 0; off >>= 1)
            m = fmaxf(m, __shfl_xor_sync(0xffffffffu, m, off));
        float pr = expf(sc - m);
        float ss = pr;
#pragma unroll
        for (int off = 16; off > 0; off >>= 1)
            ss += __shfl_xor_sync(0xffffffffu, ss, off);
        float att = pr / ss;
        float o = 0.f;
#pragma unroll
        for (int kk = 0; kk < 32; kk++) {
            float av = __shfl_sync(0xffffffffu, att, kk);
            o = fmaf(av, s_kv[kk * 261 + 128 + h * 32 + lane], o);
        }
        g_ao[((size_t)sp * 32 + q) * 128 + h * 32 + lane] = to_tf32(o);
    }
}

// ---------------- finish ----------------
__global__ __launch_bounds__(128) void k_finish(const float* __restrict__ ln2_g,
                                                const float* __restrict__ ln2_b) {
    int t = blockIdx.x;
    int tid = threadIdx.x, lane = tid & 31, w = tid >> 5;
    float y[8][4];
#pragma unroll
    for (int rr = 0; rr < 8; rr++)
#pragma unroll
        for (int j = 0; j < 4; j++) y[rr][j] = 0.f;

    for (int slot = 0; slot < 2; slot++) {
        int pr = t * 2 + slot;
        int sp = g_tok_sp[pr];
        int e = g_topidx[pr];
        float gate = g_topgate[pr];
        const float* g2 = ln2_g + e * 128;
        const float* b2 = ln2_b + e * 128;
        for (int rr = 0; rr < 8; rr++) {
            int r = w * 8 + rr;
            float v[4]; float sum = 0.f, sq = 0.f;
#pragma unroll
            for (int j = 0; j < 4; j++) {
                int c = lane + 32 * j;
                v[j] = g_h[((size_t)sp * 32 + r) * 128 + c]
                     + g_f2[((size_t)sp * 32 + r) * 128 + c];
                sum += v[j]; sq += v[j] * v[j];
            }
#pragma unroll
            for (int off = 16; off > 0; off >>= 1) {
                sum += __shfl_xor_sync(0xffffffffu, sum, off);
                sq  += __shfl_xor_sync(0xffffffffu, sq, off);
            }
            float mu = sum * (1.f / 128.f);
            float var = sq * (1.f / 128.f) - mu * mu;
            float rs = rsqrtf(var + 1e-5f);
#pragma unroll
            for (int j = 0; j < 4; j++) {
                int c = lane + 32 * j;
                y[rr][j] += gate * ((v[j] - mu) * rs * g2[c] + b2[c]);
            }
        }
    }
    for (int rr = 0; rr < 8; rr++) {
        int r = w * 8 + rr;
#pragma unroll
        for (int j = 0; j < 4; j++) {
            int c = lane + 32 * j;
            g_y[(size_t)t * ND + r * 128 + c] = to_tf32(y[rr][j]);
        }
    }
}

// ---------------- head2: fused split-K reduce + relu + GEMV ----------------
__global__ void k_head2(const float* __restrict__ hb1,
                        const float* __restrict__ hw2, const float* __restrict__ hb2,
                        float* __restrict__ out_r) {
    int b = blockIdx.x;
    int j = threadIdx.x >> 5;
    int lane = threadIdx.x & 31;
    const float* w = hw2 + (size_t)j * HH;
    float s = 0.f;
    for (int k = lane; k < HH; k += 32) {
        size_t i = (size_t)b * HH + k;
        float hsum = g_hp[i] + g_hp[(size_t)B_TOK * HH + i]
                   + g_hp[2 * (size_t)B_TOK * HH + i]
                   + g_hp[3 * (size_t)B_TOK * HH + i] + hb1[k];
        s = fmaf(fmaxf(hsum, 0.f), w[k], s);
    }
#pragma unroll
    for (int off = 16; off > 0; off >>= 1) s += __shfl_xor_sync(0xffffffffu, s, off);
    if (lane == 0) out_r[b * NR + j] = s + hb2[j];
}

// ---------------- loss ----------------
__global__ void k_loss(const float* __restrict__ gates, float* __restrict__ out_loss) {
    __shared__ float s_imp[8][32], s_ld[8][32], s_lse[256];
    int t = threadIdx.x;
    int e = t & 7, c = t >> 3;
    float imp = 0.f, ld = 0.f;
    for (int b = c; b < B_TOK; b += 32) {
        float g = gates[b * 8 + e];
        imp += g;
        if (g > 0.f) ld += 1.f;
    }
    s_imp[e][c] = imp; s_ld[e][c] = ld;
    float ls = 0.f;
    for (int b = t; b < B_TOK; b += 256) ls += g_lse[b];
    s_lse[t] = ls;
    __syncthreads();
    for (int s = 128; s > 0; s >>= 1) {
        if (t < s) s_lse[t] += s_lse[t + s];
        __syncthreads();
    }
    if (t == 0) {
        float I[8], L[8];
        float mi = 0.f, ml = 0.f;
        for (int e2 = 0; e2 < 8; e2++) {
            float si = 0.f, sl = 0.f;
            for (int c2 = 0; c2 < 32; c2++) { si += s_imp[e2][c2]; sl += s_ld[e2][c2]; }
            I[e2] = si; L[e2] = sl; mi += si; ml += sl;
        }
        mi *= 0.125f; ml *= 0.125f;
        float vi = 0.f, vl = 0.f;
        for (int e2 = 0; e2 < 8; e2++) {
            vi += (I[e2] - mi) * (I[e2] - mi);
            vl += (L[e2] - ml) * (L[e2] - ml);
        }
        vi /= 7.f; vl /= 7.f;
        float loss = vi / (mi * mi + 1e-10f) + vl / (ml * ml + 1e-10f)
                   + s_lse[0] * (1.f / (float)B_TOK);
        *out_loss = loss;
    }
}

// ---------------- launch ----------------
extern "C" void kernel_launch(void* const* d_in, const int* in_sizes, int n_in,
                              void* d_out, int out_size) {
    const float* z      = (const float*)d_in[0];
    const float* a      = (const float*)d_in[1];
    const float* w_gate = (const float*)d_in[2];
    const float* w_in   = (const float*)d_in[3];
    const float* b_in   = (const float*)d_in[4];
    const float* w_out  = (const float*)d_in[5];
    const float* b_out  = (const float*)d_in[6];
    const float* ln1_g  = (const float*)d_in[7];
    const float* ln1_b  = (const float*)d_in[8];
    const float* w1     = (const float*)d_in[9];
    const float* b1     = (const float*)d_in[10];
    const float* w2     = (const float*)d_in[11];
    const float* b2     = (const float*)d_in[12];
    const float* ln2_g  = (const float*)d_in[13];
    const float* ln2_b  = (const float*)d_in[14];
    const float* hw1    = (const float*)d_in[15];
    const float* hb1    = (const float*)d_in[16];
    const float* hw2    = (const float*)d_in[17];
    const float* hb2    = (const float*)d_in[18];

    float* out       = (float*)d_out;
    float* gates_out = out + B_TOK * NR;
    float* loss_out  = out + B_TOK * NR + B_TOK * NEXP;

    cudaFuncSetAttribute(k_gemm<0, 0>, cudaFuncAttributeMaxDynamicSharedMemorySize, GEMM_SMEM_BYTES);
    cudaFuncSetAttribute(k_gemm<1, 1>, cudaFuncAttributeMaxDynamicSharedMemorySize, GEMM_SMEM_BYTES);
    cudaFuncSetAttribute(k_head1, cudaFuncAttributeMaxDynamicSharedMemorySize, GEMM_SMEM_BYTES);
    cudaFuncSetAttribute(k_ffn, cudaFuncAttributeMaxDynamicSharedMemorySize, FFN_SMEM_BYTES);

    k_round<<<(RW4 + 255) / 256, 256>>>(w_in, w_out, w1, w2, hw1);
    k_router<<<B_TOK, 256>>>(z, a, w_gate, gates_out);
    k_sort<<<1, 256>>>();

    // qkv = x @ w_in^T + b_in
    k_gemm<0, 0><<<dim3(GROUP_MAX, 3), 256, GEMM_SMEM_BYTES>>>(b_in, 384, nullptr, nullptr);
    k_attn<<<PAIR_MAX, 128>>>();
    // o-proj + fused residual + LN1 -> g_h
    k_gemm<1, 1><<<dim3(GROUP_MAX, 1), 256, GEMM_SMEM_BYTES>>>(b_out, 128, ln1_g, ln1_b);
    // fused FFN
    k_ffn<<<dim3(GROUP_MAX, 2), 256, FFN_SMEM_BYTES>>>(b1, b2);
    k_finish<<<B_TOK, 128>>>(ln2_g, ln2_b);
    // head1 split-K; head2 fuses reduce+relu+GEMV
    k_head1<<<dim3(8, 4, 4), 256, GEMM_SMEM_BYTES>>>();
    k_head2<<<B_TOK, 128>>>(hb1, hw2, hb2, out);
    k_loss<<<1, 256>>>(gates_out, loss_out);
}

// round 14
// speedup vs baseline: 1.6794x; 1.2405x over previous
#include <cuda_runtime.h>
#include <cuda_bf16.h>
#include <cuda_fp16.h>
#include <cstdint>

// ---------------- problem constants ----------------
#define B_TOK   1024
#define NA      32
#define DZ      96
#define DA      32
#define DMODEL  128
#define ND      4096      // NA*DMODEL
#define NEXP    8
#define FF      1024
#define HH      512
#define NR      4
#define KTOP    2

#define PAIR_MAX  2072
#define GROUP_MAX 518

// ---------------- scratch ----------------
__device__ float g_x [B_TOK * ND];               // concat(z,a), UNROUNDED
__device__ float g_xt[B_TOK * ND];               // tf32-rounded copy
__device__ float g_y [B_TOK * ND];
__device__ float g_qkv[(size_t)PAIR_MAX * 32 * 384];
__device__ float g_ao [(size_t)PAIR_MAX * 32 * 128];
__device__ float g_h  [(size_t)PAIR_MAX * 32 * 128];
__device__ __half g_hh[(size_t)PAIR_MAX * 32 * 128];   // half copy for FFN
__device__ float g_f2 [(size_t)PAIR_MAX * 32 * 128];
__device__ float g_hp [4 * B_TOK * HH];
__device__ float g_lse[B_TOK];
__device__ int   g_topidx[B_TOK * KTOP];
__device__ float g_topgate[B_TOK * KTOP];

// rounded weight copies (ONLY referenced from device code!)
__device__ float  g_wint [NEXP * 384 * 128];
__device__ float  g_woutt[NEXP * 128 * 128];
__device__ __half g_w1h  [NEXP * 1024 * 128];
__device__ __half g_w2h  [NEXP * 128 * 1024];
__device__ float  g_hw1t [HH * ND];

__device__ int   g_ngroups;
__device__ int   g_npad;
__device__ int   g_grp_expert[GROUP_MAX];
__device__ int   g_sp_pair[PAIR_MAX];
__device__ int   g_tok_sp[B_TOK * KTOP];

// ---------------- helpers ----------------
__device__ __forceinline__ float to_tf32(float f) {
    uint32_t u;
    asm("cvt.rna.tf32.f32 %0, %1;" : "=r"(u) : "f"(f));
    return __uint_as_float(u);
}

__device__ __forceinline__ void mma_tf32(float* c, const uint32_t* a, const uint32_t* b) {
    asm volatile(
        "mma.sync.aligned.m16n8k8.row.col.f32.tf32.tf32.f32 "
        "{%0,%1,%2,%3},{%4,%5,%6,%7},{%8,%9},{%0,%1,%2,%3};"
        : "+f"(c[0]), "+f"(c[1]), "+f"(c[2]), "+f"(c[3])
        : "r"(a[0]), "r"(a[1]), "r"(a[2]), "r"(a[3]), "r"(b[0]), "r"(b[1]));
}

__device__ __forceinline__ void mma_f16(float* c, const uint32_t* a, const uint32_t* b) {
    asm volatile(
        "mma.sync.aligned.m16n8k16.row.col.f32.f16.f16.f32 "
        "{%0,%1,%2,%3},{%4,%5,%6,%7},{%8,%9},{%0,%1,%2,%3};"
        : "+f"(c[0]), "+f"(c[1]), "+f"(c[2]), "+f"(c[3])
        : "r"(a[0]), "r"(a[1]), "r"(a[2]), "r"(a[3]), "r"(b[0]), "r"(b[1]));
}

__device__ __forceinline__ void cp_async16(uint32_t saddr, const void* gaddr) {
    asm volatile("cp.async.cg.shared.global [%0], [%1], 16;\n" :: "r"(saddr), "l"(gaddr));
}
#define CP_COMMIT() asm volatile("cp.async.commit_group;\n")
#define CP_WAIT1()  asm volatile("cp.async.wait_group 1;\n")
#define CP_WAIT0()  asm volatile("cp.async.wait_group 0;\n")

// ---------------- weight rounding prep ----------------
#define RW0 (NEXP * 384 * 128)
#define RW1 (RW0 + NEXP * 128 * 128)
#define RW2 (RW1 + NEXP * 1024 * 128)
#define RW3 (RW2 + NEXP * 128 * 1024)
#define RW4 (RW3 + HH * ND)
__global__ void k_round(const float* __restrict__ w_in, const float* __restrict__ w_out,
                        const float* __restrict__ w1, const float* __restrict__ w2,
                        const float* __restrict__ hw1) {
    int i = blockIdx.x * 256 + threadIdx.x;
    if (i < RW0)      g_wint[i]        = to_tf32(w_in[i]);
    else if (i < RW1) g_woutt[i - RW0] = to_tf32(w_out[i - RW0]);
    else if (i < RW2) g_w1h[i - RW1]   = __float2half_rn(w1[i - RW1]);
    else if (i < RW3) g_w2h[i - RW2]   = __float2half_rn(w2[i - RW2]);
    else if (i < RW4) g_hw1t[i - RW3]  = to_tf32(hw1[i - RW3]);
}

// ---------------- router + fused concat ----------------
__global__ __launch_bounds__(256) void k_router(const float* __restrict__ z,
                                                const float* __restrict__ a,
                                                const float* __restrict__ w_gate,
                                                float* __restrict__ gates_out) {
    __shared__ float red[256 * 8];
    int b = blockIdx.x, tid = threadIdx.x;
    float p[8];
#pragma unroll
    for (int e = 0; e < 8; e++) p[e] = 0.f;
    for (int k = tid; k < ND; k += 256) {
        int dd = k & 127;
        int row = b * 32 + (k >> 7);
        float xv = (dd < DZ) ? z[row * DZ + dd] : a[row * DA + (dd - DZ)];
        g_x [(size_t)b * ND + k] = xv;
        g_xt[(size_t)b * ND + k] = to_tf32(xv);
        const float4* wg = reinterpret_cast<const float4*>(w_gate + (size_t)k * 8);
        float4 w0 = wg[0], w1 = wg[1];
        p[0] = fmaf(xv, w0.x, p[0]); p[1] = fmaf(xv, w0.y, p[1]);
        p[2] = fmaf(xv, w0.z, p[2]); p[3] = fmaf(xv, w0.w, p[3]);
        p[4] = fmaf(xv, w1.x, p[4]); p[5] = fmaf(xv, w1.y, p[5]);
        p[6] = fmaf(xv, w1.z, p[6]); p[7] = fmaf(xv, w1.w, p[7]);
    }
#pragma unroll
    for (int e = 0; e < 8; e++) red[tid * 8 + e] = p[e];
    __syncthreads();
    for (int s = 128; s > 0; s >>= 1) {
        if (tid < s) {
#pragma unroll
            for (int e = 0; e < 8; e++) red[tid * 8 + e] += red[(tid + s) * 8 + e];
        }
        __syncthreads();
    }
    if (tid == 0) {
        float l[8];
#pragma unroll
        for (int e = 0; e < 8; e++) l[e] = red[e];
        int i0 = 0; float v0 = l[0];
#pragma unroll
        for (int e = 1; e < 8; e++) if (l[e] > v0) { v0 = l[e]; i0 = e; }
        int i1 = -1; float v1 = -3.4e38f;
#pragma unroll
        for (int e = 0; e < 8; e++) if (e != i0 && l[e] > v1) { v1 = l[e]; i1 = e; }
        float e1 = expf(v1 - v0);
        float inv = 1.f / (1.f + e1);
        float g0 = inv, g1v = e1 * inv;
#pragma unroll
        for (int e = 0; e < 8; e++)
            gates_out[b * 8 + e] = (e == i0) ? g0 : ((e == i1) ? g1v : 0.f);
        g_topidx[b * 2] = i0;  g_topidx[b * 2 + 1] = i1;
        g_topgate[b * 2] = g0; g_topgate[b * 2 + 1] = g1v;
        float s = 0.f;
#pragma unroll
        for (int e = 0; e < 8; e++) s += expf(l[e] - v0);
        g_lse[b] = v0 + logf(s);
    }
}

// ---------------- parallel deterministic counting sort ----------------
__global__ __launch_bounds__(256) void k_sort() {
    __shared__ int s_cnt[256][8];
    __shared__ int s_ecnt[8];
    __shared__ int s_base[8];
    int t = threadIdx.x;
    int my[8];
    int lc[8] = {0, 0, 0, 0, 0, 0, 0, 0};
#pragma unroll
    for (int i = 0; i < 8; i++) {
        int e = g_topidx[t * 8 + i];
        my[i] = e;
        lc[e]++;
    }
#pragma unroll
    for (int e = 0; e < 8; e++) s_cnt[t][e] = lc[e];
    __syncthreads();
    if (t < 8) {
        int off = 0;
        for (int i = 0; i < 256; i++) {
            int v = s_cnt[i][t];
            s_cnt[i][t] = off;
            off += v;
        }
        s_ecnt[t] = off;
    }
    __syncthreads();
    if (t == 0) {
        int o = 0, g = 0;
        for (int e = 0; e < 8; e++) {
            s_base[e] = o;
            int pc = (s_ecnt[e] + 3) & ~3;
            for (int i = 0; i < (pc >> 2); i++) g_grp_expert[g++] = e;
            o += pc;
        }
        g_ngroups = g;
        g_npad = o;
    }
    __syncthreads();
#pragma unroll
    for (int i = 0; i < 8; i++) {
        int p = t * 8 + i;
        int e = my[i];
        int sp = s_base[e] + s_cnt[t][e]++;
        g_sp_pair[sp] = p;
        g_tok_sp[p] = sp;
    }
    if (t < 8) {
        int start = s_base[t] + s_ecnt[t];
        int end = s_base[t] + ((s_ecnt[t] + 3) & ~3);
        for (int sp = start; sp < end; sp++) g_sp_pair[sp] = -1;
    }
}

// ---------------- cp.async stage helpers ----------------
__device__ __forceinline__ void gemm_issue(uint32_t smu, int buf, int kc,
                                           const float* const* s_ab,
                                           const float* wb, int tid) {
#pragma unroll
    for (int it = 0; it < 4; it++) {
        int i = tid + it * 256;
        int r = i >> 3, q = (i & 7) * 4;
        cp_async16(smu + (uint32_t)(buf * 4608 + r * 36 + q) * 4,
                   s_ab[r >> 5] + (size_t)(r & 31) * 128 + kc + q);
        cp_async16(smu + (uint32_t)(9216 + buf * 4608 + r * 36 + q) * 4,
                   wb + (size_t)r * 128 + kc + q);
    }
    CP_COMMIT();
}

__device__ __forceinline__ void head_issue(uint32_t smu, int buf, int kc,
                                           const float* Ab, const float* Bb, int tid) {
#pragma unroll
    for (int it = 0; it < 4; it++) {
        int i = tid + it * 256;
        int r = i >> 3, q = (i & 7) * 4;
        cp_async16(smu + (uint32_t)(buf * 4608 + r * 36 + q) * 4,
                   Ab + (size_t)r * ND + kc + q);
        cp_async16(smu + (uint32_t)(9216 + buf * 4608 + r * 36 + q) * 4,
                   Bb + (size_t)r * ND + kc + q);
    }
    CP_COMMIT();
}

// ---------------- tf32 batched GEMM (cp.async double-buffered) ----------------
// DST==0: qkv -> g_qkv.  DST==1: o-proj with FUSED residual+LN1 -> g_h + g_hh.
#define GEMM_SMEM_BYTES 73728
template<int SRC, int DST>
__global__ __launch_bounds__(256) void k_gemm(const float* __restrict__ bias, int Ntot,
                                              const float* __restrict__ ln1_g,
                                              const float* __restrict__ ln1_b) {
    int g = blockIdx.x;
    if (g >= g_ngroups) return;
    int e = g_grp_expert[g];
    int n0 = blockIdx.y * 128;
    int tid = threadIdx.x, lane = tid & 31, w = tid >> 5;

    extern __shared__ float sm[];
    uint32_t smu = (uint32_t)__cvta_generic_to_shared(sm);
    __shared__ const float* s_ab[4];
    if (tid < 4) {
        const float* ab;
        if (SRC == 0) {
            int pr = g_sp_pair[g * 4 + tid];
            int tok = (pr >= 0) ? (pr >> 1) : 0;
            ab = g_xt + (size_t)tok * ND;
        } else {
            ab = g_ao + (size_t)(g * 4 + tid) * 32 * 128;
        }
        s_ab[tid] = ab;
    }
    __syncthreads();

    const float* W = (SRC == 0) ? g_wint : g_woutt;
    const float* wb = W + (size_t)e * Ntot * 128 + (size_t)n0 * 128;

    float acc[2][8][4];
#pragma unroll
    for (int i = 0; i < 2; i++)
#pragma unroll
        for (int j = 0; j < 8; j++)
#pragma unroll
            for (int k = 0; k < 4; k++) acc[i][j][k] = 0.f;

    int mt_base = (w & 3) * 2;
    int nt_base = (w >> 2) * 8;

    gemm_issue(smu, 0, 0, s_ab, wb, tid);
    for (int c = 0; c < 4; c++) {
        if (c + 1 < 4) { gemm_issue(smu, (c + 1) & 1, (c + 1) * 32, s_ab, wb, tid); CP_WAIT1(); }
        else CP_WAIT0();
        __syncthreads();
        const float* sA = sm + (c & 1) * 4608;
        const float* sB = sm + 9216 + (c & 1) * 4608;
#pragma unroll
        for (int ks = 0; ks < 4; ks++) {
            int col = ks * 8 + (lane & 3);
            uint32_t a[2][4];
#pragma unroll
            for (int mt = 0; mt < 2; mt++) {
                int r0 = (mt_base + mt) * 16 + (lane >> 2);
                a[mt][0] = __float_as_uint(sA[r0 * 36 + col]);
                a[mt][1] = __float_as_uint(sA[(r0 + 8) * 36 + col]);
                a[mt][2] = __float_as_uint(sA[r0 * 36 + col + 4]);
                a[mt][3] = __float_as_uint(sA[(r0 + 8) * 36 + col + 4]);
            }
#pragma unroll
            for (int nt = 0; nt < 8; nt++) {
                int nr = (nt_base + nt) * 8 + (lane >> 2);
                uint32_t b[2];
                b[0] = __float_as_uint(sB[nr * 36 + col]);
                b[1] = __float_as_uint(sB[nr * 36 + col + 4]);
                mma_tf32(acc[0][nt], a[0], b);
                mma_tf32(acc[1][nt], a[1], b);
            }
        }
        __syncthreads();
    }

    if (DST == 0) {
#pragma unroll
        for (int mt = 0; mt < 2; mt++) {
            int r0 = (mt_base + mt) * 16 + (lane >> 2);
            int r1 = r0 + 8;
#pragma unroll
            for (int nt = 0; nt < 8; nt++) {
                int nc = n0 + (nt_base + nt) * 8 + 2 * (lane & 3);
                float2 bv = *reinterpret_cast<const float2*>(bias + (size_t)e * Ntot + nc);
                float2 o0, o1;
                o0.x = acc[mt][nt][0] + bv.x; o0.y = acc[mt][nt][1] + bv.y;
                o1.x = acc[mt][nt][2] + bv.x; o1.y = acc[mt][nt][3] + bv.y;
                *reinterpret_cast<float2*>(g_qkv + ((size_t)g * 128 + r0) * Ntot + nc) = o0;
                *reinterpret_cast<float2*>(g_qkv + ((size_t)g * 128 + r1) * Ntot + nc) = o1;
            }
        }
    } else {
        float* sO = sm;
#pragma unroll
        for (int mt = 0; mt < 2; mt++) {
            int r0 = (mt_base + mt) * 16 + (lane >> 2);
            int r1 = r0 + 8;
#pragma unroll
            for (int nt = 0; nt < 8; nt++) {
                int nc = (nt_base + nt) * 8 + 2 * (lane & 3);
                float2 bv = *reinterpret_cast<const float2*>(bias + (size_t)e * 128 + nc);
                sO[r0 * 132 + nc]     = acc[mt][nt][0] + bv.x;
                sO[r0 * 132 + nc + 1] = acc[mt][nt][1] + bv.y;
                sO[r1 * 132 + nc]     = acc[mt][nt][2] + bv.x;
                sO[r1 * 132 + nc + 1] = acc[mt][nt][3] + bv.y;
            }
        }
        __syncthreads();
        const float* g1 = ln1_g + e * 128;
        const float* b1 = ln1_b + e * 128;
        for (int rr = 0; rr < 16; rr++) {
            int r = w * 16 + rr;
            int sp = g * 4 + (r >> 5);
            int pr = g_sp_pair[sp];
            if (pr < 0) continue;
            int token = pr >> 1;
            float v[4]; float sum = 0.f, sq = 0.f;
#pragma unroll
            for (int j = 0; j < 4; j++) {
                int c = lane + 32 * j;
                v[j] = g_x[(size_t)token * ND + (r & 31) * 128 + c] + sO[r * 132 + c];
                sum += v[j]; sq += v[j] * v[j];
            }
#pragma unroll
            for (int off = 16; off > 0; off >>= 1) {
                sum += __shfl_xor_sync(0xffffffffu, sum, off);
                sq  += __shfl_xor_sync(0xffffffffu, sq, off);
            }
            float mu = sum * (1.f / 128.f);
            float var = sq * (1.f / 128.f) - mu * mu;
            float rs = rsqrtf(var + 1e-5f);
#pragma unroll
            for (int j = 0; j < 4; j++) {
                int c = lane + 32 * j;
                float lnv = (v[j] - mu) * rs * g1[c] + b1[c];
                g_h [((size_t)g * 128 + r) * 128 + c] = to_tf32(lnv);
                g_hh[((size_t)g * 128 + r) * 128 + c] = __float2half_rn(lnv);
            }
        }
    }
}

// ---------------- head1: split-K tf32 GEMM (cp.async double-buffered) ----------------
__global__ __launch_bounds__(256) void k_head1() {
    int bm = blockIdx.x, bn = blockIdx.y, ks4 = blockIdx.z;
    int tid = threadIdx.x, lane = tid & 31, w = tid >> 5;

    extern __shared__ float sm[];
    uint32_t smu = (uint32_t)__cvta_generic_to_shared(sm);

    const float* Ab = g_y + (size_t)(bm * 128) * ND + ks4 * 1024;
    const float* Bb = g_hw1t + (size_t)(bn * 128) * ND + ks4 * 1024;

    float acc[2][8][4];
#pragma unroll
    for (int i = 0; i < 2; i++)
#pragma unroll
        for (int j = 0; j < 8; j++)
#pragma unroll
            for (int k = 0; k < 4; k++) acc[i][j][k] = 0.f;

    int mt_base = (w & 3) * 2;
    int nt_base = (w >> 2) * 8;

    head_issue(smu, 0, 0, Ab, Bb, tid);
    for (int c = 0; c < 32; c++) {
        if (c + 1 < 32) { head_issue(smu, (c + 1) & 1, (c + 1) * 32, Ab, Bb, tid); CP_WAIT1(); }
        else CP_WAIT0();
        __syncthreads();
        const float* sA = sm + (c & 1) * 4608;
        const float* sB = sm + 9216 + (c & 1) * 4608;
#pragma unroll
        for (int ks = 0; ks < 4; ks++) {
            int col = ks * 8 + (lane & 3);
            uint32_t a[2][4];
#pragma unroll
            for (int mt = 0; mt < 2; mt++) {
                int r0 = (mt_base + mt) * 16 + (lane >> 2);
                a[mt][0] = __float_as_uint(sA[r0 * 36 + col]);
                a[mt][1] = __float_as_uint(sA[(r0 + 8) * 36 + col]);
                a[mt][2] = __float_as_uint(sA[r0 * 36 + col + 4]);
                a[mt][3] = __float_as_uint(sA[(r0 + 8) * 36 + col + 4]);
            }
#pragma unroll
            for (int nt = 0; nt < 8; nt++) {
                int nr = (nt_base + nt) * 8 + (lane >> 2);
                uint32_t b[2];
                b[0] = __float_as_uint(sB[nr * 36 + col]);
                b[1] = __float_as_uint(sB[nr * 36 + col + 4]);
                mma_tf32(acc[0][nt], a[0], b);
                mma_tf32(acc[1][nt], a[1], b);
            }
        }
        __syncthreads();
    }

    float* dst = g_hp + ((size_t)ks4 * B_TOK + bm * 128) * HH + bn * 128;
#pragma unroll
    for (int mt = 0; mt < 2; mt++) {
        int r0 = (mt_base + mt) * 16 + (lane >> 2);
        int r1 = r0 + 8;
#pragma unroll
        for (int nt = 0; nt < 8; nt++) {
            int nc = (nt_base + nt) * 8 + 2 * (lane & 3);
            float2 o0, o1;
            o0.x = acc[mt][nt][0]; o0.y = acc[mt][nt][1];
            o1.x = acc[mt][nt][2]; o1.y = acc[mt][nt][3];
            *reinterpret_cast<float2*>(dst + (size_t)r0 * HH + nc) = o0;
            *reinterpret_cast<float2*>(dst + (size_t)r1 * HH + nc) = o1;
        }
    }
}

// ---------------- fused FFN: fp16 mma (m16n8k16), K=64 stages ----------------
// smem halves: sA[64*136]=8704 | sW ring 2*[128*72]=18432 | sF[64*136]=8704
// bytes: 17408 + 36864 + 17408 = 71680
#define FFN_SMEM_BYTES 71680
__device__ __forceinline__ void ffn_issue_h(uint32_t smu, int s,
                                            const __half* w1b, const __half* w2b, int tid) {
    int c = s >> 2, ph = (s >> 1) & 1, kc = s & 1;
    const __half* base;
    int rstride;
    if (ph) { base = w2b + c * 128 + kc * 64;                  rstride = 1024; }
    else    { base = w1b + (size_t)(c * 128) * 128 + kc * 64;  rstride = 128; }
#pragma unroll
    for (int it = 0; it < 4; it++) {
        int i = tid + it * 256;
        int r = i >> 3, q = (i & 7) * 8;
        cp_async16(smu + (uint32_t)(8704 + (s & 1) * 9216 + r * 72 + q) * 2,
                   base + (size_t)r * rstride + q);
    }
    CP_COMMIT();
}

__global__ __launch_bounds__(256) void k_ffn(const float* __restrict__ B1,
                                             const float* __restrict__ B2) {
    int g = blockIdx.x;
    if (g >= g_ngroups) return;
    int hf = blockIdx.y;
    int e = g_grp_expert[g];
    int tid = threadIdx.x, lane = tid & 31, w = tid >> 5;

    extern __shared__ __half smh[];
    __half* sA = smh;                    // 64 x 136
    __half* sW = smh + 8704;             // 2 x 128 x 72
    __half* sF = smh + 8704 + 18432;     // 64 x 136
    uint32_t smu = (uint32_t)__cvta_generic_to_shared(smh);

    const __half* hb  = g_hh + ((size_t)g * 128 + hf * 64) * 128;
    const __half* w1b = g_w1h + (size_t)e * 1024 * 128;
    const __half* w2b = g_w2h + (size_t)e * 128 * 1024;

    // load h tile: 64 x 128 halves = 16 KB (16B chunks)
#pragma unroll
    for (int it = 0; it < 4; it++) {
        int i = tid + it * 256;
        int r = i >> 4, q = (i & 15) * 8;
        *reinterpret_cast<float4*>(sA + r * 136 + q) =
            *reinterpret_cast<const float4*>(hb + (size_t)r * 128 + q);
    }

    int mt_base = (w & 1) * 2;
    int nt_base = (w >> 1) * 4;
    int rq = lane >> 2;
    int k2 = (lane & 3) * 2;

    float acc1[2][4][4], acc2[2][4][4];
#pragma unroll
    for (int mt = 0; mt < 2; mt++)
#pragma unroll
        for (int j = 0; j < 4; j++)
#pragma unroll
            for (int k = 0; k < 4; k++) acc2[mt][j][k] = 0.f;

    ffn_issue_h(smu, 0, w1b, w2b, tid);
    ffn_issue_h(smu, 1, w1b, w2b, tid);

    for (int s = 0; s < 32; s++) {
        if (s < 31) CP_WAIT1(); else CP_WAIT0();
        __syncthreads();                       // sW[s&1] ready; covers sA load at s=0
        if ((s & 3) == 0) {
#pragma unroll
            for (int mt = 0; mt < 2; mt++)
#pragma unroll
                for (int j = 0; j < 4; j++)
#pragma unroll
                    for (int k = 0; k < 4; k++) acc1[mt][j][k] = 0.f;
        }
        int ph = (s >> 1) & 1;
        int kc = s & 1;
        const __half* sWb = sW + (s & 1) * 9216;
        if (!ph) {
#pragma unroll
            for (int kh = 0; kh < 4; kh++) {
                int kpos = kc * 64 + kh * 16 + k2;
                int kb = kh * 16 + k2;
                uint32_t a[2][4];
#pragma unroll
                for (int mt = 0; mt < 2; mt++) {
                    int r0 = (mt_base + mt) * 16 + rq;
                    a[mt][0] = *reinterpret_cast<const uint32_t*>(sA + r0 * 136 + kpos);
                    a[mt][1] = *reinterpret_cast<const uint32_t*>(sA + (r0 + 8) * 136 + kpos);
                    a[mt][2] = *reinterpret_cast<const uint32_t*>(sA + r0 * 136 + kpos + 8);
                    a[mt][3] = *reinterpret_cast<const uint32_t*>(sA + (r0 + 8) * 136 + kpos + 8);
                }
#pragma unroll
                for (int nt = 0; nt < 4; nt++) {
                    int nr = (nt_base + nt) * 8 + rq;
                    uint32_t b[2];
                    b[0] = *reinterpret_cast<const uint32_t*>(sWb + nr * 72 + kb);
                    b[1] = *reinterpret_cast<const uint32_t*>(sWb + nr * 72 + kb + 8);
                    mma_f16(acc1[0][nt], a[0], b);
                    mma_f16(acc1[1][nt], a[1], b);
                }
            }
        } else {
#pragma unroll
            for (int kh = 0; kh < 4; kh++) {
                int kpos = kc * 64 + kh * 16 + k2;
                int kb = kh * 16 + k2;
                uint32_t a[2][4];
#pragma unroll
                for (int mt = 0; mt < 2; mt++) {
                    int r0 = (mt_base + mt) * 16 + rq;
                    a[mt][0] = *reinterpret_cast<const uint32_t*>(sF + r0 * 136 + kpos);
                    a[mt][1] = *reinterpret_cast<const uint32_t*>(sF + (r0 + 8) * 136 + kpos);
                    a[mt][2] = *reinterpret_cast<const uint32_t*>(sF + r0 * 136 + kpos + 8);
                    a[mt][3] = *reinterpret_cast<const uint32_t*>(sF + (r0 + 8) * 136 + kpos + 8);
                }
#pragma unroll
                for (int nt = 0; nt < 4; nt++) {
                    int nr = (nt_base + nt) * 8 + rq;
                    uint32_t b[2];
                    b[0] = *reinterpret_cast<const uint32_t*>(sWb + nr * 72 + kb);
                    b[1] = *reinterpret_cast<const uint32_t*>(sWb + nr * 72 + kb + 8);
                    mma_f16(acc2[0][nt], a[0], b);
                    mma_f16(acc2[1][nt], a[1], b);
                }
            }
        }
        __syncthreads();                       // mma done before sW reuse / sF write
        if ((s & 3) == 1) {
            int c = s >> 2;
#pragma unroll
            for (int mt = 0; mt < 2; mt++) {
                int r0 = (mt_base + mt) * 16 + rq;
#pragma unroll
                for (int nt = 0; nt < 4; nt++) {
                    int nc = (nt_base + nt) * 8 + 2 * (lane & 3);
                    float2 bv = *reinterpret_cast<const float2*>(B1 + (size_t)e * 1024 + c * 128 + nc);
                    __half2 h0 = __floats2half2_rn(fmaxf(acc1[mt][nt][0] + bv.x, 0.f),
                                                   fmaxf(acc1[mt][nt][1] + bv.y, 0.f));
                    __half2 h1 = __floats2half2_rn(fmaxf(acc1[mt][nt][2] + bv.x, 0.f),
                                                   fmaxf(acc1[mt][nt][3] + bv.y, 0.f));
                    *reinterpret_cast<__half2*>(sF + r0 * 136 + nc) = h0;
                    *reinterpret_cast<__half2*>(sF + (r0 + 8) * 136 + nc) = h1;
                }
            }
            __syncthreads();                   // sF visible before stage-2 reads
        }
        if (s + 2 < 32) ffn_issue_h(smu, s + 2, w1b, w2b, tid);
    }

    {
        float* f2b = g_f2 + ((size_t)g * 128 + hf * 64) * 128;
#pragma unroll
        for (int mt = 0; mt < 2; mt++) {
            int r0 = (mt_base + mt) * 16 + rq;
#pragma unroll
            for (int nt = 0; nt < 4; nt++) {
                int nc = (nt_base + nt) * 8 + 2 * (lane & 3);
                float2 bv = *reinterpret_cast<const float2*>(B2 + (size_t)e * 128 + nc);
                float2 o0, o1;
                o0.x = acc2[mt][nt][0] + bv.x; o0.y = acc2[mt][nt][1] + bv.y;
                o1.x = acc2[mt][nt][2] + bv.x; o1.y = acc2[mt][nt][3] + bv.y;
                *reinterpret_cast<float2*>(f2b + (size_t)r0 * 128 + nc) = o0;
                *reinterpret_cast<float2*>(f2b + (size_t)(r0 + 8) * 128 + nc) = o1;
            }
        }
    }
}

// ---------------- attention ----------------
__global__ __launch_bounds__(128) void k_attn() {
    int sp = blockIdx.x;
    if (sp >= g_npad) return;
    if (g_sp_pair[sp] < 0) return;
    __shared__ float s_kv[32 * 261];
    int tid = threadIdx.x, lane = tid & 31, h = tid >> 5;
    for (int i = tid; i < 32 * 256; i += 128) {
        int r = i >> 8, c = i & 255;
        s_kv[r * 261 + c] = g_qkv[((size_t)sp * 32 + r) * 384 + 128 + c];
    }
    __syncthreads();
    float kreg[32];
#pragma unroll
    for (int d = 0; d < 32; d++) kreg[d] = s_kv[lane * 261 + h * 32 + d];
    const float* qb = g_qkv + (size_t)sp * 32 * 384;
    for (int q = 0; q < 32; q++) {
        const float4* qp = reinterpret_cast<const float4*>(qb + q * 384 + h * 32);
        float sc = 0.f;
#pragma unroll
        for (int d4 = 0; d4 < 8; d4++) {
            float4 q4 = qp[d4];
            sc += q4.x * kreg[d4 * 4] + q4.y * kreg[d4 * 4 + 1]
                + q4.z * kreg[d4 * 4 + 2] + q4.w * kreg[d4 * 4 + 3];
        }
        sc *= 0.1767766952966369f;
        float m = sc;
#pragma unroll
        for (int off = 16; off > 0; off >>= 1)
            m = fmaxf(m, __shfl_xor_sync(0xffffffffu, m, off));
        float pr = expf(sc - m);
        float ss = pr;
#pragma unroll
        for (int off = 16; off > 0; off >>= 1)
            ss += __shfl_xor_sync(0xffffffffu, ss, off);
        float att = pr / ss;
        float o = 0.f;
#pragma unroll
        for (int kk = 0; kk < 32; kk++) {
            float av = __shfl_sync(0xffffffffu, att, kk);
            o = fmaf(av, s_kv[kk * 261 + 128 + h * 32 + lane], o);
        }
        g_ao[((size_t)sp * 32 + q) * 128 + h * 32 + lane] = to_tf32(o);
    }
}

// ---------------- finish ----------------
__global__ __launch_bounds__(128) void k_finish(const float* __restrict__ ln2_g,
                                                const float* __restrict__ ln2_b) {
    int t = blockIdx.x;
    int tid = threadIdx.x, lane = tid & 31, w = tid >> 5;
    float y[8][4];
#pragma unroll
    for (int rr = 0; rr < 8; rr++)
#pragma unroll
        for (int j = 0; j < 4; j++) y[rr][j] = 0.f;

    for (int slot = 0; slot < 2; slot++) {
        int pr = t * 2 + slot;
        int sp = g_tok_sp[pr];
        int e = g_topidx[pr];
        float gate = g_topgate[pr];
        const float* g2 = ln2_g + e * 128;
        const float* b2 = ln2_b + e * 128;
        for (int rr = 0; rr < 8; rr++) {
            int r = w * 8 + rr;
            float v[4]; float sum = 0.f, sq = 0.f;
#pragma unroll
            for (int j = 0; j < 4; j++) {
                int c = lane + 32 * j;
                v[j] = g_h[((size_t)sp * 32 + r) * 128 + c]
                     + g_f2[((size_t)sp * 32 + r) * 128 + c];
                sum += v[j]; sq += v[j] * v[j];
            }
#pragma unroll
            for (int off = 16; off > 0; off >>= 1) {
                sum += __shfl_xor_sync(0xffffffffu, sum, off);
                sq  += __shfl_xor_sync(0xffffffffu, sq, off);
            }
            float mu = sum * (1.f / 128.f);
            float var = sq * (1.f / 128.f) - mu * mu;
            float rs = rsqrtf(var + 1e-5f);
#pragma unroll
            for (int j = 0; j < 4; j++) {
                int c = lane + 32 * j;
                y[rr][j] += gate * ((v[j] - mu) * rs * g2[c] + b2[c]);
            }
        }
    }
    for (int rr = 0; rr < 8; rr++) {
        int r = w * 8 + rr;
#pragma unroll
        for (int j = 0; j < 4; j++) {
            int c = lane + 32 * j;
            g_y[(size_t)t * ND + r * 128 + c] = to_tf32(y[rr][j]);
        }
    }
}

// ---------------- head2: fused split-K reduce + relu + GEMV ----------------
__global__ void k_head2(const float* __restrict__ hb1,
                        const float* __restrict__ hw2, const float* __restrict__ hb2,
                        float* __restrict__ out_r) {
    int b = blockIdx.x;
    int j = threadIdx.x >> 5;
    int lane = threadIdx.x & 31;
    const float* w = hw2 + (size_t)j * HH;
    float s = 0.f;
    for (int k = lane; k < HH; k += 32) {
        size_t i = (size_t)b * HH + k;
        float hsum = g_hp[i] + g_hp[(size_t)B_TOK * HH + i]
                   + g_hp[2 * (size_t)B_TOK * HH + i]
                   + g_hp[3 * (size_t)B_TOK * HH + i] + hb1[k];
        s = fmaf(fmaxf(hsum, 0.f), w[k], s);
    }
#pragma unroll
    for (int off = 16; off > 0; off >>= 1) s += __shfl_xor_sync(0xffffffffu, s, off);
    if (lane == 0) out_r[b * NR + j] = s + hb2[j];
}

// ---------------- loss ----------------
__global__ void k_loss(const float* __restrict__ gates, float* __restrict__ out_loss) {
    __shared__ float s_imp[8][32], s_ld[8][32], s_lse[256];
    int t = threadIdx.x;
    int e = t & 7, c = t >> 3;
    float imp = 0.f, ld = 0.f;
    for (int b = c; b < B_TOK; b += 32) {
        float g = gates[b * 8 + e];
        imp += g;
        if (g > 0.f) ld += 1.f;
    }
    s_imp[e][c] = imp; s_ld[e][c] = ld;
    float ls = 0.f;
    for (int b = t; b < B_TOK; b += 256) ls += g_lse[b];
    s_lse[t] = ls;
    __syncthreads();
    for (int s = 128; s > 0; s >>= 1) {
        if (t < s) s_lse[t] += s_lse[t + s];
        __syncthreads();
    }
    if (t == 0) {
        float I[8], L[8];
        float mi = 0.f, ml = 0.f;
        for (int e2 = 0; e2 < 8; e2++) {
            float si = 0.f, sl = 0.f;
            for (int c2 = 0; c2 < 32; c2++) { si += s_imp[e2][c2]; sl += s_ld[e2][c2]; }
            I[e2] = si; L[e2] = sl; mi += si; ml += sl;
        }
        mi *= 0.125f; ml *= 0.125f;
        float vi = 0.f, vl = 0.f;
        for (int e2 = 0; e2 < 8; e2++) {
            vi += (I[e2] - mi) * (I[e2] - mi);
            vl += (L[e2] - ml) * (L[e2] - ml);
        }
        vi /= 7.f; vl /= 7.f;
        float loss = vi / (mi * mi + 1e-10f) + vl / (ml * ml + 1e-10f)
                   + s_lse[0] * (1.f / (float)B_TOK);
        *out_loss = loss;
    }
}

// ---------------- launch ----------------
extern "C" void kernel_launch(void* const* d_in, const int* in_sizes, int n_in,
                              void* d_out, int out_size) {
    const float* z      = (const float*)d_in[0];
    const float* a      = (const float*)d_in[1];
    const float* w_gate = (const float*)d_in[2];
    const float* w_in   = (const float*)d_in[3];
    const float* b_in   = (const float*)d_in[4];
    const float* w_out  = (const float*)d_in[5];
    const float* b_out  = (const float*)d_in[6];
    const float* ln1_g  = (const float*)d_in[7];
    const float* ln1_b  = (const float*)d_in[8];
    const float* w1     = (const float*)d_in[9];
    const float* b1     = (const float*)d_in[10];
    const float* w2     = (const float*)d_in[11];
    const float* b2     = (const float*)d_in[12];
    const float* ln2_g  = (const float*)d_in[13];
    const float* ln2_b  = (const float*)d_in[14];
    const float* hw1    = (const float*)d_in[15];
    const float* hb1    = (const float*)d_in[16];
    const float* hw2    = (const float*)d_in[17];
    const float* hb2    = (const float*)d_in[18];

    float* out       = (float*)d_out;
    float* gates_out = out + B_TOK * NR;
    float* loss_out  = out + B_TOK * NR + B_TOK * NEXP;

    cudaFuncSetAttribute(k_gemm<0, 0>, cudaFuncAttributeMaxDynamicSharedMemorySize, GEMM_SMEM_BYTES);
    cudaFuncSetAttribute(k_gemm<1, 1>, cudaFuncAttributeMaxDynamicSharedMemorySize, GEMM_SMEM_BYTES);
    cudaFuncSetAttribute(k_head1, cudaFuncAttributeMaxDynamicSharedMemorySize, GEMM_SMEM_BYTES);
    cudaFuncSetAttribute(k_ffn, cudaFuncAttributeMaxDynamicSharedMemorySize, FFN_SMEM_BYTES);

    k_round<<<(RW4 + 255) / 256, 256>>>(w_in, w_out, w1, w2, hw1);
    k_router<<<B_TOK, 256>>>(z, a, w_gate, gates_out);
    k_sort<<<1, 256>>>();

    k_gemm<0, 0><<<dim3(GROUP_MAX, 3), 256, GEMM_SMEM_BYTES>>>(b_in, 384, nullptr, nullptr);
    k_attn<<<PAIR_MAX, 128>>>();
    k_gemm<1, 1><<<dim3(GROUP_MAX, 1), 256, GEMM_SMEM_BYTES>>>(b_out, 128, ln1_g, ln1_b);
    k_ffn<<<dim3(GROUP_MAX, 2), 256, FFN_SMEM_BYTES>>>(b1, b2);
    k_finish<<<B_TOK, 128>>>(ln2_g, ln2_b);
    k_head1<<<dim3(8, 4, 4), 256, GEMM_SMEM_BYTES>>>();
    k_head2<<<B_TOK, 128>>>(hb1, hw2, hb2, out);
    k_loss<<<1, 256>>>(gates_out, loss_out);
}

// round 15
// speedup vs baseline: 1.8786x; 1.1186x over previous
#include <cuda_runtime.h>
#include <cuda_bf16.h>
#include <cuda_fp16.h>
#include <cstdint>

// ---------------- problem constants ----------------
#define B_TOK   1024
#define NA      32
#define DZ      96
#define DA      32
#define DMODEL  128
#define ND      4096      // NA*DMODEL
#define NEXP    8
#define FF      1024
#define HH      512
#define NR      4
#define KTOP    2

#define PAIR_MAX  2072
#define GROUP_MAX 518

// ---------------- scratch ----------------
__device__ float  g_x [B_TOK * ND];              // concat(z,a), UNROUNDED
__device__ __half g_xh[B_TOK * ND];              // half copy (qkv GEMM A)
__device__ __half g_yh[B_TOK * ND];              // MoE out, half (head1 A)
__device__ float  g_qkv[(size_t)PAIR_MAX * 32 * 384];
__device__ __half g_aoh[(size_t)PAIR_MAX * 32 * 128];
__device__ float  g_h  [(size_t)PAIR_MAX * 32 * 128];
__device__ __half g_hh [(size_t)PAIR_MAX * 32 * 128];
__device__ float  g_f2 [(size_t)PAIR_MAX * 32 * 128];
__device__ float  g_hp [4 * B_TOK * HH];
__device__ float  g_lse[B_TOK];
__device__ int    g_topidx[B_TOK * KTOP];
__device__ float  g_topgate[B_TOK * KTOP];

// half weight copies (ONLY referenced from device code!)
__device__ __half g_winh [NEXP * 384 * 128];
__device__ __half g_wouth[NEXP * 128 * 128];
__device__ __half g_w1h  [NEXP * 1024 * 128];
__device__ __half g_w2h  [NEXP * 128 * 1024];
__device__ __half g_hw1h [HH * ND];

__device__ int   g_ngroups;
__device__ int   g_npad;
__device__ int   g_grp_expert[GROUP_MAX];
__device__ int   g_sp_pair[PAIR_MAX];
__device__ int   g_tok_sp[B_TOK * KTOP];

// ---------------- helpers ----------------
__device__ __forceinline__ void mma_f16(float* c, const uint32_t* a, const uint32_t* b) {
    asm volatile(
        "mma.sync.aligned.m16n8k16.row.col.f32.f16.f16.f32 "
        "{%0,%1,%2,%3},{%4,%5,%6,%7},{%8,%9},{%0,%1,%2,%3};"
        : "+f"(c[0]), "+f"(c[1]), "+f"(c[2]), "+f"(c[3])
        : "r"(a[0]), "r"(a[1]), "r"(a[2]), "r"(a[3]), "r"(b[0]), "r"(b[1]));
}

__device__ __forceinline__ void cp_async16(uint32_t saddr, const void* gaddr) {
    asm volatile("cp.async.cg.shared.global [%0], [%1], 16;\n" :: "r"(saddr), "l"(gaddr));
}
#define CP_COMMIT() asm volatile("cp.async.commit_group;\n")
#define CP_WAIT1()  asm volatile("cp.async.wait_group 1;\n")
#define CP_WAIT0()  asm volatile("cp.async.wait_group 0;\n")

// ---------------- weight rounding prep ----------------
#define RW0 (NEXP * 384 * 128)
#define RW1 (RW0 + NEXP * 128 * 128)
#define RW2 (RW1 + NEXP * 1024 * 128)
#define RW3 (RW2 + NEXP * 128 * 1024)
#define RW4 (RW3 + HH * ND)
__global__ void k_round(const float* __restrict__ w_in, const float* __restrict__ w_out,
                        const float* __restrict__ w1, const float* __restrict__ w2,
                        const float* __restrict__ hw1) {
    int i = blockIdx.x * 256 + threadIdx.x;
    if (i < RW0)      g_winh[i]        = __float2half_rn(w_in[i]);
    else if (i < RW1) g_wouth[i - RW0] = __float2half_rn(w_out[i - RW0]);
    else if (i < RW2) g_w1h[i - RW1]   = __float2half_rn(w1[i - RW1]);
    else if (i < RW3) g_w2h[i - RW2]   = __float2half_rn(w2[i - RW2]);
    else if (i < RW4) g_hw1h[i - RW3]  = __float2half_rn(hw1[i - RW3]);
}

// ---------------- router + fused concat ----------------
__global__ __launch_bounds__(256) void k_router(const float* __restrict__ z,
                                                const float* __restrict__ a,
                                                const float* __restrict__ w_gate,
                                                float* __restrict__ gates_out) {
    __shared__ float red[256 * 8];
    int b = blockIdx.x, tid = threadIdx.x;
    float p[8];
#pragma unroll
    for (int e = 0; e < 8; e++) p[e] = 0.f;
    for (int k = tid; k < ND; k += 256) {
        int dd = k & 127;
        int row = b * 32 + (k >> 7);
        float xv = (dd < DZ) ? z[row * DZ + dd] : a[row * DA + (dd - DZ)];
        g_x [(size_t)b * ND + k] = xv;
        g_xh[(size_t)b * ND + k] = __float2half_rn(xv);
        const float4* wg = reinterpret_cast<const float4*>(w_gate + (size_t)k * 8);
        float4 w0 = wg[0], w1 = wg[1];
        p[0] = fmaf(xv, w0.x, p[0]); p[1] = fmaf(xv, w0.y, p[1]);
        p[2] = fmaf(xv, w0.z, p[2]); p[3] = fmaf(xv, w0.w, p[3]);
        p[4] = fmaf(xv, w1.x, p[4]); p[5] = fmaf(xv, w1.y, p[5]);
        p[6] = fmaf(xv, w1.z, p[6]); p[7] = fmaf(xv, w1.w, p[7]);
    }
#pragma unroll
    for (int e = 0; e < 8; e++) red[tid * 8 + e] = p[e];
    __syncthreads();
    for (int s = 128; s > 0; s >>= 1) {
        if (tid < s) {
#pragma unroll
            for (int e = 0; e < 8; e++) red[tid * 8 + e] += red[(tid + s) * 8 + e];
        }
        __syncthreads();
    }
    if (tid == 0) {
        float l[8];
#pragma unroll
        for (int e = 0; e < 8; e++) l[e] = red[e];
        int i0 = 0; float v0 = l[0];
#pragma unroll
        for (int e = 1; e < 8; e++) if (l[e] > v0) { v0 = l[e]; i0 = e; }
        int i1 = -1; float v1 = -3.4e38f;
#pragma unroll
        for (int e = 0; e < 8; e++) if (e != i0 && l[e] > v1) { v1 = l[e]; i1 = e; }
        float e1 = expf(v1 - v0);
        float inv = 1.f / (1.f + e1);
        float g0 = inv, g1v = e1 * inv;
#pragma unroll
        for (int e = 0; e < 8; e++)
            gates_out[b * 8 + e] = (e == i0) ? g0 : ((e == i1) ? g1v : 0.f);
        g_topidx[b * 2] = i0;  g_topidx[b * 2 + 1] = i1;
        g_topgate[b * 2] = g0; g_topgate[b * 2 + 1] = g1v;
        float s = 0.f;
#pragma unroll
        for (int e = 0; e < 8; e++) s += expf(l[e] - v0);
        g_lse[b] = v0 + logf(s);
    }
}

// ---------------- parallel deterministic counting sort ----------------
__global__ __launch_bounds__(256) void k_sort() {
    __shared__ int s_cnt[256][8];
    __shared__ int s_ecnt[8];
    __shared__ int s_base[8];
    int t = threadIdx.x;
    int my[8];
    int lc[8] = {0, 0, 0, 0, 0, 0, 0, 0};
#pragma unroll
    for (int i = 0; i < 8; i++) {
        int e = g_topidx[t * 8 + i];
        my[i] = e;
        lc[e]++;
    }
#pragma unroll
    for (int e = 0; e < 8; e++) s_cnt[t][e] = lc[e];
    __syncthreads();
    if (t < 8) {
        int off = 0;
        for (int i = 0; i < 256; i++) {
            int v = s_cnt[i][t];
            s_cnt[i][t] = off;
            off += v;
        }
        s_ecnt[t] = off;
    }
    __syncthreads();
    if (t == 0) {
        int o = 0, g = 0;
        for (int e = 0; e < 8; e++) {
            s_base[e] = o;
            int pc = (s_ecnt[e] + 3) & ~3;
            for (int i = 0; i < (pc >> 2); i++) g_grp_expert[g++] = e;
            o += pc;
        }
        g_ngroups = g;
        g_npad = o;
    }
    __syncthreads();
#pragma unroll
    for (int i = 0; i < 8; i++) {
        int p = t * 8 + i;
        int e = my[i];
        int sp = s_base[e] + s_cnt[t][e]++;
        g_sp_pair[sp] = p;
        g_tok_sp[p] = sp;
    }
    if (t < 8) {
        int start = s_base[t] + s_ecnt[t];
        int end = s_base[t] + ((s_ecnt[t] + 3) & ~3);
        for (int sp = start; sp < end; sp++) g_sp_pair[sp] = -1;
    }
}

// ---------------- fp16 batched GEMM (cp.async double-buffered, K stages of 64) ----------------
// halves: sA[2][128*72] at 0 | sB[2][128*72] at 18432  => 73728 bytes
#define GEMM_SMEM_BYTES 73728
__device__ __forceinline__ void gemm_issue_h(uint32_t smu, int buf, int kc,
                                             const __half* const* s_ab,
                                             const __half* wb, int tid) {
#pragma unroll
    for (int it = 0; it < 4; it++) {
        int i = tid + it * 256;
        int r = i >> 3, q = (i & 7) * 8;
        cp_async16(smu + (uint32_t)(buf * 9216 + r * 72 + q) * 2,
                   s_ab[r >> 5] + (size_t)(r & 31) * 128 + kc + q);
        cp_async16(smu + (uint32_t)(18432 + buf * 9216 + r * 72 + q) * 2,
                   wb + (size_t)r * 128 + kc + q);
    }
    CP_COMMIT();
}

// DST==0: qkv -> g_qkv.  DST==1: o-proj + FUSED residual+LN1 -> g_h + g_hh.
template<int SRC, int DST>
__global__ __launch_bounds__(256) void k_gemm(const float* __restrict__ bias, int Ntot,
                                              const float* __restrict__ ln1_g,
                                              const float* __restrict__ ln1_b) {
    int g = blockIdx.x;
    if (g >= g_ngroups) return;
    int e = g_grp_expert[g];
    int n0 = blockIdx.y * 128;
    int tid = threadIdx.x, lane = tid & 31, w = tid >> 5;

    extern __shared__ __half smh_g[];
    uint32_t smu = (uint32_t)__cvta_generic_to_shared(smh_g);
    __shared__ const __half* s_ab[4];
    if (tid < 4) {
        const __half* ab;
        if (SRC == 0) {
            int pr = g_sp_pair[g * 4 + tid];
            int tok = (pr >= 0) ? (pr >> 1) : 0;
            ab = g_xh + (size_t)tok * ND;
        } else {
            ab = g_aoh + (size_t)(g * 4 + tid) * 32 * 128;
        }
        s_ab[tid] = ab;
    }
    __syncthreads();

    const __half* W = (SRC == 0) ? g_winh : g_wouth;
    const __half* wb = W + (size_t)e * Ntot * 128 + (size_t)n0 * 128;

    float acc[2][8][4];
#pragma unroll
    for (int i = 0; i < 2; i++)
#pragma unroll
        for (int j = 0; j < 8; j++)
#pragma unroll
            for (int k = 0; k < 4; k++) acc[i][j][k] = 0.f;

    int mt_base = (w & 3) * 2;
    int nt_base = (w >> 2) * 8;
    int rq = lane >> 2;
    int k2 = (lane & 3) * 2;

    gemm_issue_h(smu, 0, 0, s_ab, wb, tid);
    for (int c = 0; c < 2; c++) {
        if (c + 1 < 2) { gemm_issue_h(smu, 1, 64, s_ab, wb, tid); CP_WAIT1(); }
        else CP_WAIT0();
        __syncthreads();
        const __half* sA = smh_g + c * 9216;
        const __half* sB = smh_g + 18432 + c * 9216;
#pragma unroll
        for (int kh = 0; kh < 4; kh++) {
            int kpos = kh * 16 + k2;
            uint32_t a[2][4];
#pragma unroll
            for (int mt = 0; mt < 2; mt++) {
                int r0 = (mt_base + mt) * 16 + rq;
                a[mt][0] = *reinterpret_cast<const uint32_t*>(sA + r0 * 72 + kpos);
                a[mt][1] = *reinterpret_cast<const uint32_t*>(sA + (r0 + 8) * 72 + kpos);
                a[mt][2] = *reinterpret_cast<const uint32_t*>(sA + r0 * 72 + kpos + 8);
                a[mt][3] = *reinterpret_cast<const uint32_t*>(sA + (r0 + 8) * 72 + kpos + 8);
            }
#pragma unroll
            for (int nt = 0; nt < 8; nt++) {
                int nr = (nt_base + nt) * 8 + rq;
                uint32_t b[2];
                b[0] = *reinterpret_cast<const uint32_t*>(sB + nr * 72 + kpos);
                b[1] = *reinterpret_cast<const uint32_t*>(sB + nr * 72 + kpos + 8);
                mma_f16(acc[0][nt], a[0], b);
                mma_f16(acc[1][nt], a[1], b);
            }
        }
        __syncthreads();
    }

    if (DST == 0) {
#pragma unroll
        for (int mt = 0; mt < 2; mt++) {
            int r0 = (mt_base + mt) * 16 + rq;
            int r1 = r0 + 8;
#pragma unroll
            for (int nt = 0; nt < 8; nt++) {
                int nc = n0 + (nt_base + nt) * 8 + 2 * (lane & 3);
                float2 bv = *reinterpret_cast<const float2*>(bias + (size_t)e * Ntot + nc);
                float2 o0, o1;
                o0.x = acc[mt][nt][0] + bv.x; o0.y = acc[mt][nt][1] + bv.y;
                o1.x = acc[mt][nt][2] + bv.x; o1.y = acc[mt][nt][3] + bv.y;
                *reinterpret_cast<float2*>(g_qkv + ((size_t)g * 128 + r0) * Ntot + nc) = o0;
                *reinterpret_cast<float2*>(g_qkv + ((size_t)g * 128 + r1) * Ntot + nc) = o1;
            }
        }
    } else {
        float* sO = reinterpret_cast<float*>(smh_g);   // 128*132 floats = 67584 B < 73728
#pragma unroll
        for (int mt = 0; mt < 2; mt++) {
            int r0 = (mt_base + mt) * 16 + rq;
            int r1 = r0 + 8;
#pragma unroll
            for (int nt = 0; nt < 8; nt++) {
                int nc = (nt_base + nt) * 8 + 2 * (lane & 3);
                float2 bv = *reinterpret_cast<const float2*>(bias + (size_t)e * 128 + nc);
                sO[r0 * 132 + nc]     = acc[mt][nt][0] + bv.x;
                sO[r0 * 132 + nc + 1] = acc[mt][nt][1] + bv.y;
                sO[r1 * 132 + nc]     = acc[mt][nt][2] + bv.x;
                sO[r1 * 132 + nc + 1] = acc[mt][nt][3] + bv.y;
            }
        }
        __syncthreads();
        const float* g1 = ln1_g + e * 128;
        const float* b1 = ln1_b + e * 128;
        for (int rr = 0; rr < 16; rr++) {
            int r = w * 16 + rr;
            int sp = g * 4 + (r >> 5);
            int pr = g_sp_pair[sp];
            if (pr < 0) continue;
            int token = pr >> 1;
            float v[4]; float sum = 0.f, sq = 0.f;
#pragma unroll
            for (int j = 0; j < 4; j++) {
                int c = lane + 32 * j;
                v[j] = g_x[(size_t)token * ND + (r & 31) * 128 + c] + sO[r * 132 + c];
                sum += v[j]; sq += v[j] * v[j];
            }
#pragma unroll
            for (int off = 16; off > 0; off >>= 1) {
                sum += __shfl_xor_sync(0xffffffffu, sum, off);
                sq  += __shfl_xor_sync(0xffffffffu, sq, off);
            }
            float mu = sum * (1.f / 128.f);
            float var = sq * (1.f / 128.f) - mu * mu;
            float rs = rsqrtf(var + 1e-5f);
#pragma unroll
            for (int j = 0; j < 4; j++) {
                int c = lane + 32 * j;
                float lnv = (v[j] - mu) * rs * g1[c] + b1[c];
                g_h [((size_t)g * 128 + r) * 128 + c] = lnv;
                g_hh[((size_t)g * 128 + r) * 128 + c] = __float2half_rn(lnv);
            }
        }
    }
}

// ---------------- head1: split-K fp16 GEMM ----------------
__device__ __forceinline__ void head_issue_h(uint32_t smu, int buf, int kc,
                                             const __half* Ab, const __half* Bb, int tid) {
#pragma unroll
    for (int it = 0; it < 4; it++) {
        int i = tid + it * 256;
        int r = i >> 3, q = (i & 7) * 8;
        cp_async16(smu + (uint32_t)(buf * 9216 + r * 72 + q) * 2,
                   Ab + (size_t)r * ND + kc + q);
        cp_async16(smu + (uint32_t)(18432 + buf * 9216 + r * 72 + q) * 2,
                   Bb + (size_t)r * ND + kc + q);
    }
    CP_COMMIT();
}

__global__ __launch_bounds__(256) void k_head1() {
    int bm = blockIdx.x, bn = blockIdx.y, ks4 = blockIdx.z;
    int tid = threadIdx.x, lane = tid & 31, w = tid >> 5;

    extern __shared__ __half smh_h[];
    uint32_t smu = (uint32_t)__cvta_generic_to_shared(smh_h);

    const __half* Ab = g_yh + (size_t)(bm * 128) * ND + ks4 * 1024;
    const __half* Bb = g_hw1h + (size_t)(bn * 128) * ND + ks4 * 1024;

    float acc[2][8][4];
#pragma unroll
    for (int i = 0; i < 2; i++)
#pragma unroll
        for (int j = 0; j < 8; j++)
#pragma unroll
            for (int k = 0; k < 4; k++) acc[i][j][k] = 0.f;

    int mt_base = (w & 3) * 2;
    int nt_base = (w >> 2) * 8;
    int rq = lane >> 2;
    int k2 = (lane & 3) * 2;

    head_issue_h(smu, 0, 0, Ab, Bb, tid);
    for (int c = 0; c < 16; c++) {
        if (c + 1 < 16) { head_issue_h(smu, (c + 1) & 1, (c + 1) * 64, Ab, Bb, tid); CP_WAIT1(); }
        else CP_WAIT0();
        __syncthreads();
        const __half* sA = smh_h + (c & 1) * 9216;
        const __half* sB = smh_h + 18432 + (c & 1) * 9216;
#pragma unroll
        for (int kh = 0; kh < 4; kh++) {
            int kpos = kh * 16 + k2;
            uint32_t a[2][4];
#pragma unroll
            for (int mt = 0; mt < 2; mt++) {
                int r0 = (mt_base + mt) * 16 + rq;
                a[mt][0] = *reinterpret_cast<const uint32_t*>(sA + r0 * 72 + kpos);
                a[mt][1] = *reinterpret_cast<const uint32_t*>(sA + (r0 + 8) * 72 + kpos);
                a[mt][2] = *reinterpret_cast<const uint32_t*>(sA + r0 * 72 + kpos + 8);
                a[mt][3] = *reinterpret_cast<const uint32_t*>(sA + (r0 + 8) * 72 + kpos + 8);
            }
#pragma unroll
            for (int nt = 0; nt < 8; nt++) {
                int nr = (nt_base + nt) * 8 + rq;
                uint32_t b[2];
                b[0] = *reinterpret_cast<const uint32_t*>(sB + nr * 72 + kpos);
                b[1] = *reinterpret_cast<const uint32_t*>(sB + nr * 72 + kpos + 8);
                mma_f16(acc[0][nt], a[0], b);
                mma_f16(acc[1][nt], a[1], b);
            }
        }
        __syncthreads();
    }

    float* dst = g_hp + ((size_t)ks4 * B_TOK + bm * 128) * HH + bn * 128;
#pragma unroll
    for (int mt = 0; mt < 2; mt++) {
        int r0 = (mt_base + mt) * 16 + rq;
        int r1 = r0 + 8;
#pragma unroll
        for (int nt = 0; nt < 8; nt++) {
            int nc = (nt_base + nt) * 8 + 2 * (lane & 3);
            float2 o0, o1;
            o0.x = acc[mt][nt][0]; o0.y = acc[mt][nt][1];
            o1.x = acc[mt][nt][2]; o1.y = acc[mt][nt][3];
            *reinterpret_cast<float2*>(dst + (size_t)r0 * HH + nc) = o0;
            *reinterpret_cast<float2*>(dst + (size_t)r1 * HH + nc) = o1;
        }
    }
}

// ---------------- fused FFN: fp16 mma (m16n8k16), K=64 stages ----------------
// smem halves: sA[64*136]=8704 | sW ring 2*[128*72]=18432 | sF[64*136]=8704 => 71680 B
#define FFN_SMEM_BYTES 71680
__device__ __forceinline__ void ffn_issue_h(uint32_t smu, int s,
                                            const __half* w1b, const __half* w2b, int tid) {
    int c = s >> 2, ph = (s >> 1) & 1, kc = s & 1;
    const __half* base;
    int rstride;
    if (ph) { base = g_w2h; }  // placeholder to keep compiler quiet (overwritten below)
    if (ph) { base = w2b + c * 128 + kc * 64;                  rstride = 1024; }
    else    { base = w1b + (size_t)(c * 128) * 128 + kc * 64;  rstride = 128; }
#pragma unroll
    for (int it = 0; it < 4; it++) {
        int i = tid + it * 256;
        int r = i >> 3, q = (i & 7) * 8;
        cp_async16(smu + (uint32_t)(8704 + (s & 1) * 9216 + r * 72 + q) * 2,
                   base + (size_t)r * rstride + q);
    }
    CP_COMMIT();
}

__global__ __launch_bounds__(256) void k_ffn(const float* __restrict__ B1,
                                             const float* __restrict__ B2) {
    int g = blockIdx.x;
    if (g >= g_ngroups) return;
    int hf = blockIdx.y;
    int e = g_grp_expert[g];
    int tid = threadIdx.x, lane = tid & 31, w = tid >> 5;

    extern __shared__ __half smh[];
    __half* sA = smh;                    // 64 x 136
    __half* sW = smh + 8704;             // 2 x 128 x 72
    __half* sF = smh + 8704 + 18432;     // 64 x 136
    uint32_t smu = (uint32_t)__cvta_generic_to_shared(smh);

    const __half* hb  = g_hh + ((size_t)g * 128 + hf * 64) * 128;
    const __half* w1b = g_w1h + (size_t)e * 1024 * 128;
    const __half* w2b = g_w2h + (size_t)e * 128 * 1024;

#pragma unroll
    for (int it = 0; it < 4; it++) {
        int i = tid + it * 256;
        int r = i >> 4, q = (i & 15) * 8;
        *reinterpret_cast<float4*>(sA + r * 136 + q) =
            *reinterpret_cast<const float4*>(hb + (size_t)r * 128 + q);
    }

    int mt_base = (w & 1) * 2;
    int nt_base = (w >> 1) * 4;
    int rq = lane >> 2;
    int k2 = (lane & 3) * 2;

    float acc1[2][4][4], acc2[2][4][4];
#pragma unroll
    for (int mt = 0; mt < 2; mt++)
#pragma unroll
        for (int j = 0; j < 4; j++)
#pragma unroll
            for (int k = 0; k < 4; k++) acc2[mt][j][k] = 0.f;

    ffn_issue_h(smu, 0, w1b, w2b, tid);
    ffn_issue_h(smu, 1, w1b, w2b, tid);

    for (int s = 0; s < 32; s++) {
        if (s < 31) CP_WAIT1(); else CP_WAIT0();
        __syncthreads();
        if ((s & 3) == 0) {
#pragma unroll
            for (int mt = 0; mt < 2; mt++)
#pragma unroll
                for (int j = 0; j < 4; j++)
#pragma unroll
                    for (int k = 0; k < 4; k++) acc1[mt][j][k] = 0.f;
        }
        int ph = (s >> 1) & 1;
        int kc = s & 1;
        const __half* sWb = sW + (s & 1) * 9216;
        if (!ph) {
#pragma unroll
            for (int kh = 0; kh < 4; kh++) {
                int kpos = kc * 64 + kh * 16 + k2;
                int kb = kh * 16 + k2;
                uint32_t a[2][4];
#pragma unroll
                for (int mt = 0; mt < 2; mt++) {
                    int r0 = (mt_base + mt) * 16 + rq;
                    a[mt][0] = *reinterpret_cast<const uint32_t*>(sA + r0 * 136 + kpos);
                    a[mt][1] = *reinterpret_cast<const uint32_t*>(sA + (r0 + 8) * 136 + kpos);
                    a[mt][2] = *reinterpret_cast<const uint32_t*>(sA + r0 * 136 + kpos + 8);
                    a[mt][3] = *reinterpret_cast<const uint32_t*>(sA + (r0 + 8) * 136 + kpos + 8);
                }
#pragma unroll
                for (int nt = 0; nt < 4; nt++) {
                    int nr = (nt_base + nt) * 8 + rq;
                    uint32_t b[2];
                    b[0] = *reinterpret_cast<const uint32_t*>(sWb + nr * 72 + kb);
                    b[1] = *reinterpret_cast<const uint32_t*>(sWb + nr * 72 + kb + 8);
                    mma_f16(acc1[0][nt], a[0], b);
                    mma_f16(acc1[1][nt], a[1], b);
                }
            }
        } else {
#pragma unroll
            for (int kh = 0; kh < 4; kh++) {
                int kpos = kc * 64 + kh * 16 + k2;
                int kb = kh * 16 + k2;
                uint32_t a[2][4];
#pragma unroll
                for (int mt = 0; mt < 2; mt++) {
                    int r0 = (mt_base + mt) * 16 + rq;
                    a[mt][0] = *reinterpret_cast<const uint32_t*>(sF + r0 * 136 + kpos);
                    a[mt][1] = *reinterpret_cast<const uint32_t*>(sF + (r0 + 8) * 136 + kpos);
                    a[mt][2] = *reinterpret_cast<const uint32_t*>(sF + r0 * 136 + kpos + 8);
                    a[mt][3] = *reinterpret_cast<const uint32_t*>(sF + (r0 + 8) * 136 + kpos + 8);
                }
#pragma unroll
                for (int nt = 0; nt < 4; nt++) {
                    int nr = (nt_base + nt) * 8 + rq;
                    uint32_t b[2];
                    b[0] = *reinterpret_cast<const uint32_t*>(sWb + nr * 72 + kb);
                    b[1] = *reinterpret_cast<const uint32_t*>(sWb + nr * 72 + kb + 8);
                    mma_f16(acc2[0][nt], a[0], b);
                    mma_f16(acc2[1][nt], a[1], b);
                }
            }
        }
        __syncthreads();
        if ((s & 3) == 1) {
            int c = s >> 2;
#pragma unroll
            for (int mt = 0; mt < 2; mt++) {
                int r0 = (mt_base + mt) * 16 + rq;
#pragma unroll
                for (int nt = 0; nt < 4; nt++) {
                    int nc = (nt_base + nt) * 8 + 2 * (lane & 3);
                    float2 bv = *reinterpret_cast<const float2*>(B1 + (size_t)e * 1024 + c * 128 + nc);
                    __half2 h0 = __floats2half2_rn(fmaxf(acc1[mt][nt][0] + bv.x, 0.f),
                                                   fmaxf(acc1[mt][nt][1] + bv.y, 0.f));
                    __half2 h1 = __floats2half2_rn(fmaxf(acc1[mt][nt][2] + bv.x, 0.f),
                                                   fmaxf(acc1[mt][nt][3] + bv.y, 0.f));
                    *reinterpret_cast<__half2*>(sF + r0 * 136 + nc) = h0;
                    *reinterpret_cast<__half2*>(sF + (r0 + 8) * 136 + nc) = h1;
                }
            }
            __syncthreads();
        }
        if (s + 2 < 32) ffn_issue_h(smu, s + 2, w1b, w2b, tid);
    }

    {
        float* f2b = g_f2 + ((size_t)g * 128 + hf * 64) * 128;
#pragma unroll
        for (int mt = 0; mt < 2; mt++) {
            int r0 = (mt_base + mt) * 16 + rq;
#pragma unroll
            for (int nt = 0; nt < 4; nt++) {
                int nc = (nt_base + nt) * 8 + 2 * (lane & 3);
                float2 bv = *reinterpret_cast<const float2*>(B2 + (size_t)e * 128 + nc);
                float2 o0, o1;
                o0.x = acc2[mt][nt][0] + bv.x; o0.y = acc2[mt][nt][1] + bv.y;
                o1.x = acc2[mt][nt][2] + bv.x; o1.y = acc2[mt][nt][3] + bv.y;
                *reinterpret_cast<float2*>(f2b + (size_t)r0 * 128 + nc) = o0;
                *reinterpret_cast<float2*>(f2b + (size_t)(r0 + 8) * 128 + nc) = o1;
            }
        }
    }
}

// ---------------- attention ----------------
__global__ __launch_bounds__(128) void k_attn() {
    int sp = blockIdx.x;
    if (sp >= g_npad) return;
    if (g_sp_pair[sp] < 0) return;
    __shared__ float s_kv[32 * 261];
    int tid = threadIdx.x, lane = tid & 31, h = tid >> 5;
    for (int i = tid; i < 32 * 256; i += 128) {
        int r = i >> 8, c = i & 255;
        s_kv[r * 261 + c] = g_qkv[((size_t)sp * 32 + r) * 384 + 128 + c];
    }
    __syncthreads();
    float kreg[32];
#pragma unroll
    for (int d = 0; d < 32; d++) kreg[d] = s_kv[lane * 261 + h * 32 + d];
    const float* qb = g_qkv + (size_t)sp * 32 * 384;
    for (int q = 0; q < 32; q++) {
        const float4* qp = reinterpret_cast<const float4*>(qb + q * 384 + h * 32);
        float sc = 0.f;
#pragma unroll
        for (int d4 = 0; d4 < 8; d4++) {
            float4 q4 = qp[d4];
            sc += q4.x * kreg[d4 * 4] + q4.y * kreg[d4 * 4 + 1]
                + q4.z * kreg[d4 * 4 + 2] + q4.w * kreg[d4 * 4 + 3];
        }
        sc *= 0.1767766952966369f;
        float m = sc;
#pragma unroll
        for (int off = 16; off > 0; off >>= 1)
            m = fmaxf(m, __shfl_xor_sync(0xffffffffu, m, off));
        float pr = expf(sc - m);
        float ss = pr;
#pragma unroll
        for (int off = 16; off > 0; off >>= 1)
            ss += __shfl_xor_sync(0xffffffffu, ss, off);
        float att = pr / ss;
        float o = 0.f;
#pragma unroll
        for (int kk = 0; kk < 32; kk++) {
            float av = __shfl_sync(0xffffffffu, att, kk);
            o = fmaf(av, s_kv[kk * 261 + 128 + h * 32 + lane], o);
        }
        g_aoh[((size_t)sp * 32 + q) * 128 + h * 32 + lane] = __float2half_rn(o);
    }
}

// ---------------- finish ----------------
__global__ __launch_bounds__(128) void k_finish(const float* __restrict__ ln2_g,
                                                const float* __restrict__ ln2_b) {
    int t = blockIdx.x;
    int tid = threadIdx.x, lane = tid & 31, w = tid >> 5;
    float y[8][4];
#pragma unroll
    for (int rr = 0; rr < 8; rr++)
#pragma unroll
        for (int j = 0; j < 4; j++) y[rr][j] = 0.f;

    for (int slot = 0; slot < 2; slot++) {
        int pr = t * 2 + slot;
        int sp = g_tok_sp[pr];
        int e = g_topidx[pr];
        float gate = g_topgate[pr];
        const float* g2 = ln2_g + e * 128;
        const float* b2 = ln2_b + e * 128;
        for (int rr = 0; rr < 8; rr++) {
            int r = w * 8 + rr;
            float v[4]; float sum = 0.f, sq = 0.f;
#pragma unroll
            for (int j = 0; j < 4; j++) {
                int c = lane + 32 * j;
                v[j] = g_h[((size_t)sp * 32 + r) * 128 + c]
                     + g_f2[((size_t)sp * 32 + r) * 128 + c];
                sum += v[j]; sq += v[j] * v[j];
            }
#pragma unroll
            for (int off = 16; off > 0; off >>= 1) {
                sum += __shfl_xor_sync(0xffffffffu, sum, off);
                sq  += __shfl_xor_sync(0xffffffffu, sq, off);
            }
            float mu = sum * (1.f / 128.f);
            float var = sq * (1.f / 128.f) - mu * mu;
            float rs = rsqrtf(var + 1e-5f);
#pragma unroll
            for (int j = 0; j < 4; j++) {
                int c = lane + 32 * j;
                y[rr][j] += gate * ((v[j] - mu) * rs * g2[c] + b2[c]);
            }
        }
    }
    for (int rr = 0; rr < 8; rr++) {
        int r = w * 8 + rr;
#pragma unroll
        for (int j = 0; j < 4; j++) {
            int c = lane + 32 * j;
            g_yh[(size_t)t * ND + r * 128 + c] = __float2half_rn(y[rr][j]);
        }
    }
}

// ---------------- head2: fused split-K reduce + relu + GEMV ----------------
__global__ void k_head2(const float* __restrict__ hb1,
                        const float* __restrict__ hw2, const float* __restrict__ hb2,
                        float* __restrict__ out_r) {
    int b = blockIdx.x;
    int j = threadIdx.x >> 5;
    int lane = threadIdx.x & 31;
    const float* w = hw2 + (size_t)j * HH;
    float s = 0.f;
    for (int k = lane; k < HH; k += 32) {
        size_t i = (size_t)b * HH + k;
        float hsum = g_hp[i] + g_hp[(size_t)B_TOK * HH + i]
                   + g_hp[2 * (size_t)B_TOK * HH + i]
                   + g_hp[3 * (size_t)B_TOK * HH + i] + hb1[k];
        s = fmaf(fmaxf(hsum, 0.f), w[k], s);
    }
#pragma unroll
    for (int off = 16; off > 0; off >>= 1) s += __shfl_xor_sync(0xffffffffu, s, off);
    if (lane == 0) out_r[b * NR + j] = s + hb2[j];
}

// ---------------- loss ----------------
__global__ void k_loss(const float* __restrict__ gates, float* __restrict__ out_loss) {
    __shared__ float s_imp[8][32], s_ld[8][32], s_lse[256];
    int t = threadIdx.x;
    int e = t & 7, c = t >> 3;
    float imp = 0.f, ld = 0.f;
    for (int b = c; b < B_TOK; b += 32) {
        float g = gates[b * 8 + e];
        imp += g;
        if (g > 0.f) ld += 1.f;
    }
    s_imp[e][c] = imp; s_ld[e][c] = ld;
    float ls = 0.f;
    for (int b = t; b < B_TOK; b += 256) ls += g_lse[b];
    s_lse[t] = ls;
    __syncthreads();
    for (int s = 128; s > 0; s >>= 1) {
        if (t < s) s_lse[t] += s_lse[t + s];
        __syncthreads();
    }
    if (t == 0) {
        float I[8], L[8];
        float mi = 0.f, ml = 0.f;
        for (int e2 = 0; e2 < 8; e2++) {
            float si = 0.f, sl = 0.f;
            for (int c2 = 0; c2 < 32; c2++) { si += s_imp[e2][c2]; sl += s_ld[e2][c2]; }
            I[e2] = si; L[e2] = sl; mi += si; ml += sl;
        }
        mi *= 0.125f; ml *= 0.125f;
        float vi = 0.f, vl = 0.f;
        for (int e2 = 0; e2 < 8; e2++) {
            vi += (I[e2] - mi) * (I[e2] - mi);
            vl += (L[e2] - ml) * (L[e2] - ml);
        }
        vi /= 7.f; vl /= 7.f;
        float loss = vi / (mi * mi + 1e-10f) + vl / (ml * ml + 1e-10f)
                   + s_lse[0] * (1.f / (float)B_TOK);
        *out_loss = loss;
    }
}

// ---------------- launch ----------------
extern "C" void kernel_launch(void* const* d_in, const int* in_sizes, int n_in,
                              void* d_out, int out_size) {
    const float* z      = (const float*)d_in[0];
    const float* a      = (const float*)d_in[1];
    const float* w_gate = (const float*)d_in[2];
    const float* w_in   = (const float*)d_in[3];
    const float* b_in   = (const float*)d_in[4];
    const float* w_out  = (const float*)d_in[5];
    const float* b_out  = (const float*)d_in[6];
    const float* ln1_g  = (const float*)d_in[7];
    const float* ln1_b  = (const float*)d_in[8];
    const float* w1     = (const float*)d_in[9];
    const float* b1     = (const float*)d_in[10];
    const float* w2     = (const float*)d_in[11];
    const float* b2     = (const float*)d_in[12];
    const float* ln2_g  = (const float*)d_in[13];
    const float* ln2_b  = (const float*)d_in[14];
    const float* hw1    = (const float*)d_in[15];
    const float* hb1    = (const float*)d_in[16];
    const float* hw2    = (const float*)d_in[17];
    const float* hb2    = (const float*)d_in[18];

    float* out       = (float*)d_out;
    float* gates_out = out + B_TOK * NR;
    float* loss_out  = out + B_TOK * NR + B_TOK * NEXP;

    cudaFuncSetAttribute(k_gemm<0, 0>, cudaFuncAttributeMaxDynamicSharedMemorySize, GEMM_SMEM_BYTES);
    cudaFuncSetAttribute(k_gemm<1, 1>, cudaFuncAttributeMaxDynamicSharedMemorySize, GEMM_SMEM_BYTES);
    cudaFuncSetAttribute(k_head1, cudaFuncAttributeMaxDynamicSharedMemorySize, GEMM_SMEM_BYTES);
    cudaFuncSetAttribute(k_ffn, cudaFuncAttributeMaxDynamicSharedMemorySize, FFN_SMEM_BYTES);

    k_round<<<(RW4 + 255) / 256, 256>>>(w_in, w_out, w1, w2, hw1);
    k_router<<<B_TOK, 256>>>(z, a, w_gate, gates_out);
    k_sort<<<1, 256>>>();

    k_gemm<0, 0><<<dim3(GROUP_MAX, 3), 256, GEMM_SMEM_BYTES>>>(b_in, 384, nullptr, nullptr);
    k_attn<<<PAIR_MAX, 128>>>();
    k_gemm<1, 1><<<dim3(GROUP_MAX, 1), 256, GEMM_SMEM_BYTES>>>(b_out, 128, ln1_g, ln1_b);
    k_ffn<<<dim3(GROUP_MAX, 2), 256, FFN_SMEM_BYTES>>>(b1, b2);
    k_finish<<<B_TOK, 128>>>(ln2_g, ln2_b);
    k_head1<<<dim3(8, 4, 4), 256, GEMM_SMEM_BYTES>>>();
    k_head2<<<B_TOK, 128>>>(hb1, hw2, hb2, out);
    k_loss<<<1, 256>>>(gates_out, loss_out);
}

// round 16
// speedup vs baseline: 1.9910x; 1.0598x over previous
#include <cuda_runtime.h>
#include <cuda_bf16.h>
#include <cuda_fp16.h>
#include <cstdint>

// ---------------- problem constants ----------------
#define B_TOK   1024
#define NA      32
#define DZ      96
#define DA      32
#define DMODEL  128
#define ND      4096      // NA*DMODEL
#define NEXP    8
#define FF      1024
#define HH      512
#define NR      4
#define KTOP    2

#define PAIR_MAX  2072
#define GROUP_MAX 518

// ---------------- scratch ----------------
__device__ float  g_x [B_TOK * ND];              // concat(z,a), UNROUNDED
__device__ __half g_xh[B_TOK * ND];              // half copy (qkv GEMM A)
__device__ __half g_yh[B_TOK * ND];              // MoE out, half (head1 A)
__device__ __half g_qkvh[(size_t)PAIR_MAX * 32 * 384];
__device__ __half g_aoh[(size_t)PAIR_MAX * 32 * 128];
__device__ float  g_h  [(size_t)PAIR_MAX * 32 * 128];
__device__ __half g_hh [(size_t)PAIR_MAX * 32 * 128];
__device__ float  g_f2 [(size_t)PAIR_MAX * 32 * 128];
__device__ float  g_hp [4 * B_TOK * HH];
__device__ float  g_lse[B_TOK];
__device__ int    g_topidx[B_TOK * KTOP];
__device__ float  g_topgate[B_TOK * KTOP];

// half weight copies (ONLY referenced from device code!)
__device__ __half g_winh [NEXP * 384 * 128];
__device__ __half g_wouth[NEXP * 128 * 128];
__device__ __half g_w1h  [NEXP * 1024 * 128];
__device__ __half g_w2h  [NEXP * 128 * 1024];
__device__ __half g_hw1h [HH * ND];

__device__ int   g_ngroups;
__device__ int   g_npad;
__device__ int   g_grp_expert[GROUP_MAX];
__device__ int   g_sp_pair[PAIR_MAX];
__device__ int   g_tok_sp[B_TOK * KTOP];

// ---------------- helpers ----------------
__device__ __forceinline__ void mma_f16(float* c, const uint32_t* a, const uint32_t* b) {
    asm volatile(
        "mma.sync.aligned.m16n8k16.row.col.f32.f16.f16.f32 "
        "{%0,%1,%2,%3},{%4,%5,%6,%7},{%8,%9},{%0,%1,%2,%3};"
        : "+f"(c[0]), "+f"(c[1]), "+f"(c[2]), "+f"(c[3])
        : "r"(a[0]), "r"(a[1]), "r"(a[2]), "r"(a[3]), "r"(b[0]), "r"(b[1]));
}

__device__ __forceinline__ void cp_async16(uint32_t saddr, const void* gaddr) {
    asm volatile("cp.async.cg.shared.global [%0], [%1], 16;\n" :: "r"(saddr), "l"(gaddr));
}
#define CP_COMMIT() asm volatile("cp.async.commit_group;\n")
#define CP_WAIT1()  asm volatile("cp.async.wait_group 1;\n")
#define CP_WAIT0()  asm volatile("cp.async.wait_group 0;\n")

// ---------------- weight rounding prep ----------------
#define RW0 (NEXP * 384 * 128)
#define RW1 (RW0 + NEXP * 128 * 128)
#define RW2 (RW1 + NEXP * 1024 * 128)
#define RW3 (RW2 + NEXP * 128 * 1024)
#define RW4 (RW3 + HH * ND)
__global__ void k_round(const float* __restrict__ w_in, const float* __restrict__ w_out,
                        const float* __restrict__ w1, const float* __restrict__ w2,
                        const float* __restrict__ hw1) {
    int i = blockIdx.x * 256 + threadIdx.x;
    if (i < RW0)      g_winh[i]        = __float2half_rn(w_in[i]);
    else if (i < RW1) g_wouth[i - RW0] = __float2half_rn(w_out[i - RW0]);
    else if (i < RW2) g_w1h[i - RW1]   = __float2half_rn(w1[i - RW1]);
    else if (i < RW3) g_w2h[i - RW2]   = __float2half_rn(w2[i - RW2]);
    else if (i < RW4) g_hw1h[i - RW3]  = __float2half_rn(hw1[i - RW3]);
}

// ---------------- router + fused concat ----------------
__global__ __launch_bounds__(256) void k_router(const float* __restrict__ z,
                                                const float* __restrict__ a,
                                                const float* __restrict__ w_gate,
                                                float* __restrict__ gates_out) {
    __shared__ float red[256 * 8];
    int b = blockIdx.x, tid = threadIdx.x;
    float p[8];
#pragma unroll
    for (int e = 0; e < 8; e++) p[e] = 0.f;
    for (int k = tid; k < ND; k += 256) {
        int dd = k & 127;
        int row = b * 32 + (k >> 7);
        float xv = (dd < DZ) ? z[row * DZ + dd] : a[row * DA + (dd - DZ)];
        g_x [(size_t)b * ND + k] = xv;
        g_xh[(size_t)b * ND + k] = __float2half_rn(xv);
        const float4* wg = reinterpret_cast<const float4*>(w_gate + (size_t)k * 8);
        float4 w0 = wg[0], w1 = wg[1];
        p[0] = fmaf(xv, w0.x, p[0]); p[1] = fmaf(xv, w0.y, p[1]);
        p[2] = fmaf(xv, w0.z, p[2]); p[3] = fmaf(xv, w0.w, p[3]);
        p[4] = fmaf(xv, w1.x, p[4]); p[5] = fmaf(xv, w1.y, p[5]);
        p[6] = fmaf(xv, w1.z, p[6]); p[7] = fmaf(xv, w1.w, p[7]);
    }
#pragma unroll
    for (int e = 0; e < 8; e++) red[tid * 8 + e] = p[e];
    __syncthreads();
    for (int s = 128; s > 0; s >>= 1) {
        if (tid < s) {
#pragma unroll
            for (int e = 0; e < 8; e++) red[tid * 8 + e] += red[(tid + s) * 8 + e];
        }
        __syncthreads();
    }
    if (tid == 0) {
        float l[8];
#pragma unroll
        for (int e = 0; e < 8; e++) l[e] = red[e];
        int i0 = 0; float v0 = l[0];
#pragma unroll
        for (int e = 1; e < 8; e++) if (l[e] > v0) { v0 = l[e]; i0 = e; }
        int i1 = -1; float v1 = -3.4e38f;
#pragma unroll
        for (int e = 0; e < 8; e++) if (e != i0 && l[e] > v1) { v1 = l[e]; i1 = e; }
        float e1 = expf(v1 - v0);
        float inv = 1.f / (1.f + e1);
        float g0 = inv, g1v = e1 * inv;
#pragma unroll
        for (int e = 0; e < 8; e++)
            gates_out[b * 8 + e] = (e == i0) ? g0 : ((e == i1) ? g1v : 0.f);
        g_topidx[b * 2] = i0;  g_topidx[b * 2 + 1] = i1;
        g_topgate[b * 2] = g0; g_topgate[b * 2 + 1] = g1v;
        float s = 0.f;
#pragma unroll
        for (int e = 0; e < 8; e++) s += expf(l[e] - v0);
        g_lse[b] = v0 + logf(s);
    }
}

// ---------------- parallel deterministic counting sort ----------------
__global__ __launch_bounds__(256) void k_sort() {
    __shared__ int s_cnt[256][8];
    __shared__ int s_ecnt[8];
    __shared__ int s_base[8];
    int t = threadIdx.x;
    int my[8];
    int lc[8] = {0, 0, 0, 0, 0, 0, 0, 0};
#pragma unroll
    for (int i = 0; i < 8; i++) {
        int e = g_topidx[t * 8 + i];
        my[i] = e;
        lc[e]++;
    }
#pragma unroll
    for (int e = 0; e < 8; e++) s_cnt[t][e] = lc[e];
    __syncthreads();
    if (t < 8) {
        int off = 0;
        for (int i = 0; i < 256; i++) {
            int v = s_cnt[i][t];
            s_cnt[i][t] = off;
            off += v;
        }
        s_ecnt[t] = off;
    }
    __syncthreads();
    if (t == 0) {
        int o = 0, g = 0;
        for (int e = 0; e < 8; e++) {
            s_base[e] = o;
            int pc = (s_ecnt[e] + 3) & ~3;
            for (int i = 0; i < (pc >> 2); i++) g_grp_expert[g++] = e;
            o += pc;
        }
        g_ngroups = g;
        g_npad = o;
    }
    __syncthreads();
#pragma unroll
    for (int i = 0; i < 8; i++) {
        int p = t * 8 + i;
        int e = my[i];
        int sp = s_base[e] + s_cnt[t][e]++;
        g_sp_pair[sp] = p;
        g_tok_sp[p] = sp;
    }
    if (t < 8) {
        int start = s_base[t] + s_ecnt[t];
        int end = s_base[t] + ((s_ecnt[t] + 3) & ~3);
        for (int sp = start; sp < end; sp++) g_sp_pair[sp] = -1;
    }
}

// ---------------- fp16 batched GEMM (cp.async double-buffered, K stages of 64) ----------------
// halves: sA[2][128*72] at 0 | sB[2][128*72] at 18432  => 73728 bytes
#define GEMM_SMEM_BYTES 73728
__device__ __forceinline__ void gemm_issue_h(uint32_t smu, int buf, int kc,
                                             const __half* const* s_ab,
                                             const __half* wb, int tid) {
#pragma unroll
    for (int it = 0; it < 4; it++) {
        int i = tid + it * 256;
        int r = i >> 3, q = (i & 7) * 8;
        cp_async16(smu + (uint32_t)(buf * 9216 + r * 72 + q) * 2,
                   s_ab[r >> 5] + (size_t)(r & 31) * 128 + kc + q);
        cp_async16(smu + (uint32_t)(18432 + buf * 9216 + r * 72 + q) * 2,
                   wb + (size_t)r * 128 + kc + q);
    }
    CP_COMMIT();
}

// DST==0: qkv -> g_qkvh (half).  DST==1: o-proj + FUSED residual+LN1 -> g_h + g_hh.
template<int SRC, int DST>
__global__ __launch_bounds__(256) void k_gemm(const float* __restrict__ bias, int Ntot,
                                              const float* __restrict__ ln1_g,
                                              const float* __restrict__ ln1_b) {
    int g = blockIdx.x;
    if (g >= g_ngroups) return;
    int e = g_grp_expert[g];
    int n0 = blockIdx.y * 128;
    int tid = threadIdx.x, lane = tid & 31, w = tid >> 5;

    extern __shared__ __half smh_g[];
    uint32_t smu = (uint32_t)__cvta_generic_to_shared(smh_g);
    __shared__ const __half* s_ab[4];
    if (tid < 4) {
        const __half* ab;
        if (SRC == 0) {
            int pr = g_sp_pair[g * 4 + tid];
            int tok = (pr >= 0) ? (pr >> 1) : 0;
            ab = g_xh + (size_t)tok * ND;
        } else {
            ab = g_aoh + (size_t)(g * 4 + tid) * 32 * 128;
        }
        s_ab[tid] = ab;
    }
    __syncthreads();

    const __half* W = (SRC == 0) ? g_winh : g_wouth;
    const __half* wb = W + (size_t)e * Ntot * 128 + (size_t)n0 * 128;

    float acc[2][8][4];
#pragma unroll
    for (int i = 0; i < 2; i++)
#pragma unroll
        for (int j = 0; j < 8; j++)
#pragma unroll
            for (int k = 0; k < 4; k++) acc[i][j][k] = 0.f;

    int mt_base = (w & 3) * 2;
    int nt_base = (w >> 2) * 8;
    int rq = lane >> 2;
    int k2 = (lane & 3) * 2;

    gemm_issue_h(smu, 0, 0, s_ab, wb, tid);
    for (int c = 0; c < 2; c++) {
        if (c + 1 < 2) { gemm_issue_h(smu, 1, 64, s_ab, wb, tid); CP_WAIT1(); }
        else CP_WAIT0();
        __syncthreads();
        const __half* sA = smh_g + c * 9216;
        const __half* sB = smh_g + 18432 + c * 9216;
#pragma unroll
        for (int kh = 0; kh < 4; kh++) {
            int kpos = kh * 16 + k2;
            uint32_t a[2][4];
#pragma unroll
            for (int mt = 0; mt < 2; mt++) {
                int r0 = (mt_base + mt) * 16 + rq;
                a[mt][0] = *reinterpret_cast<const uint32_t*>(sA + r0 * 72 + kpos);
                a[mt][1] = *reinterpret_cast<const uint32_t*>(sA + (r0 + 8) * 72 + kpos);
                a[mt][2] = *reinterpret_cast<const uint32_t*>(sA + r0 * 72 + kpos + 8);
                a[mt][3] = *reinterpret_cast<const uint32_t*>(sA + (r0 + 8) * 72 + kpos + 8);
            }
#pragma unroll
            for (int nt = 0; nt < 8; nt++) {
                int nr = (nt_base + nt) * 8 + rq;
                uint32_t b[2];
                b[0] = *reinterpret_cast<const uint32_t*>(sB + nr * 72 + kpos);
                b[1] = *reinterpret_cast<const uint32_t*>(sB + nr * 72 + kpos + 8);
                mma_f16(acc[0][nt], a[0], b);
                mma_f16(acc[1][nt], a[1], b);
            }
        }
        __syncthreads();
    }

    if (DST == 0) {
#pragma unroll
        for (int mt = 0; mt < 2; mt++) {
            int r0 = (mt_base + mt) * 16 + rq;
            int r1 = r0 + 8;
#pragma unroll
            for (int nt = 0; nt < 8; nt++) {
                int nc = n0 + (nt_base + nt) * 8 + 2 * (lane & 3);
                float2 bv = *reinterpret_cast<const float2*>(bias + (size_t)e * Ntot + nc);
                __half2 h0 = __floats2half2_rn(acc[mt][nt][0] + bv.x, acc[mt][nt][1] + bv.y);
                __half2 h1 = __floats2half2_rn(acc[mt][nt][2] + bv.x, acc[mt][nt][3] + bv.y);
                *reinterpret_cast<__half2*>(g_qkvh + ((size_t)g * 128 + r0) * Ntot + nc) = h0;
                *reinterpret_cast<__half2*>(g_qkvh + ((size_t)g * 128 + r1) * Ntot + nc) = h1;
            }
        }
    } else {
        float* sO = reinterpret_cast<float*>(smh_g);   // 128*132 floats = 67584 B < 73728
#pragma unroll
        for (int mt = 0; mt < 2; mt++) {
            int r0 = (mt_base + mt) * 16 + rq;
            int r1 = r0 + 8;
#pragma unroll
            for (int nt = 0; nt < 8; nt++) {
                int nc = (nt_base + nt) * 8 + 2 * (lane & 3);
                float2 bv = *reinterpret_cast<const float2*>(bias + (size_t)e * 128 + nc);
                sO[r0 * 132 + nc]     = acc[mt][nt][0] + bv.x;
                sO[r0 * 132 + nc + 1] = acc[mt][nt][1] + bv.y;
                sO[r1 * 132 + nc]     = acc[mt][nt][2] + bv.x;
                sO[r1 * 132 + nc + 1] = acc[mt][nt][3] + bv.y;
            }
        }
        __syncthreads();
        const float* g1 = ln1_g + e * 128;
        const float* b1 = ln1_b + e * 128;
        for (int rr = 0; rr < 16; rr++) {
            int r = w * 16 + rr;
            int sp = g * 4 + (r >> 5);
            int pr = g_sp_pair[sp];
            if (pr < 0) continue;
            int token = pr >> 1;
            float v[4]; float sum = 0.f, sq = 0.f;
#pragma unroll
            for (int j = 0; j < 4; j++) {
                int c = lane + 32 * j;
                v[j] = g_x[(size_t)token * ND + (r & 31) * 128 + c] + sO[r * 132 + c];
                sum += v[j]; sq += v[j] * v[j];
            }
#pragma unroll
            for (int off = 16; off > 0; off >>= 1) {
                sum += __shfl_xor_sync(0xffffffffu, sum, off);
                sq  += __shfl_xor_sync(0xffffffffu, sq, off);
            }
            float mu = sum * (1.f / 128.f);
            float var = sq * (1.f / 128.f) - mu * mu;
            float rs = rsqrtf(var + 1e-5f);
#pragma unroll
            for (int j = 0; j < 4; j++) {
                int c = lane + 32 * j;
                float lnv = (v[j] - mu) * rs * g1[c] + b1[c];
                g_h [((size_t)g * 128 + r) * 128 + c] = lnv;
                g_hh[((size_t)g * 128 + r) * 128 + c] = __float2half_rn(lnv);
            }
        }
    }
}

// ---------------- head1: split-K fp16 GEMM ----------------
__device__ __forceinline__ void head_issue_h(uint32_t smu, int buf, int kc,
                                             const __half* Ab, const __half* Bb, int tid) {
#pragma unroll
    for (int it = 0; it < 4; it++) {
        int i = tid + it * 256;
        int r = i >> 3, q = (i & 7) * 8;
        cp_async16(smu + (uint32_t)(buf * 9216 + r * 72 + q) * 2,
                   Ab + (size_t)r * ND + kc + q);
        cp_async16(smu + (uint32_t)(18432 + buf * 9216 + r * 72 + q) * 2,
                   Bb + (size_t)r * ND + kc + q);
    }
    CP_COMMIT();
}

__global__ __launch_bounds__(256) void k_head1() {
    int bm = blockIdx.x, bn = blockIdx.y, ks4 = blockIdx.z;
    int tid = threadIdx.x, lane = tid & 31, w = tid >> 5;

    extern __shared__ __half smh_h[];
    uint32_t smu = (uint32_t)__cvta_generic_to_shared(smh_h);

    const __half* Ab = g_yh + (size_t)(bm * 128) * ND + ks4 * 1024;
    const __half* Bb = g_hw1h + (size_t)(bn * 128) * ND + ks4 * 1024;

    float acc[2][8][4];
#pragma unroll
    for (int i = 0; i < 2; i++)
#pragma unroll
        for (int j = 0; j < 8; j++)
#pragma unroll
            for (int k = 0; k < 4; k++) acc[i][j][k] = 0.f;

    int mt_base = (w & 3) * 2;
    int nt_base = (w >> 2) * 8;
    int rq = lane >> 2;
    int k2 = (lane & 3) * 2;

    head_issue_h(smu, 0, 0, Ab, Bb, tid);
    for (int c = 0; c < 16; c++) {
        if (c + 1 < 16) { head_issue_h(smu, (c + 1) & 1, (c + 1) * 64, Ab, Bb, tid); CP_WAIT1(); }
        else CP_WAIT0();
        __syncthreads();
        const __half* sA = smh_h + (c & 1) * 9216;
        const __half* sB = smh_h + 18432 + (c & 1) * 9216;
#pragma unroll
        for (int kh = 0; kh < 4; kh++) {
            int kpos = kh * 16 + k2;
            uint32_t a[2][4];
#pragma unroll
            for (int mt = 0; mt < 2; mt++) {
                int r0 = (mt_base + mt) * 16 + rq;
                a[mt][0] = *reinterpret_cast<const uint32_t*>(sA + r0 * 72 + kpos);
                a[mt][1] = *reinterpret_cast<const uint32_t*>(sA + (r0 + 8) * 72 + kpos);
                a[mt][2] = *reinterpret_cast<const uint32_t*>(sA + r0 * 72 + kpos + 8);
                a[mt][3] = *reinterpret_cast<const uint32_t*>(sA + (r0 + 8) * 72 + kpos + 8);
            }
#pragma unroll
            for (int nt = 0; nt < 8; nt++) {
                int nr = (nt_base + nt) * 8 + rq;
                uint32_t b[2];
                b[0] = *reinterpret_cast<const uint32_t*>(sB + nr * 72 + kpos);
                b[1] = *reinterpret_cast<const uint32_t*>(sB + nr * 72 + kpos + 8);
                mma_f16(acc[0][nt], a[0], b);
                mma_f16(acc[1][nt], a[1], b);
            }
        }
        __syncthreads();
    }

    float* dst = g_hp + ((size_t)ks4 * B_TOK + bm * 128) * HH + bn * 128;
#pragma unroll
    for (int mt = 0; mt < 2; mt++) {
        int r0 = (mt_base + mt) * 16 + rq;
        int r1 = r0 + 8;
#pragma unroll
        for (int nt = 0; nt < 8; nt++) {
            int nc = (nt_base + nt) * 8 + 2 * (lane & 3);
            float2 o0, o1;
            o0.x = acc[mt][nt][0]; o0.y = acc[mt][nt][1];
            o1.x = acc[mt][nt][2]; o1.y = acc[mt][nt][3];
            *reinterpret_cast<float2*>(dst + (size_t)r0 * HH + nc) = o0;
            *reinterpret_cast<float2*>(dst + (size_t)r1 * HH + nc) = o1;
        }
    }
}

// ---------------- fused FFN: fp16 mma (m16n8k16), K=64 stages ----------------
// smem halves: sA[64*136]=8704 | sW ring 2*[128*72]=18432 | sF[64*136]=8704 => 71680 B
#define FFN_SMEM_BYTES 71680
__device__ __forceinline__ void ffn_issue_h(uint32_t smu, int s,
                                            const __half* w1b, const __half* w2b, int tid) {
    int c = s >> 2, ph = (s >> 1) & 1, kc = s & 1;
    const __half* base;
    int rstride;
    if (ph) { base = w2b + c * 128 + kc * 64;                  rstride = 1024; }
    else    { base = w1b + (size_t)(c * 128) * 128 + kc * 64;  rstride = 128; }
#pragma unroll
    for (int it = 0; it < 4; it++) {
        int i = tid + it * 256;
        int r = i >> 3, q = (i & 7) * 8;
        cp_async16(smu + (uint32_t)(8704 + (s & 1) * 9216 + r * 72 + q) * 2,
                   base + (size_t)r * rstride + q);
    }
    CP_COMMIT();
}

__global__ __launch_bounds__(256) void k_ffn(const float* __restrict__ B1,
                                             const float* __restrict__ B2) {
    int g = blockIdx.x;
    if (g >= g_ngroups) return;
    int hf = blockIdx.y;
    int e = g_grp_expert[g];
    int tid = threadIdx.x, lane = tid & 31, w = tid >> 5;

    extern __shared__ __half smh[];
    __half* sA = smh;                    // 64 x 136
    __half* sW = smh + 8704;             // 2 x 128 x 72
    __half* sF = smh + 8704 + 18432;     // 64 x 136
    uint32_t smu = (uint32_t)__cvta_generic_to_shared(smh);

    const __half* hb  = g_hh + ((size_t)g * 128 + hf * 64) * 128;
    const __half* w1b = g_w1h + (size_t)e * 1024 * 128;
    const __half* w2b = g_w2h + (size_t)e * 128 * 1024;

#pragma unroll
    for (int it = 0; it < 4; it++) {
        int i = tid + it * 256;
        int r = i >> 4, q = (i & 15) * 8;
        *reinterpret_cast<float4*>(sA + r * 136 + q) =
            *reinterpret_cast<const float4*>(hb + (size_t)r * 128 + q);
    }

    int mt_base = (w & 1) * 2;
    int nt_base = (w >> 1) * 4;
    int rq = lane >> 2;
    int k2 = (lane & 3) * 2;

    float acc1[2][4][4], acc2[2][4][4];
#pragma unroll
    for (int mt = 0; mt < 2; mt++)
#pragma unroll
        for (int j = 0; j < 4; j++)
#pragma unroll
            for (int k = 0; k < 4; k++) acc2[mt][j][k] = 0.f;

    ffn_issue_h(smu, 0, w1b, w2b, tid);
    ffn_issue_h(smu, 1, w1b, w2b, tid);

    for (int s = 0; s < 32; s++) {
        if (s < 31) CP_WAIT1(); else CP_WAIT0();
        __syncthreads();
        if ((s & 3) == 0) {
#pragma unroll
            for (int mt = 0; mt < 2; mt++)
#pragma unroll
                for (int j = 0; j < 4; j++)
#pragma unroll
                    for (int k = 0; k < 4; k++) acc1[mt][j][k] = 0.f;
        }
        int ph = (s >> 1) & 1;
        int kc = s & 1;
        const __half* sWb = sW + (s & 1) * 9216;
        if (!ph) {
#pragma unroll
            for (int kh = 0; kh < 4; kh++) {
                int kpos = kc * 64 + kh * 16 + k2;
                int kb = kh * 16 + k2;
                uint32_t a[2][4];
#pragma unroll
                for (int mt = 0; mt < 2; mt++) {
                    int r0 = (mt_base + mt) * 16 + rq;
                    a[mt][0] = *reinterpret_cast<const uint32_t*>(sA + r0 * 136 + kpos);
                    a[mt][1] = *reinterpret_cast<const uint32_t*>(sA + (r0 + 8) * 136 + kpos);
                    a[mt][2] = *reinterpret_cast<const uint32_t*>(sA + r0 * 136 + kpos + 8);
                    a[mt][3] = *reinterpret_cast<const uint32_t*>(sA + (r0 + 8) * 136 + kpos + 8);
                }
#pragma unroll
                for (int nt = 0; nt < 4; nt++) {
                    int nr = (nt_base + nt) * 8 + rq;
                    uint32_t b[2];
                    b[0] = *reinterpret_cast<const uint32_t*>(sWb + nr * 72 + kb);
                    b[1] = *reinterpret_cast<const uint32_t*>(sWb + nr * 72 + kb + 8);
                    mma_f16(acc1[0][nt], a[0], b);
                    mma_f16(acc1[1][nt], a[1], b);
                }
            }
        } else {
#pragma unroll
            for (int kh = 0; kh < 4; kh++) {
                int kpos = kc * 64 + kh * 16 + k2;
                int kb = kh * 16 + k2;
                uint32_t a[2][4];
#pragma unroll
                for (int mt = 0; mt < 2; mt++) {
                    int r0 = (mt_base + mt) * 16 + rq;
                    a[mt][0] = *reinterpret_cast<const uint32_t*>(sF + r0 * 136 + kpos);
                    a[mt][1] = *reinterpret_cast<const uint32_t*>(sF + (r0 + 8) * 136 + kpos);
                    a[mt][2] = *reinterpret_cast<const uint32_t*>(sF + r0 * 136 + kpos + 8);
                    a[mt][3] = *reinterpret_cast<const uint32_t*>(sF + (r0 + 8) * 136 + kpos + 8);
                }
#pragma unroll
                for (int nt = 0; nt < 4; nt++) {
                    int nr = (nt_base + nt) * 8 + rq;
                    uint32_t b[2];
                    b[0] = *reinterpret_cast<const uint32_t*>(sWb + nr * 72 + kb);
                    b[1] = *reinterpret_cast<const uint32_t*>(sWb + nr * 72 + kb + 8);
                    mma_f16(acc2[0][nt], a[0], b);
                    mma_f16(acc2[1][nt], a[1], b);
                }
            }
        }
        __syncthreads();
        if ((s & 3) == 1) {
            int c = s >> 2;
#pragma unroll
            for (int mt = 0; mt < 2; mt++) {
                int r0 = (mt_base + mt) * 16 + rq;
#pragma unroll
                for (int nt = 0; nt < 4; nt++) {
                    int nc = (nt_base + nt) * 8 + 2 * (lane & 3);
                    float2 bv = *reinterpret_cast<const float2*>(B1 + (size_t)e * 1024 + c * 128 + nc);
                    __half2 h0 = __floats2half2_rn(fmaxf(acc1[mt][nt][0] + bv.x, 0.f),
                                                   fmaxf(acc1[mt][nt][1] + bv.y, 0.f));
                    __half2 h1 = __floats2half2_rn(fmaxf(acc1[mt][nt][2] + bv.x, 0.f),
                                                   fmaxf(acc1[mt][nt][3] + bv.y, 0.f));
                    *reinterpret_cast<__half2*>(sF + r0 * 136 + nc) = h0;
                    *reinterpret_cast<__half2*>(sF + (r0 + 8) * 136 + nc) = h1;
                }
            }
            __syncthreads();
        }
        if (s + 2 < 32) ffn_issue_h(smu, s + 2, w1b, w2b, tid);
    }

    {
        float* f2b = g_f2 + ((size_t)g * 128 + hf * 64) * 128;
#pragma unroll
        for (int mt = 0; mt < 2; mt++) {
            int r0 = (mt_base + mt) * 16 + rq;
#pragma unroll
            for (int nt = 0; nt < 4; nt++) {
                int nc = (nt_base + nt) * 8 + 2 * (lane & 3);
                float2 bv = *reinterpret_cast<const float2*>(B2 + (size_t)e * 128 + nc);
                float2 o0, o1;
                o0.x = acc2[mt][nt][0] + bv.x; o0.y = acc2[mt][nt][1] + bv.y;
                o1.x = acc2[mt][nt][2] + bv.x; o1.y = acc2[mt][nt][3] + bv.y;
                *reinterpret_cast<float2*>(f2b + (size_t)r0 * 128 + nc) = o0;
                *reinterpret_cast<float2*>(f2b + (size_t)(r0 + 8) * 128 + nc) = o1;
            }
        }
    }
}

// ---------------- attention (reads half qkv; fp32 math) ----------------
__global__ __launch_bounds__(128) void k_attn() {
    int sp = blockIdx.x;
    if (sp >= g_npad) return;
    if (g_sp_pair[sp] < 0) return;
    __shared__ float s_kv[32 * 261];
    int tid = threadIdx.x, lane = tid & 31, h = tid >> 5;
    for (int i = tid; i < 32 * 256; i += 128) {
        int r = i >> 8, c = i & 255;
        s_kv[r * 261 + c] = __half2float(g_qkvh[((size_t)sp * 32 + r) * 384 + 128 + c]);
    }
    __syncthreads();
    float kreg[32];
#pragma unroll
    for (int d = 0; d < 32; d++) kreg[d] = s_kv[lane * 261 + h * 32 + d];
    const __half* qb = g_qkvh + (size_t)sp * 32 * 384;
    for (int q = 0; q < 32; q++) {
        const __half2* qp = reinterpret_cast<const __half2*>(qb + q * 384 + h * 32);
        float sc = 0.f;
#pragma unroll
        for (int d2 = 0; d2 < 16; d2++) {
            float2 q2 = __half22float2(qp[d2]);
            sc += q2.x * kreg[d2 * 2] + q2.y * kreg[d2 * 2 + 1];
        }
        sc *= 0.1767766952966369f;
        float m = sc;
#pragma unroll
        for (int off = 16; off > 0; off >>= 1)
            m = fmaxf(m, __shfl_xor_sync(0xffffffffu, m, off));
        float pr = expf(sc - m);
        float ss = pr;
#pragma unroll
        for (int off = 16; off > 0; off >>= 1)
            ss += __shfl_xor_sync(0xffffffffu, ss, off);
        float att = pr / ss;
        float o = 0.f;
#pragma unroll
        for (int kk = 0; kk < 32; kk++) {
            float av = __shfl_sync(0xffffffffu, att, kk);
            o = fmaf(av, s_kv[kk * 261 + 128 + h * 32 + lane], o);
        }
        g_aoh[((size_t)sp * 32 + q) * 128 + h * 32 + lane] = __float2half_rn(o);
    }
}

// ---------------- finish ----------------
__global__ __launch_bounds__(128) void k_finish(const float* __restrict__ ln2_g,
                                                const float* __restrict__ ln2_b) {
    int t = blockIdx.x;
    int tid = threadIdx.x, lane = tid & 31, w = tid >> 5;
    float y[8][4];
#pragma unroll
    for (int rr = 0; rr < 8; rr++)
#pragma unroll
        for (int j = 0; j < 4; j++) y[rr][j] = 0.f;

    for (int slot = 0; slot < 2; slot++) {
        int pr = t * 2 + slot;
        int sp = g_tok_sp[pr];
        int e = g_topidx[pr];
        float gate = g_topgate[pr];
        const float* g2 = ln2_g + e * 128;
        const float* b2 = ln2_b + e * 128;
        for (int rr = 0; rr < 8; rr++) {
            int r = w * 8 + rr;
            float v[4]; float sum = 0.f, sq = 0.f;
#pragma unroll
            for (int j = 0; j < 4; j++) {
                int c = lane + 32 * j;
                v[j] = g_h[((size_t)sp * 32 + r) * 128 + c]
                     + g_f2[((size_t)sp * 32 + r) * 128 + c];
                sum += v[j]; sq += v[j] * v[j];
            }
#pragma unroll
            for (int off = 16; off > 0; off >>= 1) {
                sum += __shfl_xor_sync(0xffffffffu, sum, off);
                sq  += __shfl_xor_sync(0xffffffffu, sq, off);
            }
            float mu = sum * (1.f / 128.f);
            float var = sq * (1.f / 128.f) - mu * mu;
            float rs = rsqrtf(var + 1e-5f);
#pragma unroll
            for (int j = 0; j < 4; j++) {
                int c = lane + 32 * j;
                y[rr][j] += gate * ((v[j] - mu) * rs * g2[c] + b2[c]);
            }
        }
    }
    for (int rr = 0; rr < 8; rr++) {
        int r = w * 8 + rr;
#pragma unroll
        for (int j = 0; j < 4; j++) {
            int c = lane + 32 * j;
            g_yh[(size_t)t * ND + r * 128 + c] = __float2half_rn(y[rr][j]);
        }
    }
}

// ---------------- head2: fused split-K reduce + relu + GEMV ----------------
__global__ void k_head2(const float* __restrict__ hb1,
                        const float* __restrict__ hw2, const float* __restrict__ hb2,
                        float* __restrict__ out_r) {
    int b = blockIdx.x;
    int j = threadIdx.x >> 5;
    int lane = threadIdx.x & 31;
    const float* w = hw2 + (size_t)j * HH;
    float s = 0.f;
    for (int k = lane; k < HH; k += 32) {
        size_t i = (size_t)b * HH + k;
        float hsum = g_hp[i] + g_hp[(size_t)B_TOK * HH + i]
                   + g_hp[2 * (size_t)B_TOK * HH + i]
                   + g_hp[3 * (size_t)B_TOK * HH + i] + hb1[k];
        s = fmaf(fmaxf(hsum, 0.f), w[k], s);
    }
#pragma unroll
    for (int off = 16; off > 0; off >>= 1) s += __shfl_xor_sync(0xffffffffu, s, off);
    if (lane == 0) out_r[b * NR + j] = s + hb2[j];
}

// ---------------- loss ----------------
__global__ void k_loss(const float* __restrict__ gates, float* __restrict__ out_loss) {
    __shared__ float s_imp[8][32], s_ld[8][32], s_lse[256];
    int t = threadIdx.x;
    int e = t & 7, c = t >> 3;
    float imp = 0.f, ld = 0.f;
    for (int b = c; b < B_TOK; b += 32) {
        float g = gates[b * 8 + e];
        imp += g;
        if (g > 0.f) ld += 1.f;
    }
    s_imp[e][c] = imp; s_ld[e][c] = ld;
    float ls = 0.f;
    for (int b = t; b < B_TOK; b += 256) ls += g_lse[b];
    s_lse[t] = ls;
    __syncthreads();
    for (int s = 128; s > 0; s >>= 1) {
        if (t < s) s_lse[t] += s_lse[t + s];
        __syncthreads();
    }
    if (t == 0) {
        float I[8], L[8];
        float mi = 0.f, ml = 0.f;
        for (int e2 = 0; e2 < 8; e2++) {
            float si = 0.f, sl = 0.f;
            for (int c2 = 0; c2 < 32; c2++) { si += s_imp[e2][c2]; sl += s_ld[e2][c2]; }
            I[e2] = si; L[e2] = sl; mi += si; ml += sl;
        }
        mi *= 0.125f; ml *= 0.125f;
        float vi = 0.f, vl = 0.f;
        for (int e2 = 0; e2 < 8; e2++) {
            vi += (I[e2] - mi) * (I[e2] - mi);
            vl += (L[e2] - ml) * (L[e2] - ml);
        }
        vi /= 7.f; vl /= 7.f;
        float loss = vi / (mi * mi + 1e-10f) + vl / (ml * ml + 1e-10f)
                   + s_lse[0] * (1.f / (float)B_TOK);
        *out_loss = loss;
    }
}

// ---------------- launch ----------------
extern "C" void kernel_launch(void* const* d_in, const int* in_sizes, int n_in,
                              void* d_out, int out_size) {
    const float* z      = (const float*)d_in[0];
    const float* a      = (const float*)d_in[1];
    const float* w_gate = (const float*)d_in[2];
    const float* w_in   = (const float*)d_in[3];
    const float* b_in   = (const float*)d_in[4];
    const float* w_out  = (const float*)d_in[5];
    const float* b_out  = (const float*)d_in[6];
    const float* ln1_g  = (const float*)d_in[7];
    const float* ln1_b  = (const float*)d_in[8];
    const float* w1     = (const float*)d_in[9];
    const float* b1     = (const float*)d_in[10];
    const float* w2     = (const float*)d_in[11];
    const float* b2     = (const float*)d_in[12];
    const float* ln2_g  = (const float*)d_in[13];
    const float* ln2_b  = (const float*)d_in[14];
    const float* hw1    = (const float*)d_in[15];
    const float* hb1    = (const float*)d_in[16];
    const float* hw2    = (const float*)d_in[17];
    const float* hb2    = (const float*)d_in[18];

    float* out       = (float*)d_out;
    float* gates_out = out + B_TOK * NR;
    float* loss_out  = out + B_TOK * NR + B_TOK * NEXP;

    cudaFuncSetAttribute(k_gemm<0, 0>, cudaFuncAttributeMaxDynamicSharedMemorySize, GEMM_SMEM_BYTES);
    cudaFuncSetAttribute(k_gemm<1, 1>, cudaFuncAttributeMaxDynamicSharedMemorySize, GEMM_SMEM_BYTES);
    cudaFuncSetAttribute(k_head1, cudaFuncAttributeMaxDynamicSharedMemorySize, GEMM_SMEM_BYTES);
    cudaFuncSetAttribute(k_ffn, cudaFuncAttributeMaxDynamicSharedMemorySize, FFN_SMEM_BYTES);

    k_round<<<(RW4 + 255) / 256, 256>>>(w_in, w_out, w1, w2, hw1);
    k_router<<<B_TOK, 256>>>(z, a, w_gate, gates_out);
    k_sort<<<1, 256>>>();

    k_gemm<0, 0><<<dim3(GROUP_MAX, 3), 256, GEMM_SMEM_BYTES>>>(b_in, 384, nullptr, nullptr);
    k_attn<<<PAIR_MAX, 128>>>();
    k_gemm<1, 1><<<dim3(GROUP_MAX, 1), 256, GEMM_SMEM_BYTES>>>(b_out, 128, ln1_g, ln1_b);
    k_ffn<<<dim3(GROUP_MAX, 2), 256, FFN_SMEM_BYTES>>>(b1, b2);
    k_finish<<<B_TOK, 128>>>(ln2_g, ln2_b);
    k_head1<<<dim3(8, 4, 4), 256, GEMM_SMEM_BYTES>>>();
    k_head2<<<B_TOK, 128>>>(hb1, hw2, hb2, out);
    k_loss<<<1, 256>>>(gates_out, loss_out);
}